// round 2
// baseline (speedup 1.0000x reference)
#include <cuda_runtime.h>
#include <cuda_bf16.h>
#include <math.h>

#define NN 50000
#define EE 800000
#define DD 96
#define HIDN 128
#define OUTD 8
#define BN_EPS 1e-5f
#define AGG_EPS 1e-6f

// ---------------- device scratch ----------------
__device__ __align__(16) float g_h[NN * DD];
__device__ __align__(16) float g_A[NN * DD];
__device__ __align__(16) float g_B[NN * DD];
__device__ __align__(16) float g_D[NN * DD];
__device__ __align__(16) float g_E[NN * DD];
__device__ __align__(16) float g_num[NN * DD];
__device__ __align__(16) float g_den[NN * DD];
__device__ __align__(16) float g_hnew[NN * DD];
__device__ __align__(16) float g_e[EE * DD];
__device__ __align__(16) float g_enew[EE * DD];
__device__ __align__(16) float g_sums[4 * DD];
__device__ __align__(16) float g_scale_e[DD], g_shift_e[DD];
__device__ __align__(16) float g_scale_h[DD], g_shift_h[DD];
// transposed bf16 hi/lo weights: [type(A,B,C,D,E)][layer][n*96+k]
__device__ __align__(16) __nv_bfloat16 g_Wt_hi[20 * DD * DD];
__device__ __align__(16) __nv_bfloat16 g_Wt_lo[20 * DD * DD];

// ---------------- helpers ----------------
__device__ __forceinline__ unsigned pack_bf16(float x, float y) {
    __nv_bfloat162 t;
    t.x = __float2bfloat16(x);
    t.y = __float2bfloat16(y);
    return *reinterpret_cast<unsigned*>(&t);
}

__device__ __forceinline__ void mma16816(float* c, const unsigned* a, unsigned b0, unsigned b1) {
    asm volatile(
        "mma.sync.aligned.m16n8k16.row.col.f32.bf16.bf16.f32 "
        "{%0,%1,%2,%3},{%4,%5,%6,%7},{%8,%9},{%0,%1,%2,%3};"
        : "+f"(c[0]), "+f"(c[1]), "+f"(c[2]), "+f"(c[3])
        : "r"(a[0]), "r"(a[1]), "r"(a[2]), "r"(a[3]), "r"(b0), "r"(b1));
}

// ---------------- weight prep: transpose + bf16 hi/lo split ----------------
__global__ void k_prep(const float* __restrict__ W, __nv_bfloat16* __restrict__ hi,
                       __nv_bfloat16* __restrict__ lo, int nmat) {
    int idx = blockIdx.x * blockDim.x + threadIdx.x;
    if (idx >= nmat * DD * DD) return;
    int m = idx / (DD * DD), e = idx % (DD * DD);
    int k = e / DD, n = e % DD;
    float w = W[m * DD * DD + k * DD + n];
    __nv_bfloat16 h = __float2bfloat16(w);
    float r = w - __bfloat162float(h);
    hi[m * DD * DD + n * DD + k] = h;
    lo[m * DD * DD + n * DD + k] = __float2bfloat16(r);
}

// ---------------- input embeddings ----------------
__global__ void k_embed_h(const float* __restrict__ h1, const float* __restrict__ h2,
                          const float* __restrict__ z, const float* __restrict__ W,
                          const float* __restrict__ b) {
    int idx = blockIdx.x * blockDim.x + threadIdx.x;
    if (idx >= NN * DD) return;
    int row = idx / DD, col = idx % DD;
    float acc = b[col];
    const float* x1 = h1 + row * 6;
#pragma unroll
    for (int k = 0; k < 6; k++) acc += x1[k] * W[k * DD + col];
    const float* x2 = h2 + row * 4;
#pragma unroll
    for (int k = 0; k < 4; k++) acc += x2[k] * W[(6 + k) * DD + col];
    const float* x3 = z + row * 16;
#pragma unroll
    for (int k = 0; k < 16; k++) acc += x3[k] * W[(10 + k) * DD + col];
    g_h[idx] = acc;
}

__global__ void k_embed_e(const float* __restrict__ ef, const float* __restrict__ W,
                          const float* __restrict__ b) {
    long long idx = (long long)blockIdx.x * blockDim.x + threadIdx.x;
    if (idx >= (long long)EE * DD) return;
    int row = (int)(idx / DD), col = (int)(idx % DD);
    const float* x = ef + (long long)row * 4;
    float acc = b[col];
#pragma unroll
    for (int k = 0; k < 4; k++) acc += x[k] * W[k * DD + col];
    g_e[idx] = acc;
}

// ---------------- zero accumulators ----------------
__global__ void k_zero() {
    int idx = blockIdx.x * blockDim.x + threadIdx.x;
    const float4 z4 = make_float4(0.f, 0.f, 0.f, 0.f);
    if (idx < NN * DD / 4) {
        ((float4*)g_num)[idx] = z4;
        ((float4*)g_den)[idx] = z4;
    }
    if (idx < 4 * DD) g_sums[idx] = 0.f;
}

// smem layout (in unsigned units):
//   A_hi [128*52]  A_lo [128*52]  W_hi [96*52]  W_lo [96*52]   total 93184 B
#define A_HI_OFF 0
#define A_LO_OFF (128 * 52)
#define W_HI_OFF (2 * 128 * 52)
#define W_LO_OFF (2 * 128 * 52 + 96 * 52)
#define SMEM_U32 (2 * 128 * 52 + 2 * 96 * 52)

// ---------------- fused node GEMM: A,B,D,E = h @ W + b (+ fused h update) ----------------
__global__ __launch_bounds__(256) void k_node(const __nv_bfloat16* __restrict__ WtHi,
                                              const __nv_bfloat16* __restrict__ WtLo,
                                              const float* __restrict__ bA, const float* __restrict__ bB,
                                              const float* __restrict__ bD, const float* __restrict__ bE,
                                              int layer, int fuse) {
    extern __shared__ unsigned sm[];
    unsigned* Ahi = sm + A_HI_OFF;
    unsigned* Alo = sm + A_LO_OFF;
    unsigned* Whi = sm + W_HI_OFF;
    unsigned* Wlo = sm + W_LO_OFF;
    int tid = threadIdx.x;
    int m0 = blockIdx.x * 128;
    int rows_valid = NN - m0;
    if (rows_valid > 128) rows_valid = 128;

    // load h tile (+ fused residual update), convert to bf16 hi/lo
    for (int i = tid; i < 128 * 24; i += 256) {
        int r = i / 24, c4 = i % 24;
        float4 v = make_float4(0.f, 0.f, 0.f, 0.f);
        if (r < rows_valid) {
            long long gi = (long long)(m0 + r) * 24 + c4;
            v = ((const float4*)g_h)[gi];
            if (fuse) {
                float4 en = ((const float4*)g_hnew)[gi];
                int c = c4 * 4;
                v.x += fmaxf(0.f, en.x * g_scale_h[c] + g_shift_h[c]);
                v.y += fmaxf(0.f, en.y * g_scale_h[c + 1] + g_shift_h[c + 1]);
                v.z += fmaxf(0.f, en.z * g_scale_h[c + 2] + g_shift_h[c + 2]);
                v.w += fmaxf(0.f, en.w * g_scale_h[c + 3] + g_shift_h[c + 3]);
                ((float4*)g_h)[gi] = v;
            }
        }
        float rx = v.x - __bfloat162float(__float2bfloat16(v.x));
        float ry = v.y - __bfloat162float(__float2bfloat16(v.y));
        float rz = v.z - __bfloat162float(__float2bfloat16(v.z));
        float rw = v.w - __bfloat162float(__float2bfloat16(v.w));
        Ahi[r * 52 + c4 * 2] = pack_bf16(v.x, v.y);
        Ahi[r * 52 + c4 * 2 + 1] = pack_bf16(v.z, v.w);
        Alo[r * 52 + c4 * 2] = pack_bf16(rx, ry);
        Alo[r * 52 + c4 * 2 + 1] = pack_bf16(rz, rw);
    }

    int w = tid >> 5, lane = tid & 31;
    int wm = w & 3, wn = w >> 2;
    const int types[4] = {0, 1, 3, 4};  // A, B, D, E
    const float* biases[4] = {bA, bB, bD, bE};
    float* outs[4] = {g_A, g_B, g_D, g_E};

    for (int t = 0; t < 4; t++) {
        __syncthreads();
        const unsigned* gwh = (const unsigned*)(WtHi + (types[t] * 4 + layer) * DD * DD);
        const unsigned* gwl = (const unsigned*)(WtLo + (types[t] * 4 + layer) * DD * DD);
        for (int i = tid; i < 96 * 48; i += 256) {
            int n = i / 48, kp = i % 48;
            Whi[n * 52 + kp] = gwh[i];
            Wlo[n * 52 + kp] = gwl[i];
        }
        __syncthreads();

        float acc[2][6][4];
#pragma unroll
        for (int m = 0; m < 2; m++)
#pragma unroll
            for (int n = 0; n < 6; n++)
#pragma unroll
                for (int j = 0; j < 4; j++) acc[m][n][j] = 0.f;

#pragma unroll
        for (int kt = 0; kt < 6; kt++) {
            int kp = kt * 8 + (lane & 3);
            unsigned ah[2][4], al[2][4];
#pragma unroll
            for (int m = 0; m < 2; m++) {
                int row = wm * 32 + m * 16 + (lane >> 2);
                ah[m][0] = Ahi[row * 52 + kp];
                ah[m][1] = Ahi[(row + 8) * 52 + kp];
                ah[m][2] = Ahi[row * 52 + kp + 4];
                ah[m][3] = Ahi[(row + 8) * 52 + kp + 4];
                al[m][0] = Alo[row * 52 + kp];
                al[m][1] = Alo[(row + 8) * 52 + kp];
                al[m][2] = Alo[row * 52 + kp + 4];
                al[m][3] = Alo[(row + 8) * 52 + kp + 4];
            }
#pragma unroll
            for (int n = 0; n < 6; n++) {
                int col = wn * 48 + n * 8 + (lane >> 2);
                unsigned bh0 = Whi[col * 52 + kp], bh1 = Whi[col * 52 + kp + 4];
                unsigned bl0 = Wlo[col * 52 + kp], bl1 = Wlo[col * 52 + kp + 4];
#pragma unroll
                for (int m = 0; m < 2; m++) {
                    mma16816(acc[m][n], ah[m], bh0, bh1);
                    mma16816(acc[m][n], ah[m], bl0, bl1);
                    mma16816(acc[m][n], al[m], bh0, bh1);
                }
            }
        }

        const float* bias = biases[t];
        float* out = outs[t];
#pragma unroll
        for (int m = 0; m < 2; m++) {
#pragma unroll
            for (int n = 0; n < 6; n++) {
                int row = m0 + wm * 32 + m * 16 + (lane >> 2);
                int col = wn * 48 + n * 8 + ((lane & 3) << 1);
                float b0 = bias[col], b1 = bias[col + 1];
                if (row < NN)
                    *(float2*)&out[(long long)row * 96 + col] =
                        make_float2(acc[m][n][0] + b0, acc[m][n][1] + b1);
                if (row + 8 < NN)
                    *(float2*)&out[(long long)(row + 8) * 96 + col] =
                        make_float2(acc[m][n][2] + b0, acc[m][n][3] + b1);
            }
        }
    }
}

// ---------------- fused edge layer ----------------
__global__ __launch_bounds__(256) void k_edge(const __nv_bfloat16* __restrict__ WtHi,
                                              const __nv_bfloat16* __restrict__ WtLo,
                                              const float* __restrict__ bC,
                                              const int* __restrict__ src,
                                              const int* __restrict__ dst,
                                              int fuse, int last) {
    extern __shared__ unsigned sm[];
    unsigned* Ahi = sm + A_HI_OFF;
    unsigned* Alo = sm + A_LO_OFF;
    unsigned* Whi = sm + W_HI_OFF;
    unsigned* Wlo = sm + W_LO_OFF;
    float* Sst = (float*)sm;  // staging 128 x 100 floats, aliases A_hi/A_lo
    int tid = threadIdx.x;
    int e0 = blockIdx.x * 128;

    // load e tile (+ fused residual update), convert
    for (int i = tid; i < 128 * 24; i += 256) {
        int r = i / 24, c4 = i % 24;
        long long gi = (long long)(e0 + r) * 24 + c4;
        float4 v = ((const float4*)g_e)[gi];
        if (fuse) {
            float4 en = ((const float4*)g_enew)[gi];
            int c = c4 * 4;
            v.x += fmaxf(0.f, en.x * g_scale_e[c] + g_shift_e[c]);
            v.y += fmaxf(0.f, en.y * g_scale_e[c + 1] + g_shift_e[c + 1]);
            v.z += fmaxf(0.f, en.z * g_scale_e[c + 2] + g_shift_e[c + 2]);
            v.w += fmaxf(0.f, en.w * g_scale_e[c + 3] + g_shift_e[c + 3]);
            ((float4*)g_e)[gi] = v;
        }
        float rx = v.x - __bfloat162float(__float2bfloat16(v.x));
        float ry = v.y - __bfloat162float(__float2bfloat16(v.y));
        float rz = v.z - __bfloat162float(__float2bfloat16(v.z));
        float rw = v.w - __bfloat162float(__float2bfloat16(v.w));
        Ahi[r * 52 + c4 * 2] = pack_bf16(v.x, v.y);
        Ahi[r * 52 + c4 * 2 + 1] = pack_bf16(v.z, v.w);
        Alo[r * 52 + c4 * 2] = pack_bf16(rx, ry);
        Alo[r * 52 + c4 * 2 + 1] = pack_bf16(rz, rw);
    }
    {
        const unsigned* gwh = (const unsigned*)WtHi;
        const unsigned* gwl = (const unsigned*)WtLo;
        for (int i = tid; i < 96 * 48; i += 256) {
            int n = i / 48, kp = i % 48;
            Whi[n * 52 + kp] = gwh[i];
            Wlo[n * 52 + kp] = gwl[i];
        }
    }
    __syncthreads();

    int w = tid >> 5, lane = tid & 31;
    int wm = w & 3, wn = w >> 2;
    float acc[2][6][4];
#pragma unroll
    for (int m = 0; m < 2; m++)
#pragma unroll
        for (int n = 0; n < 6; n++)
#pragma unroll
            for (int j = 0; j < 4; j++) acc[m][n][j] = 0.f;

#pragma unroll
    for (int kt = 0; kt < 6; kt++) {
        int kp = kt * 8 + (lane & 3);
        unsigned ah[2][4], al[2][4];
#pragma unroll
        for (int m = 0; m < 2; m++) {
            int row = wm * 32 + m * 16 + (lane >> 2);
            ah[m][0] = Ahi[row * 52 + kp];
            ah[m][1] = Ahi[(row + 8) * 52 + kp];
            ah[m][2] = Ahi[row * 52 + kp + 4];
            ah[m][3] = Ahi[(row + 8) * 52 + kp + 4];
            al[m][0] = Alo[row * 52 + kp];
            al[m][1] = Alo[(row + 8) * 52 + kp];
            al[m][2] = Alo[row * 52 + kp + 4];
            al[m][3] = Alo[(row + 8) * 52 + kp + 4];
        }
#pragma unroll
        for (int n = 0; n < 6; n++) {
            int col = wn * 48 + n * 8 + (lane >> 2);
            unsigned bh0 = Whi[col * 52 + kp], bh1 = Whi[col * 52 + kp + 4];
            unsigned bl0 = Wlo[col * 52 + kp], bl1 = Wlo[col * 52 + kp + 4];
#pragma unroll
            for (int m = 0; m < 2; m++) {
                mma16816(acc[m][n], ah[m], bh0, bh1);
                mma16816(acc[m][n], ah[m], bl0, bl1);
                mma16816(acc[m][n], al[m], bh0, bh1);
            }
        }
    }
    __syncthreads();  // done reading A smem; safe to overwrite with staging

    // stage accumulators to smem (stride 100 to dodge bank conflicts)
#pragma unroll
    for (int m = 0; m < 2; m++) {
#pragma unroll
        for (int n = 0; n < 6; n++) {
            int lr = wm * 32 + m * 16 + (lane >> 2);
            int col = wn * 48 + n * 8 + ((lane & 3) << 1);
            *(float2*)&Sst[lr * 100 + col] = make_float2(acc[m][n][0], acc[m][n][1]);
            *(float2*)&Sst[(lr + 8) * 100 + col] = make_float2(acc[m][n][2], acc[m][n][3]);
        }
    }
    __syncthreads();

    // per-row epilogue: e_new = Ce + bC + Dh[src] + Eh[dst]; sigmoid; atomics
    {
        int r = tid >> 1, half = tid & 1;
        int e = e0 + r;
        int s = src[e], d = dst[e];
        const float4* Dr = (const float4*)(g_D + (long long)s * 96) + half * 12;
        const float4* Er = (const float4*)(g_E + (long long)d * 96) + half * 12;
        const float4* Br = (const float4*)(g_B + (long long)s * 96) + half * 12;
        float4* nr = (float4*)(g_num + (long long)d * 96) + half * 12;
        float4* dr = (float4*)(g_den + (long long)d * 96) + half * 12;
        float* sp = Sst + r * 100 + half * 48;
        float4* ep = (float4*)(g_enew + (long long)e * 96) + half * 12;
        const float4* bc4 = (const float4*)bC + half * 12;
#pragma unroll
        for (int i = 0; i < 12; i++) {
            float4 a = ((float4*)sp)[i];
            float4 b = bc4[i], dv = Dr[i], ev = Er[i];
            float4 v = make_float4(a.x + b.x + dv.x + ev.x, a.y + b.y + dv.y + ev.y,
                                   a.z + b.z + dv.z + ev.z, a.w + b.w + dv.w + ev.w);
            ((float4*)sp)[i] = v;
            if (!last) ep[i] = v;
            float4 sg = make_float4(1.f / (1.f + __expf(-v.x)), 1.f / (1.f + __expf(-v.y)),
                                    1.f / (1.f + __expf(-v.z)), 1.f / (1.f + __expf(-v.w)));
            float4 bb = Br[i];
            atomicAdd(&nr[i], make_float4(sg.x * bb.x, sg.y * bb.y, sg.z * bb.z, sg.w * bb.w));
            atomicAdd(&dr[i], sg);
        }
    }
    __syncthreads();

    // BN-e column moments (skip on last layer — unused)
    if (!last && tid < 96) {
        float s = 0.f, q = 0.f;
#pragma unroll 4
        for (int r = 0; r < 128; r++) {
            float v = Sst[r * 100 + tid];
            s += v;
            q += v * v;
        }
        atomicAdd(&g_sums[tid], s);
        atomicAdd(&g_sums[DD + tid], q);
    }
}

// ---------------- h_new = Ah + num/(den+eps) + BN-h moments ----------------
__global__ __launch_bounds__(384) void k_hnew() {
    __shared__ float ssum[96], ssq[96];
    int tid = threadIdx.x;
    int col = tid % 96, yr = tid / 96;
    if (tid < 96) { ssum[tid] = 0.f; ssq[tid] = 0.f; }
    __syncthreads();
    float sm = 0.f, sq = 0.f;
    for (int row = blockIdx.x * 4 + yr; row < NN; row += gridDim.x * 4) {
        int i = row * 96 + col;
        float v = g_A[i] + g_num[i] / (g_den[i] + AGG_EPS);
        g_hnew[i] = v;
        sm += v; sq += v * v;
    }
    atomicAdd(&ssum[col], sm);
    atomicAdd(&ssq[col], sq);
    __syncthreads();
    if (tid < 96) {
        atomicAdd(&g_sums[2 * DD + tid], ssum[tid]);
        atomicAdd(&g_sums[3 * DD + tid], ssq[tid]);
    }
}

// ---------------- finalize BN stats ----------------
__global__ void k_finalize(int which, const float* __restrict__ g,
                           const float* __restrict__ b, float invM) {
    int c = threadIdx.x;
    if (c >= 96) return;
    int base = which * 2 * DD;
    float mu = g_sums[base + c] * invM;
    float var = g_sums[base + DD + c] * invM - mu * mu;
    float rstd = rsqrtf(var + BN_EPS);
    float sc = g[c] * rstd;
    float sh = b[c] - mu * sc;
    if (which == 0) { g_scale_e[c] = sc; g_shift_e[c] = sh; }
    else            { g_scale_h[c] = sc; g_shift_h[c] = sh; }
}

// ---------------- MLP head (applies final h update in-flight) ----------------
__global__ __launch_bounds__(128) void k_head(const float* __restrict__ W1,
                                              const float* __restrict__ b1,
                                              const float* __restrict__ W2,
                                              const float* __restrict__ b2,
                                              const float* __restrict__ maxa,
                                              float* __restrict__ out) {
    __shared__ float hs[8][96];
    __shared__ float hid[8][HIDN];
    int r0 = blockIdx.x * 8;
    int tid = threadIdx.x;
    for (int i = tid; i < 8 * 96; i += 128) {
        int r = i / 96, c = i % 96;
        int row = r0 + r;
        float v = 0.f;
        if (row < NN) {
            long long gi = (long long)row * 96 + c;
            v = g_h[gi] + fmaxf(0.f, g_hnew[gi] * g_scale_h[c] + g_shift_h[c]);
        }
        hs[r][c] = v;
    }
    __syncthreads();
    float acc[8];
#pragma unroll
    for (int r = 0; r < 8; r++) acc[r] = b1[tid];
#pragma unroll 4
    for (int k = 0; k < 96; k++) {
        float w = W1[k * HIDN + tid];
#pragma unroll
        for (int r = 0; r < 8; r++) acc[r] += hs[r][k] * w;
    }
#pragma unroll
    for (int r = 0; r < 8; r++) hid[r][tid] = fmaxf(acc[r], 0.f);
    __syncthreads();
    if (tid < 64) {
        int r = tid >> 3, c = tid & 7;
        int row = r0 + r;
        if (row < NN) {
            float a = b2[c];
#pragma unroll 8
            for (int k = 0; k < HIDN; k++) a += hid[r][k] * W2[k * OUTD + c];
            out[(long long)row * OUTD + c] = maxa[row] * tanhf(a);
        }
    }
}

// ---------------- launch ----------------
extern "C" void kernel_launch(void* const* d_in, const int* in_sizes, int n_in,
                              void* d_out, int out_size) {
    const float* h1 = (const float*)d_in[0];
    const float* h2 = (const float*)d_in[1];
    const float* z = (const float*)d_in[2];
    const float* efeat = (const float*)d_in[3];
    const float* max_action = (const float*)d_in[4];
    const float* Wh_emb = (const float*)d_in[5];
    const float* bh_emb = (const float*)d_in[6];
    const float* We_emb = (const float*)d_in[7];
    const float* be_emb = (const float*)d_in[8];
    const float* WA = (const float*)d_in[9];
    const float* bA = (const float*)d_in[10];
    const float* WB = (const float*)d_in[11];
    const float* bB = (const float*)d_in[12];
    const float* WC = (const float*)d_in[13];
    const float* bC = (const float*)d_in[14];
    const float* WD = (const float*)d_in[15];
    const float* bD = (const float*)d_in[16];
    const float* WE = (const float*)d_in[17];
    const float* bE = (const float*)d_in[18];
    const float* bn_h_g = (const float*)d_in[19];
    const float* bn_h_b = (const float*)d_in[20];
    const float* bn_e_g = (const float*)d_in[21];
    const float* bn_e_b = (const float*)d_in[22];
    const float* W1 = (const float*)d_in[23];
    const float* b1 = (const float*)d_in[24];
    const float* W2 = (const float*)d_in[25];
    const float* b2 = (const float*)d_in[26];
    const int* src = (const int*)d_in[27];
    const int* dst = (const int*)d_in[28];
    float* out = (float*)d_out;

    __nv_bfloat16 *p_wthi, *p_wtlo;
    cudaGetSymbolAddress((void**)&p_wthi, g_Wt_hi);
    cudaGetSymbolAddress((void**)&p_wtlo, g_Wt_lo);

    const int smem_bytes = SMEM_U32 * 4;  // 93184
    cudaFuncSetAttribute(k_node, cudaFuncAttributeMaxDynamicSharedMemorySize, smem_bytes);
    cudaFuncSetAttribute(k_edge, cudaFuncAttributeMaxDynamicSharedMemorySize, smem_bytes);

    // prep transposed bf16 hi/lo weights: types A=0,B=1,C=2,D=3,E=4
    const int prep_blk = (4 * DD * DD + 255) / 256;
    k_prep<<<prep_blk, 256>>>(WA, p_wthi + 0 * 4 * DD * DD, p_wtlo + 0 * 4 * DD * DD, 4);
    k_prep<<<prep_blk, 256>>>(WB, p_wthi + 1 * 4 * DD * DD, p_wtlo + 1 * 4 * DD * DD, 4);
    k_prep<<<prep_blk, 256>>>(WC, p_wthi + 2 * 4 * DD * DD, p_wtlo + 2 * 4 * DD * DD, 4);
    k_prep<<<prep_blk, 256>>>(WD, p_wthi + 3 * 4 * DD * DD, p_wtlo + 3 * 4 * DD * DD, 4);
    k_prep<<<prep_blk, 256>>>(WE, p_wthi + 4 * 4 * DD * DD, p_wtlo + 4 * 4 * DD * DD, 4);

    k_embed_h<<<(NN * DD + 255) / 256, 256>>>(h1, h2, z, Wh_emb, bh_emb);
    k_embed_e<<<(int)(((long long)EE * DD + 255) / 256), 256>>>(efeat, We_emb, be_emb);

    const int nblk = (NN + 127) / 128;  // 391
    const int eblk = EE / 128;          // 6250

    for (int l = 0; l < 4; l++) {
        k_node<<<nblk, 256, smem_bytes>>>(p_wthi, p_wtlo, bA + l * DD, bB + l * DD,
                                          bD + l * DD, bE + l * DD, l, l > 0 ? 1 : 0);
        k_zero<<<(NN * DD / 4 + 255) / 256, 256>>>();
        k_edge<<<eblk, 256, smem_bytes>>>(p_wthi + (2 * 4 + l) * DD * DD,
                                          p_wtlo + (2 * 4 + l) * DD * DD,
                                          bC + l * DD, src, dst,
                                          l > 0 ? 1 : 0, l == 3 ? 1 : 0);
        if (l < 3)
            k_finalize<<<1, 96>>>(0, bn_e_g + l * DD, bn_e_b + l * DD, 1.f / EE);
        k_hnew<<<256, 384>>>();
        k_finalize<<<1, 96>>>(1, bn_h_g + l * DD, bn_h_b + l * DD, 1.f / NN);
    }

    k_head<<<NN / 8, 128>>>(W1, b1, W2, b2, max_action, out);
}

// round 3
// speedup vs baseline: 1.0169x; 1.0169x over previous
#include <cuda_runtime.h>
#include <cuda_bf16.h>
#include <cuda_fp16.h>
#include <math.h>

#define NN 50000
#define EE 800000
#define DD 96
#define HIDN 128
#define OUTD 8
#define BN_EPS 1e-5f
#define AGG_EPS 1e-6f

// ---------------- device scratch ----------------
__device__ __align__(16) float g_h[NN * DD];
__device__ __align__(16) float g_A[NN * DD];
__device__ __align__(16) __half g_Bh[NN * DD];
__device__ __align__(16) __half g_Dh[NN * DD];
__device__ __align__(16) __half g_Eh[NN * DD];
__device__ __align__(16) float g_num[NN * DD];
__device__ __align__(16) float g_den[NN * DD];
__device__ __align__(16) float g_hnew[NN * DD];
__device__ __align__(16) __half g_e[EE * DD];
__device__ __align__(16) __half g_enew[EE * DD];
__device__ __align__(16) float g_sums[4 * DD];
__device__ __align__(16) float g_scale_e[DD], g_shift_e[DD];
__device__ __align__(16) float g_scale_h[DD], g_shift_h[DD];
// transposed bf16 hi/lo weights: [type(A,B,C,D,E)*4+layer][n*96+k]
__device__ __align__(16) __nv_bfloat16 g_Wt_hi[20 * DD * DD];
__device__ __align__(16) __nv_bfloat16 g_Wt_lo[20 * DD * DD];

// ---------------- helpers ----------------
__device__ __forceinline__ unsigned pack_bf16(float x, float y) {
    __nv_bfloat162 t;
    t.x = __float2bfloat16(x);
    t.y = __float2bfloat16(y);
    return *reinterpret_cast<unsigned*>(&t);
}

__device__ __forceinline__ void mma16816(float* c, const unsigned* a, unsigned b0, unsigned b1) {
    asm volatile(
        "mma.sync.aligned.m16n8k16.row.col.f32.bf16.bf16.f32 "
        "{%0,%1,%2,%3},{%4,%5,%6,%7},{%8,%9},{%0,%1,%2,%3};"
        : "+f"(c[0]), "+f"(c[1]), "+f"(c[2]), "+f"(c[3])
        : "r"(a[0]), "r"(a[1]), "r"(a[2]), "r"(a[3]), "r"(b0), "r"(b1));
}

// ---------------- weight prep: all 20 matrices, transpose + bf16 hi/lo ----------------
struct WPtrs { const float *a, *b, *c, *d, *e; };

__global__ void k_prep(WPtrs p) {
    int idx = blockIdx.x * blockDim.x + threadIdx.x;
    if (idx >= 20 * DD * DD) return;
    int m = idx / (DD * DD), r = idx % (DD * DD);
    int k = r / DD, n = r % DD;
    int type = m >> 2, layer = m & 3;
    const float* src = type == 0 ? p.a : type == 1 ? p.b : type == 2 ? p.c
                       : type == 3 ? p.d : p.e;
    float w = src[layer * DD * DD + k * DD + n];
    __nv_bfloat16 hi = __float2bfloat16(w);
    g_Wt_hi[m * DD * DD + n * DD + k] = hi;
    g_Wt_lo[m * DD * DD + n * DD + k] = __float2bfloat16(w - __bfloat162float(hi));
}

// ---------------- input embeddings (embed_h also zeroes accumulators) ----------------
__global__ void k_embed_h(const float* __restrict__ h1, const float* __restrict__ h2,
                          const float* __restrict__ z, const float* __restrict__ W,
                          const float* __restrict__ b) {
    int idx = blockIdx.x * blockDim.x + threadIdx.x;
    if (idx >= NN * DD) return;
    int row = idx / DD, col = idx % DD;
    float acc = b[col];
    const float* x1 = h1 + row * 6;
#pragma unroll
    for (int k = 0; k < 6; k++) acc += x1[k] * W[k * DD + col];
    const float* x2 = h2 + row * 4;
#pragma unroll
    for (int k = 0; k < 4; k++) acc += x2[k] * W[(6 + k) * DD + col];
    const float* x3 = z + row * 16;
#pragma unroll
    for (int k = 0; k < 16; k++) acc += x3[k] * W[(10 + k) * DD + col];
    g_h[idx] = acc;
    g_num[idx] = 0.f;
    g_den[idx] = 0.f;
    if (idx < 4 * DD) g_sums[idx] = 0.f;
}

__global__ void k_embed_e(const float* __restrict__ ef, const float* __restrict__ W,
                          const float* __restrict__ b) {
    long long idx = (long long)blockIdx.x * blockDim.x + threadIdx.x;
    if (idx >= (long long)EE * 48) return;
    int row = (int)(idx / 48), cp = (int)(idx % 48);
    const float* x = ef + (long long)row * 4;
    float a0 = b[2 * cp], a1 = b[2 * cp + 1];
#pragma unroll
    for (int k = 0; k < 4; k++) {
        a0 += x[k] * W[k * DD + 2 * cp];
        a1 += x[k] * W[k * DD + 2 * cp + 1];
    }
    ((__half2*)g_e)[idx] = __floats2half2_rn(a0, a1);
}

// smem layout (unsigned units): A_hi[128*52] A_lo[128*52] W_hi[96*52] W_lo[96*52]
#define A_HI_OFF 0
#define A_LO_OFF (128 * 52)
#define W_HI_OFF (2 * 128 * 52)
#define W_LO_OFF (2 * 128 * 52 + 96 * 52)
#define SMEM_U32 (2 * 128 * 52 + 2 * 96 * 52)

// ---------------- fused node GEMM: A(fp32), B/D/E(fp16) = h @ W + b (+ h update) ----------------
__global__ __launch_bounds__(256) void k_node(const float* __restrict__ bA, const float* __restrict__ bB,
                                              const float* __restrict__ bD, const float* __restrict__ bE,
                                              int layer, int fuse) {
    extern __shared__ unsigned sm[];
    unsigned* Ahi = sm + A_HI_OFF;
    unsigned* Alo = sm + A_LO_OFF;
    unsigned* Whi = sm + W_HI_OFF;
    unsigned* Wlo = sm + W_LO_OFF;
    int tid = threadIdx.x;
    int m0 = blockIdx.x * 128;
    int rows_valid = NN - m0;
    if (rows_valid > 128) rows_valid = 128;

    for (int i = tid; i < 128 * 24; i += 256) {
        int r = i / 24, c4 = i % 24;
        float4 v = make_float4(0.f, 0.f, 0.f, 0.f);
        if (r < rows_valid) {
            long long gi = (long long)(m0 + r) * 24 + c4;
            v = ((const float4*)g_h)[gi];
            if (fuse) {
                float4 en = ((const float4*)g_hnew)[gi];
                int c = c4 * 4;
                v.x += fmaxf(0.f, en.x * g_scale_h[c] + g_shift_h[c]);
                v.y += fmaxf(0.f, en.y * g_scale_h[c + 1] + g_shift_h[c + 1]);
                v.z += fmaxf(0.f, en.z * g_scale_h[c + 2] + g_shift_h[c + 2]);
                v.w += fmaxf(0.f, en.w * g_scale_h[c + 3] + g_shift_h[c + 3]);
                ((float4*)g_h)[gi] = v;
            }
        }
        float rx = v.x - __bfloat162float(__float2bfloat16(v.x));
        float ry = v.y - __bfloat162float(__float2bfloat16(v.y));
        float rz = v.z - __bfloat162float(__float2bfloat16(v.z));
        float rw = v.w - __bfloat162float(__float2bfloat16(v.w));
        Ahi[r * 52 + c4 * 2] = pack_bf16(v.x, v.y);
        Ahi[r * 52 + c4 * 2 + 1] = pack_bf16(v.z, v.w);
        Alo[r * 52 + c4 * 2] = pack_bf16(rx, ry);
        Alo[r * 52 + c4 * 2 + 1] = pack_bf16(rz, rw);
    }

    int w = tid >> 5, lane = tid & 31;
    int wm = w & 3, wn = w >> 2;
    const int types[4] = {0, 1, 3, 4};  // A, B, D, E
    const float* biases[4] = {bA, bB, bD, bE};
    __half* outsH[4] = {0, g_Bh, g_Dh, g_Eh};

    for (int t = 0; t < 4; t++) {
        __syncthreads();
        const unsigned* gwh = (const unsigned*)(g_Wt_hi + (types[t] * 4 + layer) * DD * DD);
        const unsigned* gwl = (const unsigned*)(g_Wt_lo + (types[t] * 4 + layer) * DD * DD);
        for (int i = tid; i < 96 * 48; i += 256) {
            int n = i / 48, kp = i % 48;
            Whi[n * 52 + kp] = gwh[i];
            Wlo[n * 52 + kp] = gwl[i];
        }
        __syncthreads();

        float acc[2][6][4];
#pragma unroll
        for (int m = 0; m < 2; m++)
#pragma unroll
            for (int n = 0; n < 6; n++)
#pragma unroll
                for (int j = 0; j < 4; j++) acc[m][n][j] = 0.f;

#pragma unroll
        for (int kt = 0; kt < 6; kt++) {
            int kp = kt * 8 + (lane & 3);
            unsigned ah[2][4], al[2][4];
#pragma unroll
            for (int m = 0; m < 2; m++) {
                int row = wm * 32 + m * 16 + (lane >> 2);
                ah[m][0] = Ahi[row * 52 + kp];
                ah[m][1] = Ahi[(row + 8) * 52 + kp];
                ah[m][2] = Ahi[row * 52 + kp + 4];
                ah[m][3] = Ahi[(row + 8) * 52 + kp + 4];
                al[m][0] = Alo[row * 52 + kp];
                al[m][1] = Alo[(row + 8) * 52 + kp];
                al[m][2] = Alo[row * 52 + kp + 4];
                al[m][3] = Alo[(row + 8) * 52 + kp + 4];
            }
#pragma unroll
            for (int n = 0; n < 6; n++) {
                int col = wn * 48 + n * 8 + (lane >> 2);
                unsigned bh0 = Whi[col * 52 + kp], bh1 = Whi[col * 52 + kp + 4];
                unsigned bl0 = Wlo[col * 52 + kp], bl1 = Wlo[col * 52 + kp + 4];
#pragma unroll
                for (int m = 0; m < 2; m++) {
                    mma16816(acc[m][n], ah[m], bh0, bh1);
                    mma16816(acc[m][n], ah[m], bl0, bl1);
                    mma16816(acc[m][n], al[m], bh0, bh1);
                }
            }
        }

        const float* bias = biases[t];
#pragma unroll
        for (int m = 0; m < 2; m++) {
#pragma unroll
            for (int n = 0; n < 6; n++) {
                int row = m0 + wm * 32 + m * 16 + (lane >> 2);
                int col = wn * 48 + n * 8 + ((lane & 3) << 1);
                float b0 = bias[col], b1 = bias[col + 1];
                float v00 = acc[m][n][0] + b0, v01 = acc[m][n][1] + b1;
                float v10 = acc[m][n][2] + b0, v11 = acc[m][n][3] + b1;
                if (t == 0) {
                    if (row < NN)
                        *(float2*)&g_A[(long long)row * 96 + col] = make_float2(v00, v01);
                    if (row + 8 < NN)
                        *(float2*)&g_A[(long long)(row + 8) * 96 + col] = make_float2(v10, v11);
                } else {
                    __half* o = outsH[t];
                    if (row < NN)
                        *(__half2*)&o[(long long)row * 96 + col] = __floats2half2_rn(v00, v01);
                    if (row + 8 < NN)
                        *(__half2*)&o[(long long)(row + 8) * 96 + col] = __floats2half2_rn(v10, v11);
                }
            }
        }
    }
}

// ---------------- fused edge layer ----------------
__global__ __launch_bounds__(256) void k_edge(const __nv_bfloat16* __restrict__ WtHi,
                                              const __nv_bfloat16* __restrict__ WtLo,
                                              const float* __restrict__ bC,
                                              const int* __restrict__ src,
                                              const int* __restrict__ dst,
                                              int fuse, int last) {
    extern __shared__ unsigned sm[];
    unsigned* Ahi = sm + A_HI_OFF;
    unsigned* Alo = sm + A_LO_OFF;
    unsigned* Whi = sm + W_HI_OFF;
    unsigned* Wlo = sm + W_LO_OFF;
    float* Sst = (float*)sm;  // staging 128x100 fp32, aliases A region
    int tid = threadIdx.x;
    int e0 = blockIdx.x * 128;

    // load e tile (fp16) + fused BN residual, split to bf16 hi/lo
    for (int i = tid; i < 128 * 12; i += 256) {
        int r = i / 12, c8 = i % 12;
        long long gi = (long long)(e0 + r) * 12 + c8;
        uint4 v = ((const uint4*)g_e)[gi];
        __half2* vh = (__half2*)&v;
        float2 f[4];
#pragma unroll
        for (int j = 0; j < 4; j++) f[j] = __half22float2(vh[j]);
        if (fuse) {
            uint4 en = ((const uint4*)g_enew)[gi];
            __half2* eh = (__half2*)&en;
            int c = c8 * 8;
#pragma unroll
            for (int j = 0; j < 4; j++) {
                float2 ef = __half22float2(eh[j]);
                f[j].x += fmaxf(0.f, ef.x * g_scale_e[c + 2 * j] + g_shift_e[c + 2 * j]);
                f[j].y += fmaxf(0.f, ef.y * g_scale_e[c + 2 * j + 1] + g_shift_e[c + 2 * j + 1]);
            }
            if (!last) {
#pragma unroll
                for (int j = 0; j < 4; j++) vh[j] = __floats2half2_rn(f[j].x, f[j].y);
                ((uint4*)g_e)[gi] = v;
            }
        }
#pragma unroll
        for (int j = 0; j < 4; j++) {
            int base = r * 52 + c8 * 4 + j;
            Ahi[base] = pack_bf16(f[j].x, f[j].y);
            float rx = f[j].x - __bfloat162float(__float2bfloat16(f[j].x));
            float ry = f[j].y - __bfloat162float(__float2bfloat16(f[j].y));
            Alo[base] = pack_bf16(rx, ry);
        }
    }
    {
        const unsigned* gwh = (const unsigned*)WtHi;
        const unsigned* gwl = (const unsigned*)WtLo;
        for (int i = tid; i < 96 * 48; i += 256) {
            int n = i / 48, kp = i % 48;
            Whi[n * 52 + kp] = gwh[i];
            Wlo[n * 52 + kp] = gwl[i];
        }
    }
    __syncthreads();

    int w = tid >> 5, lane = tid & 31;
    int wm = w & 3, wn = w >> 2;
    float acc[2][6][4];
#pragma unroll
    for (int m = 0; m < 2; m++)
#pragma unroll
        for (int n = 0; n < 6; n++)
#pragma unroll
            for (int j = 0; j < 4; j++) acc[m][n][j] = 0.f;

#pragma unroll
    for (int kt = 0; kt < 6; kt++) {
        int kp = kt * 8 + (lane & 3);
        unsigned ah[2][4], al[2][4];
#pragma unroll
        for (int m = 0; m < 2; m++) {
            int row = wm * 32 + m * 16 + (lane >> 2);
            ah[m][0] = Ahi[row * 52 + kp];
            ah[m][1] = Ahi[(row + 8) * 52 + kp];
            ah[m][2] = Ahi[row * 52 + kp + 4];
            ah[m][3] = Ahi[(row + 8) * 52 + kp + 4];
            al[m][0] = Alo[row * 52 + kp];
            al[m][1] = Alo[(row + 8) * 52 + kp];
            al[m][2] = Alo[row * 52 + kp + 4];
            al[m][3] = Alo[(row + 8) * 52 + kp + 4];
        }
#pragma unroll
        for (int n = 0; n < 6; n++) {
            int col = wn * 48 + n * 8 + (lane >> 2);
            unsigned bh0 = Whi[col * 52 + kp], bh1 = Whi[col * 52 + kp + 4];
            unsigned bl0 = Wlo[col * 52 + kp], bl1 = Wlo[col * 52 + kp + 4];
#pragma unroll
            for (int m = 0; m < 2; m++) {
                mma16816(acc[m][n], ah[m], bh0, bh1);
                mma16816(acc[m][n], ah[m], bl0, bl1);
                mma16816(acc[m][n], al[m], bh0, bh1);
            }
        }
    }
    __syncthreads();  // A smem dead; reuse as staging

#pragma unroll
    for (int m = 0; m < 2; m++) {
#pragma unroll
        for (int n = 0; n < 6; n++) {
            int lr = wm * 32 + m * 16 + (lane >> 2);
            int col = wn * 48 + n * 8 + ((lane & 3) << 1);
            *(float2*)&Sst[lr * 100 + col] = make_float2(acc[m][n][0], acc[m][n][1]);
            *(float2*)&Sst[(lr + 8) * 100 + col] = make_float2(acc[m][n][2], acc[m][n][3]);
        }
    }
    __syncthreads();

    // per-edge epilogue: e_new = Ce + bC + Dh[src] + Eh[dst]; sigmoid; atomics
    {
        int r = tid >> 1, half = tid & 1;
        int e = e0 + r;
        int s = src[e], d = dst[e];
        const uint4* Dr = (const uint4*)(g_Dh + (long long)s * 96) + half * 6;
        const uint4* Er = (const uint4*)(g_Eh + (long long)d * 96) + half * 6;
        const uint4* Br = (const uint4*)(g_Bh + (long long)s * 96) + half * 6;
        float* nr = g_num + (long long)d * 96 + half * 48;
        float* dr = g_den + (long long)d * 96 + half * 48;
        float* sp = Sst + r * 100 + half * 48;
        uint4* ep = (uint4*)g_enew + (long long)e * 12 + half * 6;
        const float* bc = bC + half * 48;
#pragma unroll
        for (int i = 0; i < 6; i++) {
            uint4 du = Dr[i], eu = Er[i], bu = Br[i];
            __half2* dh = (__half2*)&du;
            __half2* ehh = (__half2*)&eu;
            __half2* bh = (__half2*)&bu;
            float vv[8], sg[8], bb[8];
#pragma unroll
            for (int j = 0; j < 4; j++) {
                float2 dv = __half22float2(dh[j]);
                float2 ev = __half22float2(ehh[j]);
                float2 bv = __half22float2(bh[j]);
                vv[2 * j] = sp[i * 8 + 2 * j] + bc[i * 8 + 2 * j] + dv.x + ev.x;
                vv[2 * j + 1] = sp[i * 8 + 2 * j + 1] + bc[i * 8 + 2 * j + 1] + dv.y + ev.y;
                bb[2 * j] = bv.x;
                bb[2 * j + 1] = bv.y;
            }
            if (!last) {
                uint4 outv;
                __half2* oh = (__half2*)&outv;
#pragma unroll
                for (int j = 0; j < 4; j++) oh[j] = __floats2half2_rn(vv[2 * j], vv[2 * j + 1]);
                ep[i] = outv;
#pragma unroll
                for (int j = 0; j < 8; j++) sp[i * 8 + j] = vv[j];
            }
#pragma unroll
            for (int j = 0; j < 8; j++) sg[j] = 1.f / (1.f + __expf(-vv[j]));
            atomicAdd((float4*)(nr + i * 8),
                      make_float4(sg[0] * bb[0], sg[1] * bb[1], sg[2] * bb[2], sg[3] * bb[3]));
            atomicAdd((float4*)(nr + i * 8 + 4),
                      make_float4(sg[4] * bb[4], sg[5] * bb[5], sg[6] * bb[6], sg[7] * bb[7]));
            atomicAdd((float4*)(dr + i * 8), make_float4(sg[0], sg[1], sg[2], sg[3]));
            atomicAdd((float4*)(dr + i * 8 + 4), make_float4(sg[4], sg[5], sg[6], sg[7]));
        }
    }
    __syncthreads();

    if (!last && tid < 96) {
        float s = 0.f, q = 0.f;
#pragma unroll 4
        for (int r = 0; r < 128; r++) {
            float v = Sst[r * 100 + tid];
            s += v;
            q += v * v;
        }
        atomicAdd(&g_sums[tid], s);
        atomicAdd(&g_sums[DD + tid], q);
    }
}

// ---------------- h_new = Ah + num/(den+eps), BN-h moments, re-zero num/den ----------------
__global__ __launch_bounds__(384) void k_hnew() {
    __shared__ float ssum[96], ssq[96];
    int tid = threadIdx.x;
    int col = tid % 96, yr = tid / 96;
    if (tid < 96) { ssum[tid] = 0.f; ssq[tid] = 0.f; }
    __syncthreads();
    float sm = 0.f, sq = 0.f;
    for (int row = blockIdx.x * 4 + yr; row < NN; row += gridDim.x * 4) {
        int i = row * 96 + col;
        float v = g_A[i] + g_num[i] / (g_den[i] + AGG_EPS);
        g_hnew[i] = v;
        g_num[i] = 0.f;
        g_den[i] = 0.f;
        sm += v;
        sq += v * v;
    }
    atomicAdd(&ssum[col], sm);
    atomicAdd(&ssq[col], sq);
    __syncthreads();
    if (tid < 96) {
        atomicAdd(&g_sums[2 * DD + tid], ssum[tid]);
        atomicAdd(&g_sums[3 * DD + tid], ssq[tid]);
    }
}

// ---------------- finalize BN stats (consumes + re-zeroes its slots) ----------------
__global__ void k_finalize(int which, const float* __restrict__ g,
                           const float* __restrict__ b, float invM) {
    int c = threadIdx.x;
    if (c >= 96) return;
    int base = which * 2 * DD;
    float mu = g_sums[base + c] * invM;
    float var = g_sums[base + DD + c] * invM - mu * mu;
    float rstd = rsqrtf(var + BN_EPS);
    float sc = g[c] * rstd;
    float sh = b[c] - mu * sc;
    if (which == 0) { g_scale_e[c] = sc; g_shift_e[c] = sh; }
    else            { g_scale_h[c] = sc; g_shift_h[c] = sh; }
    g_sums[base + c] = 0.f;
    g_sums[base + DD + c] = 0.f;
}

// ---------------- MLP head (applies final h update in-flight) ----------------
__global__ __launch_bounds__(128) void k_head(const float* __restrict__ W1,
                                              const float* __restrict__ b1,
                                              const float* __restrict__ W2,
                                              const float* __restrict__ b2,
                                              const float* __restrict__ maxa,
                                              float* __restrict__ out) {
    __shared__ float hs[8][96];
    __shared__ float hid[8][HIDN];
    int r0 = blockIdx.x * 8;
    int tid = threadIdx.x;
    for (int i = tid; i < 8 * 96; i += 128) {
        int r = i / 96, c = i % 96;
        int row = r0 + r;
        float v = 0.f;
        if (row < NN) {
            long long gi = (long long)row * 96 + c;
            v = g_h[gi] + fmaxf(0.f, g_hnew[gi] * g_scale_h[c] + g_shift_h[c]);
        }
        hs[r][c] = v;
    }
    __syncthreads();
    float acc[8];
#pragma unroll
    for (int r = 0; r < 8; r++) acc[r] = b1[tid];
#pragma unroll 4
    for (int k = 0; k < 96; k++) {
        float w = W1[k * HIDN + tid];
#pragma unroll
        for (int r = 0; r < 8; r++) acc[r] += hs[r][k] * w;
    }
#pragma unroll
    for (int r = 0; r < 8; r++) hid[r][tid] = fmaxf(acc[r], 0.f);
    __syncthreads();
    if (tid < 64) {
        int r = tid >> 3, c = tid & 7;
        int row = r0 + r;
        if (row < NN) {
            float a = b2[c];
#pragma unroll 8
            for (int k = 0; k < HIDN; k++) a += hid[r][k] * W2[k * OUTD + c];
            out[(long long)row * OUTD + c] = maxa[row] * tanhf(a);
        }
    }
}

// ---------------- launch ----------------
extern "C" void kernel_launch(void* const* d_in, const int* in_sizes, int n_in,
                              void* d_out, int out_size) {
    const float* h1 = (const float*)d_in[0];
    const float* h2 = (const float*)d_in[1];
    const float* z = (const float*)d_in[2];
    const float* efeat = (const float*)d_in[3];
    const float* max_action = (const float*)d_in[4];
    const float* Wh_emb = (const float*)d_in[5];
    const float* bh_emb = (const float*)d_in[6];
    const float* We_emb = (const float*)d_in[7];
    const float* be_emb = (const float*)d_in[8];
    const float* WA = (const float*)d_in[9];
    const float* bA = (const float*)d_in[10];
    const float* WB = (const float*)d_in[11];
    const float* bB = (const float*)d_in[12];
    const float* WC = (const float*)d_in[13];
    const float* bC = (const float*)d_in[14];
    const float* WD = (const float*)d_in[15];
    const float* bD = (const float*)d_in[16];
    const float* WE = (const float*)d_in[17];
    const float* bE = (const float*)d_in[18];
    const float* bn_h_g = (const float*)d_in[19];
    const float* bn_h_b = (const float*)d_in[20];
    const float* bn_e_g = (const float*)d_in[21];
    const float* bn_e_b = (const float*)d_in[22];
    const float* W1 = (const float*)d_in[23];
    const float* b1 = (const float*)d_in[24];
    const float* W2 = (const float*)d_in[25];
    const float* b2 = (const float*)d_in[26];
    const int* src = (const int*)d_in[27];
    const int* dst = (const int*)d_in[28];
    float* out = (float*)d_out;

    __nv_bfloat16 *p_wthi, *p_wtlo;
    cudaGetSymbolAddress((void**)&p_wthi, g_Wt_hi);
    cudaGetSymbolAddress((void**)&p_wtlo, g_Wt_lo);

    const int smem_bytes = SMEM_U32 * 4;  // 93184
    cudaFuncSetAttribute(k_node, cudaFuncAttributeMaxDynamicSharedMemorySize, smem_bytes);
    cudaFuncSetAttribute(k_edge, cudaFuncAttributeMaxDynamicSharedMemorySize, smem_bytes);

    WPtrs wp{WA, WB, WC, WD, WE};
    k_prep<<<(20 * DD * DD + 255) / 256, 256>>>(wp);
    k_embed_h<<<(NN * DD + 255) / 256, 256>>>(h1, h2, z, Wh_emb, bh_emb);
    k_embed_e<<<(int)(((long long)EE * 48 + 255) / 256), 256>>>(efeat, We_emb, be_emb);

    const int nblk = (NN + 127) / 128;  // 391
    const int eblk = EE / 128;          // 6250

    for (int l = 0; l < 4; l++) {
        k_node<<<nblk, 256, smem_bytes>>>(bA + l * DD, bB + l * DD, bD + l * DD, bE + l * DD,
                                          l, l > 0 ? 1 : 0);
        k_edge<<<eblk, 256, smem_bytes>>>(p_wthi + (2 * 4 + l) * DD * DD,
                                          p_wtlo + (2 * 4 + l) * DD * DD,
                                          bC + l * DD, src, dst,
                                          l > 0 ? 1 : 0, l == 3 ? 1 : 0);
        if (l < 3)
            k_finalize<<<1, 96>>>(0, bn_e_g + l * DD, bn_e_b + l * DD, 1.f / EE);
        k_hnew<<<256, 384>>>();
        k_finalize<<<1, 96>>>(1, bn_h_g + l * DD, bn_h_b + l * DD, 1.f / NN);
    }

    k_head<<<NN / 8, 128>>>(W1, b1, W2, b2, max_action, out);
}

// round 5
// speedup vs baseline: 1.1672x; 1.1478x over previous
#include <cuda_runtime.h>
#include <cuda_bf16.h>
#include <cuda_fp16.h>
#include <math.h>

#define NN 50000
#define EE 800000
#define DD 96
#define HIDN 128
#define OUTD 8
#define BN_EPS 1e-5f
#define AGG_EPS 1e-6f

// ---------------- device scratch ----------------
__device__ __align__(16) float g_h[NN * DD];
__device__ __align__(16) float g_A[NN * DD];
__device__ __align__(16) __half g_Bh[NN * DD];
__device__ __align__(16) __half g_Dh[NN * DD];
__device__ __align__(16) __half g_Eh[NN * DD];
__device__ __align__(16) float g_agg[NN * DD * 2];  // interleaved num/den
__device__ __align__(16) float g_hnew[NN * DD];
__device__ __align__(16) __half g_e[EE * DD];       // sorted order
__device__ __align__(16) __half g_enew[EE * DD];    // sorted order
__device__ __align__(16) float g_sums[4 * DD];
__device__ __align__(16) float g_scale_e[DD], g_shift_e[DD];
__device__ __align__(16) float g_scale_h[DD], g_shift_h[DD];
__device__ __align__(16) __nv_bfloat16 g_Wt_hi[20 * DD * DD];
__device__ __align__(16) __nv_bfloat16 g_Wt_lo[20 * DD * DD];
// dst-sorted edge structure
__device__ int g_perm[EE];
__device__ int g_src_s[EE];
__device__ int g_dst_s[EE];
__device__ int g_off[NN];
__device__ int g_cursor[NN];

// ---------------- helpers ----------------
__device__ __forceinline__ unsigned pack_bf16(float x, float y) {
    __nv_bfloat162 t;
    t.x = __float2bfloat16(x);
    t.y = __float2bfloat16(y);
    return *reinterpret_cast<unsigned*>(&t);
}

__device__ __forceinline__ void mma16816(float* c, const unsigned* a, unsigned b0, unsigned b1) {
    asm volatile(
        "mma.sync.aligned.m16n8k16.row.col.f32.bf16.bf16.f32 "
        "{%0,%1,%2,%3},{%4,%5,%6,%7},{%8,%9},{%0,%1,%2,%3};"
        : "+f"(c[0]), "+f"(c[1]), "+f"(c[2]), "+f"(c[3])
        : "r"(a[0]), "r"(a[1]), "r"(a[2]), "r"(a[3]), "r"(b0), "r"(b1));
}

// ---------------- counting sort by dst ----------------
__global__ void k_zoff() {
    int i = blockIdx.x * blockDim.x + threadIdx.x;
    if (i < NN) { g_off[i] = 0; g_cursor[i] = 0; }
}

__global__ void k_hist(const int* __restrict__ dst) {
    int e = blockIdx.x * blockDim.x + threadIdx.x;
    if (e < EE) atomicAdd(&g_off[dst[e]], 1);
}

__global__ void k_scan() {  // single block, 1024 threads: exclusive prefix of g_off
    __shared__ int ssum[1024];
    const int STRIP = (NN + 1023) / 1024;  // 49
    int t = threadIdx.x;
    int beg = t * STRIP, end = beg + STRIP;
    if (end > NN) end = NN;
    int s = 0;
    for (int i = beg; i < end; i++) s += g_off[i];
    ssum[t] = s;
    __syncthreads();
    for (int ofs = 1; ofs < 1024; ofs <<= 1) {
        int v = (t >= ofs) ? ssum[t - ofs] : 0;
        __syncthreads();
        ssum[t] += v;
        __syncthreads();
    }
    int carry = (t > 0) ? ssum[t - 1] : 0;
    for (int i = beg; i < end; i++) {
        int v = g_off[i];
        g_off[i] = carry;
        carry += v;
    }
}

__global__ void k_scatter(const int* __restrict__ src, const int* __restrict__ dst) {
    int e = blockIdx.x * blockDim.x + threadIdx.x;
    if (e >= EE) return;
    int d = dst[e];
    int p = g_off[d] + atomicAdd(&g_cursor[d], 1);
    g_perm[p] = e;
    g_src_s[p] = src[e];
    g_dst_s[p] = d;
}

// ---------------- weight prep ----------------
struct WPtrs { const float *a, *b, *c, *d, *e; };

__global__ void k_prep(WPtrs p) {
    int idx = blockIdx.x * blockDim.x + threadIdx.x;
    if (idx >= 20 * DD * DD) return;
    int m = idx / (DD * DD), r = idx % (DD * DD);
    int k = r / DD, n = r % DD;
    int type = m >> 2, layer = m & 3;
    const float* src = type == 0 ? p.a : type == 1 ? p.b : type == 2 ? p.c
                       : type == 3 ? p.d : p.e;
    float w = src[layer * DD * DD + k * DD + n];
    __nv_bfloat16 hi = __float2bfloat16(w);
    g_Wt_hi[m * DD * DD + n * DD + k] = hi;
    g_Wt_lo[m * DD * DD + n * DD + k] = __float2bfloat16(w - __bfloat162float(hi));
}

// ---------------- input embeddings ----------------
__global__ void k_embed_h(const float* __restrict__ h1, const float* __restrict__ h2,
                          const float* __restrict__ z, const float* __restrict__ W,
                          const float* __restrict__ b) {
    int idx = blockIdx.x * blockDim.x + threadIdx.x;
    if (idx >= NN * DD) return;
    int row = idx / DD, col = idx % DD;
    float acc = b[col];
    const float* x1 = h1 + row * 6;
#pragma unroll
    for (int k = 0; k < 6; k++) acc += x1[k] * W[k * DD + col];
    const float* x2 = h2 + row * 4;
#pragma unroll
    for (int k = 0; k < 4; k++) acc += x2[k] * W[(6 + k) * DD + col];
    const float* x3 = z + row * 16;
#pragma unroll
    for (int k = 0; k < 16; k++) acc += x3[k] * W[(10 + k) * DD + col];
    g_h[idx] = acc;
    ((float2*)g_agg)[idx] = make_float2(0.f, 0.f);
    if (idx < 4 * DD) g_sums[idx] = 0.f;
}

__global__ void k_embed_e(const float* __restrict__ ef, const float* __restrict__ W,
                          const float* __restrict__ b) {
    long long idx = (long long)blockIdx.x * blockDim.x + threadIdx.x;
    if (idx >= (long long)EE * 48) return;
    int p = (int)(idx / 48), cp = (int)(idx % 48);
    const float* x = ef + (long long)g_perm[p] * 4;
    float a0 = b[2 * cp], a1 = b[2 * cp + 1];
#pragma unroll
    for (int k = 0; k < 4; k++) {
        a0 += x[k] * W[k * DD + 2 * cp];
        a1 += x[k] * W[k * DD + 2 * cp + 1];
    }
    ((__half2*)g_e)[idx] = __floats2half2_rn(a0, a1);
}

// smem layout (unsigned units): A_hi[128*52] A_lo[128*52] W_hi[96*52] W_lo[96*52]
#define A_HI_OFF 0
#define A_LO_OFF (128 * 52)
#define W_HI_OFF (2 * 128 * 52)
#define W_LO_OFF (2 * 128 * 52 + 96 * 52)
#define SMEM_U32 (2 * 128 * 52 + 2 * 96 * 52)

// ---------------- fused node GEMM: A(fp32), B/D/E(fp16) ----------------
__global__ __launch_bounds__(256) void k_node(const float* __restrict__ bA, const float* __restrict__ bB,
                                              const float* __restrict__ bD, const float* __restrict__ bE,
                                              int layer, int fuse) {
    extern __shared__ unsigned sm[];
    unsigned* Ahi = sm + A_HI_OFF;
    unsigned* Alo = sm + A_LO_OFF;
    unsigned* Whi = sm + W_HI_OFF;
    unsigned* Wlo = sm + W_LO_OFF;
    int tid = threadIdx.x;
    int m0 = blockIdx.x * 128;
    int rows_valid = NN - m0;
    if (rows_valid > 128) rows_valid = 128;

    for (int i = tid; i < 128 * 24; i += 256) {
        int r = i / 24, c4 = i % 24;
        float4 v = make_float4(0.f, 0.f, 0.f, 0.f);
        if (r < rows_valid) {
            long long gi = (long long)(m0 + r) * 24 + c4;
            v = ((const float4*)g_h)[gi];
            if (fuse) {
                float4 en = ((const float4*)g_hnew)[gi];
                int c = c4 * 4;
                v.x += fmaxf(0.f, en.x * g_scale_h[c] + g_shift_h[c]);
                v.y += fmaxf(0.f, en.y * g_scale_h[c + 1] + g_shift_h[c + 1]);
                v.z += fmaxf(0.f, en.z * g_scale_h[c + 2] + g_shift_h[c + 2]);
                v.w += fmaxf(0.f, en.w * g_scale_h[c + 3] + g_shift_h[c + 3]);
                ((float4*)g_h)[gi] = v;
            }
        }
        float rx = v.x - __bfloat162float(__float2bfloat16(v.x));
        float ry = v.y - __bfloat162float(__float2bfloat16(v.y));
        float rz = v.z - __bfloat162float(__float2bfloat16(v.z));
        float rw = v.w - __bfloat162float(__float2bfloat16(v.w));
        Ahi[r * 52 + c4 * 2] = pack_bf16(v.x, v.y);
        Ahi[r * 52 + c4 * 2 + 1] = pack_bf16(v.z, v.w);
        Alo[r * 52 + c4 * 2] = pack_bf16(rx, ry);
        Alo[r * 52 + c4 * 2 + 1] = pack_bf16(rz, rw);
    }

    int w = tid >> 5, lane = tid & 31;
    int wm = w & 3, wn = w >> 2;
    const int types[4] = {0, 1, 3, 4};
    const float* biases[4] = {bA, bB, bD, bE};
    __half* outsH[4] = {0, g_Bh, g_Dh, g_Eh};

    for (int t = 0; t < 4; t++) {
        __syncthreads();
        const unsigned* gwh = (const unsigned*)(g_Wt_hi + (types[t] * 4 + layer) * DD * DD);
        const unsigned* gwl = (const unsigned*)(g_Wt_lo + (types[t] * 4 + layer) * DD * DD);
        for (int i = tid; i < 96 * 48; i += 256) {
            int n = i / 48, kp = i % 48;
            Whi[n * 52 + kp] = gwh[i];
            Wlo[n * 52 + kp] = gwl[i];
        }
        __syncthreads();

        float acc[2][6][4];
#pragma unroll
        for (int m = 0; m < 2; m++)
#pragma unroll
            for (int n = 0; n < 6; n++)
#pragma unroll
                for (int j = 0; j < 4; j++) acc[m][n][j] = 0.f;

#pragma unroll
        for (int kt = 0; kt < 6; kt++) {
            int kp = kt * 8 + (lane & 3);
            unsigned ah[2][4], al[2][4];
#pragma unroll
            for (int m = 0; m < 2; m++) {
                int row = wm * 32 + m * 16 + (lane >> 2);
                ah[m][0] = Ahi[row * 52 + kp];
                ah[m][1] = Ahi[(row + 8) * 52 + kp];
                ah[m][2] = Ahi[row * 52 + kp + 4];
                ah[m][3] = Ahi[(row + 8) * 52 + kp + 4];
                al[m][0] = Alo[row * 52 + kp];
                al[m][1] = Alo[(row + 8) * 52 + kp];
                al[m][2] = Alo[row * 52 + kp + 4];
                al[m][3] = Alo[(row + 8) * 52 + kp + 4];
            }
#pragma unroll
            for (int n = 0; n < 6; n++) {
                int col = wn * 48 + n * 8 + (lane >> 2);
                unsigned bh0 = Whi[col * 52 + kp], bh1 = Whi[col * 52 + kp + 4];
                unsigned bl0 = Wlo[col * 52 + kp], bl1 = Wlo[col * 52 + kp + 4];
#pragma unroll
                for (int m = 0; m < 2; m++) {
                    mma16816(acc[m][n], ah[m], bh0, bh1);
                    mma16816(acc[m][n], ah[m], bl0, bl1);
                    mma16816(acc[m][n], al[m], bh0, bh1);
                }
            }
        }

        const float* bias = biases[t];
#pragma unroll
        for (int m = 0; m < 2; m++) {
#pragma unroll
            for (int n = 0; n < 6; n++) {
                int row = m0 + wm * 32 + m * 16 + (lane >> 2);
                int col = wn * 48 + n * 8 + ((lane & 3) << 1);
                float b0 = bias[col], b1 = bias[col + 1];
                float v00 = acc[m][n][0] + b0, v01 = acc[m][n][1] + b1;
                float v10 = acc[m][n][2] + b0, v11 = acc[m][n][3] + b1;
                if (t == 0) {
                    if (row < NN)
                        *(float2*)&g_A[(long long)row * 96 + col] = make_float2(v00, v01);
                    if (row + 8 < NN)
                        *(float2*)&g_A[(long long)(row + 8) * 96 + col] = make_float2(v10, v11);
                } else {
                    __half* o = outsH[t];
                    if (row < NN)
                        *(__half2*)&o[(long long)row * 96 + col] = __floats2half2_rn(v00, v01);
                    if (row + 8 < NN)
                        *(__half2*)&o[(long long)(row + 8) * 96 + col] = __floats2half2_rn(v10, v11);
                }
            }
        }
    }
}

// ---------------- fused edge layer (dst-sorted) ----------------
__global__ __launch_bounds__(256) void k_edge(const __nv_bfloat16* __restrict__ WtHi,
                                              const __nv_bfloat16* __restrict__ WtLo,
                                              const float* __restrict__ bC,
                                              int fuse, int last) {
    extern __shared__ unsigned sm[];
    unsigned* Ahi = sm + A_HI_OFF;
    unsigned* Alo = sm + A_LO_OFF;
    unsigned* Whi = sm + W_HI_OFF;
    unsigned* Wlo = sm + W_LO_OFF;
    float* Sst = (float*)sm;  // staging 128x100 fp32, aliases A region
    __shared__ int s_src[128], s_dst[128];
    __shared__ float bn_s[2][96], bn_q[2][96];
    int tid = threadIdx.x;
    int e0 = blockIdx.x * 128;

    if (tid < 128) {
        s_src[tid] = g_src_s[e0 + tid];
        s_dst[tid] = g_dst_s[e0 + tid];
    }

    // load e tile (fp16) + fused BN residual, split bf16 hi/lo
    for (int i = tid; i < 128 * 12; i += 256) {
        int r = i / 12, c8 = i % 12;
        long long gi = (long long)(e0 + r) * 12 + c8;
        uint4 v = ((const uint4*)g_e)[gi];
        __half2* vh = (__half2*)&v;
        float2 f[4];
#pragma unroll
        for (int j = 0; j < 4; j++) f[j] = __half22float2(vh[j]);
        if (fuse) {
            uint4 en = ((const uint4*)g_enew)[gi];
            __half2* eh = (__half2*)&en;
            int c = c8 * 8;
#pragma unroll
            for (int j = 0; j < 4; j++) {
                float2 ef = __half22float2(eh[j]);
                f[j].x += fmaxf(0.f, ef.x * g_scale_e[c + 2 * j] + g_shift_e[c + 2 * j]);
                f[j].y += fmaxf(0.f, ef.y * g_scale_e[c + 2 * j + 1] + g_shift_e[c + 2 * j + 1]);
            }
            if (!last) {
#pragma unroll
                for (int j = 0; j < 4; j++) vh[j] = __floats2half2_rn(f[j].x, f[j].y);
                ((uint4*)g_e)[gi] = v;
            }
        }
#pragma unroll
        for (int j = 0; j < 4; j++) {
            int base = r * 52 + c8 * 4 + j;
            Ahi[base] = pack_bf16(f[j].x, f[j].y);
            float rx = f[j].x - __bfloat162float(__float2bfloat16(f[j].x));
            float ry = f[j].y - __bfloat162float(__float2bfloat16(f[j].y));
            Alo[base] = pack_bf16(rx, ry);
        }
    }
    {
        const unsigned* gwh = (const unsigned*)WtHi;
        const unsigned* gwl = (const unsigned*)WtLo;
        for (int i = tid; i < 96 * 48; i += 256) {
            int n = i / 48, kp = i % 48;
            Whi[n * 52 + kp] = gwh[i];
            Wlo[n * 52 + kp] = gwl[i];
        }
    }
    __syncthreads();

    int w = tid >> 5, lane = tid & 31;
    int wm = w & 3, wn = w >> 2;
    float acc[2][6][4];
#pragma unroll
    for (int m = 0; m < 2; m++)
#pragma unroll
        for (int n = 0; n < 6; n++)
#pragma unroll
            for (int j = 0; j < 4; j++) acc[m][n][j] = 0.f;

#pragma unroll
    for (int kt = 0; kt < 6; kt++) {
        int kp = kt * 8 + (lane & 3);
        unsigned ah[2][4], al[2][4];
#pragma unroll
        for (int m = 0; m < 2; m++) {
            int row = wm * 32 + m * 16 + (lane >> 2);
            ah[m][0] = Ahi[row * 52 + kp];
            ah[m][1] = Ahi[(row + 8) * 52 + kp];
            ah[m][2] = Ahi[row * 52 + kp + 4];
            ah[m][3] = Ahi[(row + 8) * 52 + kp + 4];
            al[m][0] = Alo[row * 52 + kp];
            al[m][1] = Alo[(row + 8) * 52 + kp];
            al[m][2] = Alo[row * 52 + kp + 4];
            al[m][3] = Alo[(row + 8) * 52 + kp + 4];
        }
#pragma unroll
        for (int n = 0; n < 6; n++) {
            int col = wn * 48 + n * 8 + (lane >> 2);
            unsigned bh0 = Whi[col * 52 + kp], bh1 = Whi[col * 52 + kp + 4];
            unsigned bl0 = Wlo[col * 52 + kp], bl1 = Wlo[col * 52 + kp + 4];
#pragma unroll
            for (int m = 0; m < 2; m++) {
                mma16816(acc[m][n], ah[m], bh0, bh1);
                mma16816(acc[m][n], ah[m], bl0, bl1);
                mma16816(acc[m][n], al[m], bh0, bh1);
            }
        }
    }
    __syncthreads();  // A smem dead; reuse as staging

#pragma unroll
    for (int m = 0; m < 2; m++) {
#pragma unroll
        for (int n = 0; n < 6; n++) {
            int lr = wm * 32 + m * 16 + (lane >> 2);
            int col = wn * 48 + n * 8 + ((lane & 3) << 1);
            *(float2*)&Sst[lr * 100 + col] = make_float2(acc[m][n][0], acc[m][n][1]);
            *(float2*)&Sst[(lr + 8) * 100 + col] = make_float2(acc[m][n][2], acc[m][n][3]);
        }
    }
    __syncthreads();

    // pass 1: per-edge vv = Ce + bC + Dh[src] + Eh[dst]; store vv; write e_new
    {
        int r = tid >> 1, half = tid & 1;
        int s = s_src[r], d = s_dst[r];
        const uint4* Dr = (const uint4*)(g_Dh + (long long)s * 96) + half * 6;
        const uint4* Er = (const uint4*)(g_Eh + (long long)d * 96) + half * 6;
        float* sp = Sst + r * 100 + half * 48;
        uint4* ep = (uint4*)g_enew + (long long)(e0 + r) * 12 + half * 6;
        const float* bc = bC + half * 48;
#pragma unroll
        for (int i = 0; i < 6; i++) {
            uint4 du = Dr[i], eu = Er[i];
            __half2* dh = (__half2*)&du;
            __half2* ehh = (__half2*)&eu;
            float vv[8];
#pragma unroll
            for (int j = 0; j < 4; j++) {
                float2 dv = __half22float2(dh[j]);
                float2 ev = __half22float2(ehh[j]);
                vv[2 * j] = sp[i * 8 + 2 * j] + bc[i * 8 + 2 * j] + dv.x + ev.x;
                vv[2 * j + 1] = sp[i * 8 + 2 * j + 1] + bc[i * 8 + 2 * j + 1] + dv.y + ev.y;
            }
#pragma unroll
            for (int j = 0; j < 8; j++) sp[i * 8 + j] = vv[j];
            if (!last) {
                uint4 outv;
                __half2* oh = (__half2*)&outv;
#pragma unroll
                for (int j = 0; j < 4; j++) oh[j] = __floats2half2_rn(vv[2 * j], vv[2 * j + 1]);
                ep[i] = outv;
            }
        }
    }
    __syncthreads();

    // pass 2: per-column segment scan over dst-sorted rows
    if (tid < 192) {
        int col = tid % 96;
        int g = tid / 96;
        int rbeg = g * 64, rend = rbeg + 64;
        float num_acc = 0.f, den_acc = 0.f, bs = 0.f, bq = 0.f;
        int d = s_dst[rbeg];
        for (int r = rbeg; r < rend; r++) {
            float vv = Sst[r * 100 + col];
            float sg = 1.f / (1.f + __expf(-vv));
            float bv = __half2float(g_Bh[(long long)s_src[r] * 96 + col]);
            num_acc += sg * bv;
            den_acc += sg;
            bs += vv;
            bq += vv * vv;
            int dn = (r + 1 < rend) ? s_dst[r + 1] : -1;
            if (dn != d) {
                atomicAdd((float2*)&g_agg[((long long)d * 96 + col) * 2],
                          make_float2(num_acc, den_acc));
                num_acc = 0.f;
                den_acc = 0.f;
                d = dn;
            }
        }
        bn_s[g][col] = bs;
        bn_q[g][col] = bq;
    }
    __syncthreads();
    if (!last && tid < 96) {
        atomicAdd(&g_sums[tid], bn_s[0][tid] + bn_s[1][tid]);
        atomicAdd(&g_sums[DD + tid], bn_q[0][tid] + bn_q[1][tid]);
    }
}

// ---------------- h_new = Ah + num/(den+eps), BN-h moments, re-zero agg ----------------
__global__ __launch_bounds__(384) void k_hnew() {
    __shared__ float ssum[96], ssq[96];
    int tid = threadIdx.x;
    int col = tid % 96, yr = tid / 96;
    if (tid < 96) { ssum[tid] = 0.f; ssq[tid] = 0.f; }
    __syncthreads();
    float sm = 0.f, sq = 0.f;
    for (int row = blockIdx.x * 4 + yr; row < NN; row += gridDim.x * 4) {
        int i = row * 96 + col;
        float2 nd = ((float2*)g_agg)[i];
        float v = g_A[i] + nd.x / (nd.y + AGG_EPS);
        g_hnew[i] = v;
        ((float2*)g_agg)[i] = make_float2(0.f, 0.f);
        sm += v;
        sq += v * v;
    }
    atomicAdd(&ssum[col], sm);
    atomicAdd(&ssq[col], sq);
    __syncthreads();
    if (tid < 96) {
        atomicAdd(&g_sums[2 * DD + tid], ssum[tid]);
        atomicAdd(&g_sums[3 * DD + tid], ssq[tid]);
    }
}

// ---------------- finalize BN stats ----------------
__global__ void k_finalize(int which, const float* __restrict__ g,
                           const float* __restrict__ b, float invM) {
    int c = threadIdx.x;
    if (c >= 96) return;
    int base = which * 2 * DD;
    float mu = g_sums[base + c] * invM;
    float var = g_sums[base + DD + c] * invM - mu * mu;
    float rstd = rsqrtf(var + BN_EPS);
    float sc = g[c] * rstd;
    float sh = b[c] - mu * sc;
    if (which == 0) { g_scale_e[c] = sc; g_shift_e[c] = sh; }
    else            { g_scale_h[c] = sc; g_shift_h[c] = sh; }
    g_sums[base + c] = 0.f;
    g_sums[base + DD + c] = 0.f;
}

// ---------------- MLP head ----------------
__global__ __launch_bounds__(128) void k_head(const float* __restrict__ W1,
                                              const float* __restrict__ b1,
                                              const float* __restrict__ W2,
                                              const float* __restrict__ b2,
                                              const float* __restrict__ maxa,
                                              float* __restrict__ out) {
    __shared__ float hs[8][96];
    __shared__ float hid[8][HIDN];
    int r0 = blockIdx.x * 8;
    int tid = threadIdx.x;
    for (int i = tid; i < 8 * 96; i += 128) {
        int r = i / 96, c = i % 96;
        int row = r0 + r;
        float v = 0.f;
        if (row < NN) {
            long long gi = (long long)row * 96 + c;
            v = g_h[gi] + fmaxf(0.f, g_hnew[gi] * g_scale_h[c] + g_shift_h[c]);
        }
        hs[r][c] = v;
    }
    __syncthreads();
    float acc[8];
#pragma unroll
    for (int r = 0; r < 8; r++) acc[r] = b1[tid];
#pragma unroll 4
    for (int k = 0; k < 96; k++) {
        float w = W1[k * HIDN + tid];
#pragma unroll
        for (int r = 0; r < 8; r++) acc[r] += hs[r][k] * w;
    }
#pragma unroll
    for (int r = 0; r < 8; r++) hid[r][tid] = fmaxf(acc[r], 0.f);
    __syncthreads();
    if (tid < 64) {
        int r = tid >> 3, c = tid & 7;
        int row = r0 + r;
        if (row < NN) {
            float a = b2[c];
#pragma unroll 8
            for (int k = 0; k < HIDN; k++) a += hid[r][k] * W2[k * OUTD + c];
            out[(long long)row * OUTD + c] = maxa[row] * tanhf(a);
        }
    }
}

// ---------------- launch ----------------
extern "C" void kernel_launch(void* const* d_in, const int* in_sizes, int n_in,
                              void* d_out, int out_size) {
    const float* h1 = (const float*)d_in[0];
    const float* h2 = (const float*)d_in[1];
    const float* z = (const float*)d_in[2];
    const float* efeat = (const float*)d_in[3];
    const float* max_action = (const float*)d_in[4];
    const float* Wh_emb = (const float*)d_in[5];
    const float* bh_emb = (const float*)d_in[6];
    const float* We_emb = (const float*)d_in[7];
    const float* be_emb = (const float*)d_in[8];
    const float* WA = (const float*)d_in[9];
    const float* bA = (const float*)d_in[10];
    const float* WB = (const float*)d_in[11];
    const float* bB = (const float*)d_in[12];
    const float* WC = (const float*)d_in[13];
    const float* bC = (const float*)d_in[14];
    const float* WD = (const float*)d_in[15];
    const float* bD = (const float*)d_in[16];
    const float* WE = (const float*)d_in[17];
    const float* bE = (const float*)d_in[18];
    const float* bn_h_g = (const float*)d_in[19];
    const float* bn_h_b = (const float*)d_in[20];
    const float* bn_e_g = (const float*)d_in[21];
    const float* bn_e_b = (const float*)d_in[22];
    const float* W1 = (const float*)d_in[23];
    const float* b1 = (const float*)d_in[24];
    const float* W2 = (const float*)d_in[25];
    const float* b2 = (const float*)d_in[26];
    const int* src = (const int*)d_in[27];
    const int* dst = (const int*)d_in[28];
    float* out = (float*)d_out;

    __nv_bfloat16 *p_wthi, *p_wtlo;
    cudaGetSymbolAddress((void**)&p_wthi, g_Wt_hi);
    cudaGetSymbolAddress((void**)&p_wtlo, g_Wt_lo);

    const int smem_bytes = SMEM_U32 * 4;  // 93184
    cudaFuncSetAttribute(k_node, cudaFuncAttributeMaxDynamicSharedMemorySize, smem_bytes);
    cudaFuncSetAttribute(k_edge, cudaFuncAttributeMaxDynamicSharedMemorySize, smem_bytes);

    // dst-sorted edge permutation
    k_zoff<<<(NN + 255) / 256, 256>>>();
    k_hist<<<(EE + 255) / 256, 256>>>(dst);
    k_scan<<<1, 1024>>>();
    k_scatter<<<(EE + 255) / 256, 256>>>(src, dst);

    WPtrs wp{WA, WB, WC, WD, WE};
    k_prep<<<(20 * DD * DD + 255) / 256, 256>>>(wp);
    k_embed_h<<<(NN * DD + 255) / 256, 256>>>(h1, h2, z, Wh_emb, bh_emb);
    k_embed_e<<<(int)(((long long)EE * 48 + 255) / 256), 256>>>(efeat, We_emb, be_emb);

    const int nblk = (NN + 127) / 128;  // 391
    const int eblk = EE / 128;          // 6250

    for (int l = 0; l < 4; l++) {
        k_node<<<nblk, 256, smem_bytes>>>(bA + l * DD, bB + l * DD, bD + l * DD, bE + l * DD,
                                          l, l > 0 ? 1 : 0);
        k_edge<<<eblk, 256, smem_bytes>>>(p_wthi + (2 * 4 + l) * DD * DD,
                                          p_wtlo + (2 * 4 + l) * DD * DD,
                                          bC + l * DD, l > 0 ? 1 : 0, l == 3 ? 1 : 0);
        if (l < 3)
            k_finalize<<<1, 96>>>(0, bn_e_g + l * DD, bn_e_b + l * DD, 1.f / EE);
        k_hnew<<<256, 384>>>();
        k_finalize<<<1, 96>>>(1, bn_h_g + l * DD, bn_h_b + l * DD, 1.f / NN);
    }

    k_head<<<NN / 8, 128>>>(W1, b1, W2, b2, max_action, out);
}

// round 6
// speedup vs baseline: 1.5662x; 1.3419x over previous
#include <cuda_runtime.h>
#include <cuda_bf16.h>
#include <cuda_fp16.h>
#include <math.h>

#define NN 50000
#define EE 800000
#define DD 96
#define HIDN 128
#define OUTD 8
#define BN_EPS 1e-5f
#define AGG_EPS 1e-6f

// ---------------- device scratch ----------------
__device__ __align__(16) float g_h[NN * DD];
__device__ __align__(16) float g_A[NN * DD];
__device__ __align__(16) __half g_Bh[NN * DD];
__device__ __align__(16) __half g_Dh[NN * DD];
__device__ __align__(16) __half g_Eh[NN * DD];
__device__ __align__(16) float g_agg[NN * DD * 2];  // interleaved num/den
__device__ __align__(16) float g_hnew[NN * DD];
__device__ __align__(16) __half g_e[EE * DD];       // sorted order
__device__ __align__(16) __half g_enew[EE * DD];    // sorted order
__device__ __align__(16) float g_sums[4 * DD];
__device__ __align__(16) float g_scale_e[DD], g_shift_e[DD];
__device__ __align__(16) float g_scale_h[DD], g_shift_h[DD];
__device__ __align__(16) __nv_bfloat16 g_Wt_hi[20 * DD * DD];
__device__ __align__(16) __nv_bfloat16 g_Wt_lo[20 * DD * DD];
// dst-sorted edge structure
__device__ int g_perm[EE];
__device__ int g_src_s[EE];
__device__ int g_dst_s[EE];
__device__ int g_off[NN];
__device__ int g_cursor[NN];

// ---------------- helpers ----------------
__device__ __forceinline__ unsigned pack_bf16(float x, float y) {
    __nv_bfloat162 t;
    t.x = __float2bfloat16(x);
    t.y = __float2bfloat16(y);
    return *reinterpret_cast<unsigned*>(&t);
}

__device__ __forceinline__ float sigmoid_fast(float x) {
    float t;
    asm("tanh.approx.f32 %0, %1;" : "=f"(t) : "f"(0.5f * x));
    return fmaf(0.5f, t, 0.5f);
}

__device__ __forceinline__ void mma16816(float* c, const unsigned* a, unsigned b0, unsigned b1) {
    asm volatile(
        "mma.sync.aligned.m16n8k16.row.col.f32.bf16.bf16.f32 "
        "{%0,%1,%2,%3},{%4,%5,%6,%7},{%8,%9},{%0,%1,%2,%3};"
        : "+f"(c[0]), "+f"(c[1]), "+f"(c[2]), "+f"(c[3])
        : "r"(a[0]), "r"(a[1]), "r"(a[2]), "r"(a[3]), "r"(b0), "r"(b1));
}

// ---------------- counting sort by dst ----------------
__global__ void k_zoff() {
    int i = blockIdx.x * blockDim.x + threadIdx.x;
    if (i < NN) { g_off[i] = 0; g_cursor[i] = 0; }
}

__global__ void k_hist(const int* __restrict__ dst) {
    int e = blockIdx.x * blockDim.x + threadIdx.x;
    if (e < EE) atomicAdd(&g_off[dst[e]], 1);
}

__global__ void k_scan() {  // single block, 1024 threads: exclusive prefix of g_off
    __shared__ int ssum[1024];
    const int STRIP = (NN + 1023) / 1024;  // 49
    int t = threadIdx.x;
    int beg = t * STRIP, end = beg + STRIP;
    if (end > NN) end = NN;
    int s = 0;
    for (int i = beg; i < end; i++) s += g_off[i];
    ssum[t] = s;
    __syncthreads();
    for (int ofs = 1; ofs < 1024; ofs <<= 1) {
        int v = (t >= ofs) ? ssum[t - ofs] : 0;
        __syncthreads();
        ssum[t] += v;
        __syncthreads();
    }
    int carry = (t > 0) ? ssum[t - 1] : 0;
    for (int i = beg; i < end; i++) {
        int v = g_off[i];
        g_off[i] = carry;
        carry += v;
    }
}

__global__ void k_scatter(const int* __restrict__ src, const int* __restrict__ dst) {
    int e = blockIdx.x * blockDim.x + threadIdx.x;
    if (e >= EE) return;
    int d = dst[e];
    int p = g_off[d] + atomicAdd(&g_cursor[d], 1);
    g_perm[p] = e;
    g_src_s[p] = src[e];
    g_dst_s[p] = d;
}

// ---------------- weight prep ----------------
struct WPtrs { const float *a, *b, *c, *d, *e; };

__global__ void k_prep(WPtrs p) {
    int idx = blockIdx.x * blockDim.x + threadIdx.x;
    if (idx >= 20 * DD * DD) return;
    int m = idx / (DD * DD), r = idx % (DD * DD);
    int k = r / DD, n = r % DD;
    int type = m >> 2, layer = m & 3;
    const float* src = type == 0 ? p.a : type == 1 ? p.b : type == 2 ? p.c
                       : type == 3 ? p.d : p.e;
    float w = src[layer * DD * DD + k * DD + n];
    __nv_bfloat16 hi = __float2bfloat16(w);
    g_Wt_hi[m * DD * DD + n * DD + k] = hi;
    g_Wt_lo[m * DD * DD + n * DD + k] = __float2bfloat16(w - __bfloat162float(hi));
}

// ---------------- input embeddings ----------------
__global__ void k_embed_h(const float* __restrict__ h1, const float* __restrict__ h2,
                          const float* __restrict__ z, const float* __restrict__ W,
                          const float* __restrict__ b) {
    int idx = blockIdx.x * blockDim.x + threadIdx.x;
    if (idx >= NN * DD) return;
    int row = idx / DD, col = idx % DD;
    float acc = b[col];
    const float* x1 = h1 + row * 6;
#pragma unroll
    for (int k = 0; k < 6; k++) acc += x1[k] * W[k * DD + col];
    const float* x2 = h2 + row * 4;
#pragma unroll
    for (int k = 0; k < 4; k++) acc += x2[k] * W[(6 + k) * DD + col];
    const float* x3 = z + row * 16;
#pragma unroll
    for (int k = 0; k < 16; k++) acc += x3[k] * W[(10 + k) * DD + col];
    g_h[idx] = acc;
    ((float2*)g_agg)[idx] = make_float2(0.f, 0.f);
    if (idx < 4 * DD) g_sums[idx] = 0.f;
}

__global__ void k_embed_e(const float* __restrict__ ef, const float* __restrict__ W,
                          const float* __restrict__ b) {
    long long idx = (long long)blockIdx.x * blockDim.x + threadIdx.x;
    if (idx >= (long long)EE * 48) return;
    int p = (int)(idx / 48), cp = (int)(idx % 48);
    const float* x = ef + (long long)g_perm[p] * 4;
    float a0 = b[2 * cp], a1 = b[2 * cp + 1];
#pragma unroll
    for (int k = 0; k < 4; k++) {
        a0 += x[k] * W[k * DD + 2 * cp];
        a1 += x[k] * W[k * DD + 2 * cp + 1];
    }
    ((__half2*)g_e)[idx] = __floats2half2_rn(a0, a1);
}

// smem layout (unsigned units): A_hi[128*52] A_lo[128*52] W_hi[96*52] W_lo[96*52]
// epilogue aliasing: Sst1 (128x100 f32) at 0; Sst2 (128x100 f32) at 13312 u32
#define A_HI_OFF 0
#define A_LO_OFF (128 * 52)
#define W_HI_OFF (2 * 128 * 52)
#define W_LO_OFF (2 * 128 * 52 + 96 * 52)
#define SST2_OFF (2 * 128 * 52)
#define SMEM_U32 (2 * 128 * 52 + 128 * 100)   // 26112 u32 = 104448 B

// ---------------- fused node GEMM: A(fp32), B/D/E(fp16) ----------------
__global__ __launch_bounds__(256) void k_node(const float* __restrict__ bA, const float* __restrict__ bB,
                                              const float* __restrict__ bD, const float* __restrict__ bE,
                                              int layer, int fuse) {
    extern __shared__ unsigned sm[];
    unsigned* Ahi = sm + A_HI_OFF;
    unsigned* Alo = sm + A_LO_OFF;
    unsigned* Whi = sm + W_HI_OFF;
    unsigned* Wlo = sm + W_LO_OFF;
    int tid = threadIdx.x;
    int m0 = blockIdx.x * 128;
    int rows_valid = NN - m0;
    if (rows_valid > 128) rows_valid = 128;

    for (int i = tid; i < 128 * 24; i += 256) {
        int r = i / 24, c4 = i % 24;
        float4 v = make_float4(0.f, 0.f, 0.f, 0.f);
        if (r < rows_valid) {
            long long gi = (long long)(m0 + r) * 24 + c4;
            v = ((const float4*)g_h)[gi];
            if (fuse) {
                float4 en = ((const float4*)g_hnew)[gi];
                int c = c4 * 4;
                v.x += fmaxf(0.f, en.x * g_scale_h[c] + g_shift_h[c]);
                v.y += fmaxf(0.f, en.y * g_scale_h[c + 1] + g_shift_h[c + 1]);
                v.z += fmaxf(0.f, en.z * g_scale_h[c + 2] + g_shift_h[c + 2]);
                v.w += fmaxf(0.f, en.w * g_scale_h[c + 3] + g_shift_h[c + 3]);
                ((float4*)g_h)[gi] = v;
            }
        }
        float rx = v.x - __bfloat162float(__float2bfloat16(v.x));
        float ry = v.y - __bfloat162float(__float2bfloat16(v.y));
        float rz = v.z - __bfloat162float(__float2bfloat16(v.z));
        float rw = v.w - __bfloat162float(__float2bfloat16(v.w));
        Ahi[r * 52 + c4 * 2] = pack_bf16(v.x, v.y);
        Ahi[r * 52 + c4 * 2 + 1] = pack_bf16(v.z, v.w);
        Alo[r * 52 + c4 * 2] = pack_bf16(rx, ry);
        Alo[r * 52 + c4 * 2 + 1] = pack_bf16(rz, rw);
    }

    int w = tid >> 5, lane = tid & 31;
    int wm = w & 3, wn = w >> 2;
    const int types[4] = {0, 1, 3, 4};
    const float* biases[4] = {bA, bB, bD, bE};
    __half* outsH[4] = {0, g_Bh, g_Dh, g_Eh};

    for (int t = 0; t < 4; t++) {
        __syncthreads();
        const unsigned* gwh = (const unsigned*)(g_Wt_hi + (types[t] * 4 + layer) * DD * DD);
        const unsigned* gwl = (const unsigned*)(g_Wt_lo + (types[t] * 4 + layer) * DD * DD);
        for (int i = tid; i < 96 * 48; i += 256) {
            int n = i / 48, kp = i % 48;
            Whi[n * 52 + kp] = gwh[i];
            Wlo[n * 52 + kp] = gwl[i];
        }
        __syncthreads();

        float acc[2][6][4];
#pragma unroll
        for (int m = 0; m < 2; m++)
#pragma unroll
            for (int n = 0; n < 6; n++)
#pragma unroll
                for (int j = 0; j < 4; j++) acc[m][n][j] = 0.f;

#pragma unroll
        for (int kt = 0; kt < 6; kt++) {
            int kp = kt * 8 + (lane & 3);
            unsigned ah[2][4], al[2][4];
#pragma unroll
            for (int m = 0; m < 2; m++) {
                int row = wm * 32 + m * 16 + (lane >> 2);
                ah[m][0] = Ahi[row * 52 + kp];
                ah[m][1] = Ahi[(row + 8) * 52 + kp];
                ah[m][2] = Ahi[row * 52 + kp + 4];
                ah[m][3] = Ahi[(row + 8) * 52 + kp + 4];
                al[m][0] = Alo[row * 52 + kp];
                al[m][1] = Alo[(row + 8) * 52 + kp];
                al[m][2] = Alo[row * 52 + kp + 4];
                al[m][3] = Alo[(row + 8) * 52 + kp + 4];
            }
#pragma unroll
            for (int n = 0; n < 6; n++) {
                int col = wn * 48 + n * 8 + (lane >> 2);
                unsigned bh0 = Whi[col * 52 + kp], bh1 = Whi[col * 52 + kp + 4];
                unsigned bl0 = Wlo[col * 52 + kp], bl1 = Wlo[col * 52 + kp + 4];
#pragma unroll
                for (int m = 0; m < 2; m++) {
                    mma16816(acc[m][n], ah[m], bh0, bh1);
                    mma16816(acc[m][n], ah[m], bl0, bl1);
                    mma16816(acc[m][n], al[m], bh0, bh1);
                }
            }
        }

        const float* bias = biases[t];
#pragma unroll
        for (int m = 0; m < 2; m++) {
#pragma unroll
            for (int n = 0; n < 6; n++) {
                int row = m0 + wm * 32 + m * 16 + (lane >> 2);
                int col = wn * 48 + n * 8 + ((lane & 3) << 1);
                float b0 = bias[col], b1 = bias[col + 1];
                float v00 = acc[m][n][0] + b0, v01 = acc[m][n][1] + b1;
                float v10 = acc[m][n][2] + b0, v11 = acc[m][n][3] + b1;
                if (t == 0) {
                    if (row < NN)
                        *(float2*)&g_A[(long long)row * 96 + col] = make_float2(v00, v01);
                    if (row + 8 < NN)
                        *(float2*)&g_A[(long long)(row + 8) * 96 + col] = make_float2(v10, v11);
                } else {
                    __half* o = outsH[t];
                    if (row < NN)
                        *(__half2*)&o[(long long)row * 96 + col] = __floats2half2_rn(v00, v01);
                    if (row + 8 < NN)
                        *(__half2*)&o[(long long)(row + 8) * 96 + col] = __floats2half2_rn(v10, v11);
                }
            }
        }
    }
}

// ---------------- fused edge layer (dst-sorted, smem-staged epilogue) ----------------
__global__ __launch_bounds__(256) void k_edge(const __nv_bfloat16* __restrict__ WtHi,
                                              const __nv_bfloat16* __restrict__ WtLo,
                                              const float* __restrict__ bC,
                                              int fuse, int last) {
    extern __shared__ unsigned sm[];
    unsigned* Ahi = sm + A_HI_OFF;
    unsigned* Alo = sm + A_LO_OFF;
    unsigned* Whi = sm + W_HI_OFF;
    unsigned* Wlo = sm + W_LO_OFF;
    float* Sst = (float*)sm;                  // vv staging 128x100
    float* Sbv = (float*)(sm + SST2_OFF);     // Bv staging 128x100
    __shared__ int s_src[128], s_dst[128];
    __shared__ float bn_s[2][96], bn_q[2][96];
    int tid = threadIdx.x;
    int e0 = blockIdx.x * 128;

    if (tid < 128) {
        s_src[tid] = g_src_s[e0 + tid];
        s_dst[tid] = g_dst_s[e0 + tid];
    }

    // load e tile (fp16) + fused BN residual, split bf16 hi/lo
    for (int i = tid; i < 128 * 12; i += 256) {
        int r = i / 12, c8 = i % 12;
        long long gi = (long long)(e0 + r) * 12 + c8;
        uint4 v = ((const uint4*)g_e)[gi];
        __half2* vh = (__half2*)&v;
        float2 f[4];
#pragma unroll
        for (int j = 0; j < 4; j++) f[j] = __half22float2(vh[j]);
        if (fuse) {
            uint4 en = ((const uint4*)g_enew)[gi];
            __half2* eh = (__half2*)&en;
            int c = c8 * 8;
#pragma unroll
            for (int j = 0; j < 4; j++) {
                float2 ef = __half22float2(eh[j]);
                f[j].x += fmaxf(0.f, ef.x * g_scale_e[c + 2 * j] + g_shift_e[c + 2 * j]);
                f[j].y += fmaxf(0.f, ef.y * g_scale_e[c + 2 * j + 1] + g_shift_e[c + 2 * j + 1]);
            }
            if (!last) {
#pragma unroll
                for (int j = 0; j < 4; j++) vh[j] = __floats2half2_rn(f[j].x, f[j].y);
                ((uint4*)g_e)[gi] = v;
            }
        }
#pragma unroll
        for (int j = 0; j < 4; j++) {
            int base = r * 52 + c8 * 4 + j;
            Ahi[base] = pack_bf16(f[j].x, f[j].y);
            float rx = f[j].x - __bfloat162float(__float2bfloat16(f[j].x));
            float ry = f[j].y - __bfloat162float(__float2bfloat16(f[j].y));
            Alo[base] = pack_bf16(rx, ry);
        }
    }
    {
        const unsigned* gwh = (const unsigned*)WtHi;
        const unsigned* gwl = (const unsigned*)WtLo;
        for (int i = tid; i < 96 * 48; i += 256) {
            int n = i / 48, kp = i % 48;
            Whi[n * 52 + kp] = gwh[i];
            Wlo[n * 52 + kp] = gwl[i];
        }
    }
    __syncthreads();

    int w = tid >> 5, lane = tid & 31;
    int wm = w & 3, wn = w >> 2;
    float acc[2][6][4];
#pragma unroll
    for (int m = 0; m < 2; m++)
#pragma unroll
        for (int n = 0; n < 6; n++)
#pragma unroll
            for (int j = 0; j < 4; j++) acc[m][n][j] = 0.f;

#pragma unroll
    for (int kt = 0; kt < 6; kt++) {
        int kp = kt * 8 + (lane & 3);
        unsigned ah[2][4], al[2][4];
#pragma unroll
        for (int m = 0; m < 2; m++) {
            int row = wm * 32 + m * 16 + (lane >> 2);
            ah[m][0] = Ahi[row * 52 + kp];
            ah[m][1] = Ahi[(row + 8) * 52 + kp];
            ah[m][2] = Ahi[row * 52 + kp + 4];
            ah[m][3] = Ahi[(row + 8) * 52 + kp + 4];
            al[m][0] = Alo[row * 52 + kp];
            al[m][1] = Alo[(row + 8) * 52 + kp];
            al[m][2] = Alo[row * 52 + kp + 4];
            al[m][3] = Alo[(row + 8) * 52 + kp + 4];
        }
#pragma unroll
        for (int n = 0; n < 6; n++) {
            int col = wn * 48 + n * 8 + (lane >> 2);
            unsigned bh0 = Whi[col * 52 + kp], bh1 = Whi[col * 52 + kp + 4];
            unsigned bl0 = Wlo[col * 52 + kp], bl1 = Wlo[col * 52 + kp + 4];
#pragma unroll
            for (int m = 0; m < 2; m++) {
                mma16816(acc[m][n], ah[m], bh0, bh1);
                mma16816(acc[m][n], ah[m], bl0, bl1);
                mma16816(acc[m][n], al[m], bh0, bh1);
            }
        }
    }
    __syncthreads();  // A & W smem dead; reuse as staging

#pragma unroll
    for (int m = 0; m < 2; m++) {
#pragma unroll
        for (int n = 0; n < 6; n++) {
            int lr = wm * 32 + m * 16 + (lane >> 2);
            int col = wn * 48 + n * 8 + ((lane & 3) << 1);
            *(float2*)&Sst[lr * 100 + col] = make_float2(acc[m][n][0], acc[m][n][1]);
            *(float2*)&Sst[(lr + 8) * 100 + col] = make_float2(acc[m][n][2], acc[m][n][3]);
        }
    }
    __syncthreads();

    // pass 1 (per edge, 2 threads/row): vv = Ce+bC+Dh[src]+Eh[dst]; stage vv + Bv; write e_new
    {
        int r = tid >> 1, half = tid & 1;
        int s = s_src[r], d = s_dst[r];
        const uint4* Dr = (const uint4*)(g_Dh + (long long)s * 96) + half * 6;
        const uint4* Er = (const uint4*)(g_Eh + (long long)d * 96) + half * 6;
        const uint4* Br = (const uint4*)(g_Bh + (long long)s * 96) + half * 6;
        float* sp = Sst + r * 100 + half * 48;
        float* bp = Sbv + r * 100 + half * 48;
        uint4* ep = (uint4*)g_enew + (long long)(e0 + r) * 12 + half * 6;
        const float* bc = bC + half * 48;
#pragma unroll
        for (int i = 0; i < 6; i++) {
            uint4 du = Dr[i], eu = Er[i], bu = Br[i];
            __half2* dh = (__half2*)&du;
            __half2* ehh = (__half2*)&eu;
            __half2* bh = (__half2*)&bu;
            float vv[8];
#pragma unroll
            for (int j = 0; j < 4; j++) {
                float2 dv = __half22float2(dh[j]);
                float2 ev = __half22float2(ehh[j]);
                float2 bv = __half22float2(bh[j]);
                vv[2 * j] = sp[i * 8 + 2 * j] + bc[i * 8 + 2 * j] + dv.x + ev.x;
                vv[2 * j + 1] = sp[i * 8 + 2 * j + 1] + bc[i * 8 + 2 * j + 1] + dv.y + ev.y;
                bp[i * 8 + 2 * j] = bv.x;
                bp[i * 8 + 2 * j + 1] = bv.y;
            }
#pragma unroll
            for (int j = 0; j < 8; j++) sp[i * 8 + j] = vv[j];
            if (!last) {
                uint4 outv;
                __half2* oh = (__half2*)&outv;
#pragma unroll
                for (int j = 0; j < 4; j++) oh[j] = __floats2half2_rn(vv[2 * j], vv[2 * j + 1]);
                ep[i] = outv;
            }
        }
    }
    __syncthreads();

    // pass 2: per-column segment scan, pure smem
    if (tid < 192) {
        int col = tid % 96;
        int g = tid / 96;
        int rbeg = g * 64, rend = rbeg + 64;
        float num_acc = 0.f, den_acc = 0.f, bs = 0.f, bq = 0.f;
        int d = s_dst[rbeg];
        for (int r = rbeg; r < rend; r++) {
            float vv = Sst[r * 100 + col];
            float bv = Sbv[r * 100 + col];
            float sg = sigmoid_fast(vv);
            num_acc = fmaf(sg, bv, num_acc);
            den_acc += sg;
            bs += vv;
            bq = fmaf(vv, vv, bq);
            int dn = (r + 1 < rend) ? s_dst[r + 1] : -1;
            if (dn != d) {
                atomicAdd((float2*)&g_agg[((long long)d * 96 + col) * 2],
                          make_float2(num_acc, den_acc));
                num_acc = 0.f;
                den_acc = 0.f;
                d = dn;
            }
        }
        bn_s[g][col] = bs;
        bn_q[g][col] = bq;
    }
    __syncthreads();
    if (!last && tid < 96) {
        atomicAdd(&g_sums[tid], bn_s[0][tid] + bn_s[1][tid]);
        atomicAdd(&g_sums[DD + tid], bn_q[0][tid] + bn_q[1][tid]);
    }
}

// ---------------- h_new = Ah + num/(den+eps), BN-h moments, re-zero agg ----------------
__global__ __launch_bounds__(384) void k_hnew() {
    __shared__ float ssum[96], ssq[96];
    int tid = threadIdx.x;
    int col = tid % 96, yr = tid / 96;
    if (tid < 96) { ssum[tid] = 0.f; ssq[tid] = 0.f; }
    __syncthreads();
    float sm = 0.f, sq = 0.f;
    for (int row = blockIdx.x * 4 + yr; row < NN; row += gridDim.x * 4) {
        int i = row * 96 + col;
        float2 nd = ((float2*)g_agg)[i];
        float v = g_A[i] + nd.x / (nd.y + AGG_EPS);
        g_hnew[i] = v;
        ((float2*)g_agg)[i] = make_float2(0.f, 0.f);
        sm += v;
        sq = fmaf(v, v, sq);
    }
    atomicAdd(&ssum[col], sm);
    atomicAdd(&ssq[col], sq);
    __syncthreads();
    if (tid < 96) {
        atomicAdd(&g_sums[2 * DD + tid], ssum[tid]);
        atomicAdd(&g_sums[3 * DD + tid], ssq[tid]);
    }
}

// ---------------- finalize BN stats ----------------
__global__ void k_finalize(int which, const float* __restrict__ g,
                           const float* __restrict__ b, float invM) {
    int c = threadIdx.x;
    if (c >= 96) return;
    int base = which * 2 * DD;
    float mu = g_sums[base + c] * invM;
    float var = g_sums[base + DD + c] * invM - mu * mu;
    float rstd = rsqrtf(var + BN_EPS);
    float sc = g[c] * rstd;
    float sh = b[c] - mu * sc;
    if (which == 0) { g_scale_e[c] = sc; g_shift_e[c] = sh; }
    else            { g_scale_h[c] = sc; g_shift_h[c] = sh; }
    g_sums[base + c] = 0.f;
    g_sums[base + DD + c] = 0.f;
}

// ---------------- MLP head ----------------
__global__ __launch_bounds__(128) void k_head(const float* __restrict__ W1,
                                              const float* __restrict__ b1,
                                              const float* __restrict__ W2,
                                              const float* __restrict__ b2,
                                              const float* __restrict__ maxa,
                                              float* __restrict__ out) {
    __shared__ float hs[8][96];
    __shared__ float hid[8][HIDN];
    int r0 = blockIdx.x * 8;
    int tid = threadIdx.x;
    for (int i = tid; i < 8 * 96; i += 128) {
        int r = i / 96, c = i % 96;
        int row = r0 + r;
        float v = 0.f;
        if (row < NN) {
            long long gi = (long long)row * 96 + c;
            v = g_h[gi] + fmaxf(0.f, g_hnew[gi] * g_scale_h[c] + g_shift_h[c]);
        }
        hs[r][c] = v;
    }
    __syncthreads();
    float acc[8];
#pragma unroll
    for (int r = 0; r < 8; r++) acc[r] = b1[tid];
#pragma unroll 4
    for (int k = 0; k < 96; k++) {
        float w = W1[k * HIDN + tid];
#pragma unroll
        for (int r = 0; r < 8; r++) acc[r] += hs[r][k] * w;
    }
#pragma unroll
    for (int r = 0; r < 8; r++) hid[r][tid] = fmaxf(acc[r], 0.f);
    __syncthreads();
    if (tid < 64) {
        int r = tid >> 3, c = tid & 7;
        int row = r0 + r;
        if (row < NN) {
            float a = b2[c];
#pragma unroll 8
            for (int k = 0; k < HIDN; k++) a += hid[r][k] * W2[k * OUTD + c];
            out[(long long)row * OUTD + c] = maxa[row] * tanhf(a);
        }
    }
}

// ---------------- launch ----------------
extern "C" void kernel_launch(void* const* d_in, const int* in_sizes, int n_in,
                              void* d_out, int out_size) {
    const float* h1 = (const float*)d_in[0];
    const float* h2 = (const float*)d_in[1];
    const float* z = (const float*)d_in[2];
    const float* efeat = (const float*)d_in[3];
    const float* max_action = (const float*)d_in[4];
    const float* Wh_emb = (const float*)d_in[5];
    const float* bh_emb = (const float*)d_in[6];
    const float* We_emb = (const float*)d_in[7];
    const float* be_emb = (const float*)d_in[8];
    const float* WA = (const float*)d_in[9];
    const float* bA = (const float*)d_in[10];
    const float* WB = (const float*)d_in[11];
    const float* bB = (const float*)d_in[12];
    const float* WC = (const float*)d_in[13];
    const float* bC = (const float*)d_in[14];
    const float* WD = (const float*)d_in[15];
    const float* bD = (const float*)d_in[16];
    const float* WE = (const float*)d_in[17];
    const float* bE = (const float*)d_in[18];
    const float* bn_h_g = (const float*)d_in[19];
    const float* bn_h_b = (const float*)d_in[20];
    const float* bn_e_g = (const float*)d_in[21];
    const float* bn_e_b = (const float*)d_in[22];
    const float* W1 = (const float*)d_in[23];
    const float* b1 = (const float*)d_in[24];
    const float* W2 = (const float*)d_in[25];
    const float* b2 = (const float*)d_in[26];
    const int* src = (const int*)d_in[27];
    const int* dst = (const int*)d_in[28];
    float* out = (float*)d_out;

    __nv_bfloat16 *p_wthi, *p_wtlo;
    cudaGetSymbolAddress((void**)&p_wthi, g_Wt_hi);
    cudaGetSymbolAddress((void**)&p_wtlo, g_Wt_lo);

    const int smem_node = (2 * 128 * 52 + 2 * 96 * 52) * 4;  // 93184
    const int smem_edge = SMEM_U32 * 4;                       // 104448
    cudaFuncSetAttribute(k_node, cudaFuncAttributeMaxDynamicSharedMemorySize, smem_node);
    cudaFuncSetAttribute(k_edge, cudaFuncAttributeMaxDynamicSharedMemorySize, smem_edge);

    // dst-sorted edge permutation
    k_zoff<<<(NN + 255) / 256, 256>>>();
    k_hist<<<(EE + 255) / 256, 256>>>(dst);
    k_scan<<<1, 1024>>>();
    k_scatter<<<(EE + 255) / 256, 256>>>(src, dst);

    WPtrs wp{WA, WB, WC, WD, WE};
    k_prep<<<(20 * DD * DD + 255) / 256, 256>>>(wp);
    k_embed_h<<<(NN * DD + 255) / 256, 256>>>(h1, h2, z, Wh_emb, bh_emb);
    k_embed_e<<<(int)(((long long)EE * 48 + 255) / 256), 256>>>(efeat, We_emb, be_emb);

    const int nblk = (NN + 127) / 128;  // 391
    const int eblk = EE / 128;          // 6250

    for (int l = 0; l < 4; l++) {
        k_node<<<nblk, 256, smem_node>>>(bA + l * DD, bB + l * DD, bD + l * DD, bE + l * DD,
                                         l, l > 0 ? 1 : 0);
        k_edge<<<eblk, 256, smem_edge>>>(p_wthi + (2 * 4 + l) * DD * DD,
                                         p_wtlo + (2 * 4 + l) * DD * DD,
                                         bC + l * DD, l > 0 ? 1 : 0, l == 3 ? 1 : 0);
        if (l < 3)
            k_finalize<<<1, 96>>>(0, bn_e_g + l * DD, bn_e_b + l * DD, 1.f / EE);
        k_hnew<<<256, 384>>>();
        k_finalize<<<1, 96>>>(1, bn_h_g + l * DD, bn_h_b + l * DD, 1.f / NN);
    }

    k_head<<<NN / 8, 128>>>(W1, b1, W2, b2, max_action, out);
}

// round 7
// speedup vs baseline: 2.1690x; 1.3848x over previous
#include <cuda_runtime.h>
#include <cuda_bf16.h>
#include <cuda_fp16.h>
#include <math.h>

#define NN 50000
#define EE 800000
#define DD 96
#define HIDN 128
#define OUTD 8
#define BN_EPS 1e-5f
#define AGG_EPS 1e-6f
#define NTILE 6250

// ---------------- device scratch ----------------
__device__ __align__(16) float g_h[NN * DD];
__device__ __align__(16) float g_A[NN * DD];
__device__ __align__(16) __half g_Bh[NN * DD];
__device__ __align__(16) __half g_Dh[NN * DD];
__device__ __align__(16) __half g_Eh[NN * DD];
__device__ __align__(16) float g_agg[NN * DD * 2];  // interleaved num/den
__device__ __align__(16) float g_hnew[NN * DD];
__device__ __align__(16) __half g_e[EE * DD];       // sorted order
__device__ __align__(16) __half g_enew[EE * DD];    // sorted order
__device__ __align__(16) float g_sums[4 * DD];
__device__ __align__(16) float g_scale_e[DD], g_shift_e[DD];
__device__ __align__(16) float g_scale_h[DD], g_shift_h[DD];
__device__ __align__(16) __nv_bfloat16 g_Wt_hi[20 * DD * DD];  // node types bf16
__device__ __align__(16) __nv_bfloat16 g_Wt_lo[20 * DD * DD];
__device__ __align__(16) __half g_Wc_hi[4 * DD * DD];          // edge C fp16
__device__ __align__(16) __half g_Wc_lo[4 * DD * DD];
// dst-sorted edge structure
__device__ int g_perm[EE];
__device__ int g_src_s[EE];
__device__ int g_dst_s[EE];
__device__ int g_off[NN];
__device__ int g_cursor[NN];

// ---------------- helpers ----------------
__device__ __forceinline__ unsigned pack_bf16(float x, float y) {
    __nv_bfloat162 t;
    t.x = __float2bfloat16(x);
    t.y = __float2bfloat16(y);
    return *reinterpret_cast<unsigned*>(&t);
}

__device__ __forceinline__ float sigmoid_fast(float x) {
    float t;
    asm("tanh.approx.f32 %0, %1;" : "=f"(t) : "f"(0.5f * x));
    return fmaf(0.5f, t, 0.5f);
}

__device__ __forceinline__ void mma_bf16(float* c, const unsigned* a, unsigned b0, unsigned b1) {
    asm volatile(
        "mma.sync.aligned.m16n8k16.row.col.f32.bf16.bf16.f32 "
        "{%0,%1,%2,%3},{%4,%5,%6,%7},{%8,%9},{%0,%1,%2,%3};"
        : "+f"(c[0]), "+f"(c[1]), "+f"(c[2]), "+f"(c[3])
        : "r"(a[0]), "r"(a[1]), "r"(a[2]), "r"(a[3]), "r"(b0), "r"(b1));
}

__device__ __forceinline__ void mma_f16(float* c, const unsigned* a, unsigned b0, unsigned b1) {
    asm volatile(
        "mma.sync.aligned.m16n8k16.row.col.f32.f16.f16.f32 "
        "{%0,%1,%2,%3},{%4,%5,%6,%7},{%8,%9},{%0,%1,%2,%3};"
        : "+f"(c[0]), "+f"(c[1]), "+f"(c[2]), "+f"(c[3])
        : "r"(a[0]), "r"(a[1]), "r"(a[2]), "r"(a[3]), "r"(b0), "r"(b1));
}

// ---------------- counting sort by dst ----------------
__global__ void k_hist(const int* __restrict__ dst) {
    int e = blockIdx.x * blockDim.x + threadIdx.x;
    if (e < EE) atomicAdd(&g_off[dst[e]], 1);
}

__global__ void k_scan() {
    __shared__ int ssum[1024];
    const int STRIP = (NN + 1023) / 1024;
    int t = threadIdx.x;
    int beg = t * STRIP, end = beg + STRIP;
    if (end > NN) end = NN;
    int s = 0;
    for (int i = beg; i < end; i++) s += g_off[i];
    ssum[t] = s;
    __syncthreads();
    for (int ofs = 1; ofs < 1024; ofs <<= 1) {
        int v = (t >= ofs) ? ssum[t - ofs] : 0;
        __syncthreads();
        ssum[t] += v;
        __syncthreads();
    }
    int carry = (t > 0) ? ssum[t - 1] : 0;
    for (int i = beg; i < end; i++) {
        int v = g_off[i];
        g_off[i] = carry;
        carry += v;
    }
}

__global__ void k_scatter(const int* __restrict__ src, const int* __restrict__ dst) {
    int e = blockIdx.x * blockDim.x + threadIdx.x;
    if (e >= EE) return;
    int d = dst[e];
    int p = g_off[d] + atomicAdd(&g_cursor[d], 1);
    g_perm[p] = e;
    g_src_s[p] = src[e];
    g_dst_s[p] = d;
}

// ---------------- weight prep ----------------
struct WPtrs { const float *a, *b, *c, *d, *e; };

__global__ void k_prep(WPtrs p) {
    int idx = blockIdx.x * blockDim.x + threadIdx.x;
    if (idx >= 20 * DD * DD) return;
    int m = idx / (DD * DD), r = idx % (DD * DD);
    int k = r / DD, n = r % DD;
    int type = m >> 2, layer = m & 3;
    const float* src = type == 0 ? p.a : type == 1 ? p.b : type == 2 ? p.c
                       : type == 3 ? p.d : p.e;
    float w = src[layer * DD * DD + k * DD + n];
    __nv_bfloat16 hi = __float2bfloat16(w);
    g_Wt_hi[m * DD * DD + n * DD + k] = hi;
    g_Wt_lo[m * DD * DD + n * DD + k] = __float2bfloat16(w - __bfloat162float(hi));
    if (type == 2) {
        __half h16 = __float2half(w);
        g_Wc_hi[layer * DD * DD + n * DD + k] = h16;
        g_Wc_lo[layer * DD * DD + n * DD + k] = __float2half(w - __half2float(h16));
    }
}

// smem layout node (u32): A_hi[128*52] A_lo[128*52] W_hi[96*52] W_lo[96*52]
#define A_HI_OFF 0
#define A_LO_OFF (128 * 52)
#define W_HI_OFF (2 * 128 * 52)
#define W_LO_OFF (2 * 128 * 52 + 96 * 52)
#define NODE_U32 (2 * 128 * 52 + 2 * 96 * 52)

// ---------------- fused node GEMM: A(fp32), B/D/E(fp16); layer0 fuses input embed ----------------
__global__ __launch_bounds__(256) void k_node(const float* __restrict__ bA, const float* __restrict__ bB,
                                              const float* __restrict__ bD, const float* __restrict__ bE,
                                              int layer, int fuse,
                                              const float* __restrict__ h1, const float* __restrict__ h2,
                                              const float* __restrict__ z,
                                              const float* __restrict__ Wh_emb,
                                              const float* __restrict__ bh_emb) {
    extern __shared__ unsigned sm[];
    unsigned* Ahi = sm + A_HI_OFF;
    unsigned* Alo = sm + A_LO_OFF;
    unsigned* Whi = sm + W_HI_OFF;
    unsigned* Wlo = sm + W_LO_OFF;
    int tid = threadIdx.x;
    int m0 = blockIdx.x * 128;
    int rows_valid = NN - m0;
    if (rows_valid > 128) rows_valid = 128;

    if (fuse == 2) {
        // layer 0: compute input embedding in-flight; also reset sort scratch
        float* Whf = (float*)(sm + W_HI_OFF);  // 26*96 floats fits in W region
        for (int i = tid; i < 26 * 96; i += 256) Whf[i] = Wh_emb[i];
        int gid = blockIdx.x * 256 + tid;
        if (gid < NN) { g_off[gid] = 0; g_cursor[gid] = 0; }
        __syncthreads();
        for (int i = tid; i < 128 * 24; i += 256) {
            int r = i / 24, c4 = i % 24;
            int row = m0 + r;
            float4 v = make_float4(0.f, 0.f, 0.f, 0.f);
            if (row < rows_valid + m0) {
                float x[26];
                const float* p1 = h1 + row * 6;
#pragma unroll
                for (int k = 0; k < 6; k++) x[k] = p1[k];
                const float* p2 = h2 + row * 4;
#pragma unroll
                for (int k = 0; k < 4; k++) x[6 + k] = p2[k];
                const float* p3 = z + row * 16;
#pragma unroll
                for (int k = 0; k < 16; k++) x[10 + k] = p3[k];
                float a[4];
#pragma unroll
                for (int c = 0; c < 4; c++) a[c] = bh_emb[c4 * 4 + c];
#pragma unroll
                for (int k = 0; k < 26; k++) {
#pragma unroll
                    for (int c = 0; c < 4; c++)
                        a[c] = fmaf(x[k], Whf[k * 96 + c4 * 4 + c], a[c]);
                }
                v = make_float4(a[0], a[1], a[2], a[3]);
                ((float4*)g_h)[(long long)row * 24 + c4] = v;
            }
            float rx = v.x - __bfloat162float(__float2bfloat16(v.x));
            float ry = v.y - __bfloat162float(__float2bfloat16(v.y));
            float rz = v.z - __bfloat162float(__float2bfloat16(v.z));
            float rw = v.w - __bfloat162float(__float2bfloat16(v.w));
            Ahi[r * 52 + c4 * 2] = pack_bf16(v.x, v.y);
            Ahi[r * 52 + c4 * 2 + 1] = pack_bf16(v.z, v.w);
            Alo[r * 52 + c4 * 2] = pack_bf16(rx, ry);
            Alo[r * 52 + c4 * 2 + 1] = pack_bf16(rz, rw);
        }
    } else {
        for (int i = tid; i < 128 * 24; i += 256) {
            int r = i / 24, c4 = i % 24;
            float4 v = make_float4(0.f, 0.f, 0.f, 0.f);
            if (r < rows_valid) {
                long long gi = (long long)(m0 + r) * 24 + c4;
                v = ((const float4*)g_h)[gi];
                float4 en = ((const float4*)g_hnew)[gi];
                int c = c4 * 4;
                v.x += fmaxf(0.f, en.x * g_scale_h[c] + g_shift_h[c]);
                v.y += fmaxf(0.f, en.y * g_scale_h[c + 1] + g_shift_h[c + 1]);
                v.z += fmaxf(0.f, en.z * g_scale_h[c + 2] + g_shift_h[c + 2]);
                v.w += fmaxf(0.f, en.w * g_scale_h[c + 3] + g_shift_h[c + 3]);
                ((float4*)g_h)[gi] = v;
            }
            float rx = v.x - __bfloat162float(__float2bfloat16(v.x));
            float ry = v.y - __bfloat162float(__float2bfloat16(v.y));
            float rz = v.z - __bfloat162float(__float2bfloat16(v.z));
            float rw = v.w - __bfloat162float(__float2bfloat16(v.w));
            Ahi[r * 52 + c4 * 2] = pack_bf16(v.x, v.y);
            Ahi[r * 52 + c4 * 2 + 1] = pack_bf16(v.z, v.w);
            Alo[r * 52 + c4 * 2] = pack_bf16(rx, ry);
            Alo[r * 52 + c4 * 2 + 1] = pack_bf16(rz, rw);
        }
    }

    int w = tid >> 5, lane = tid & 31;
    int wm = w & 3, wn = w >> 2;
    const int types[4] = {0, 1, 3, 4};
    const float* biases[4] = {bA, bB, bD, bE};
    __half* outsH[4] = {0, g_Bh, g_Dh, g_Eh};

    for (int t = 0; t < 4; t++) {
        __syncthreads();
        const unsigned* gwh = (const unsigned*)(g_Wt_hi + (types[t] * 4 + layer) * DD * DD);
        const unsigned* gwl = (const unsigned*)(g_Wt_lo + (types[t] * 4 + layer) * DD * DD);
        for (int i = tid; i < 96 * 48; i += 256) {
            int n = i / 48, kp = i % 48;
            Whi[n * 52 + kp] = gwh[i];
            Wlo[n * 52 + kp] = gwl[i];
        }
        __syncthreads();

        float acc[2][6][4];
#pragma unroll
        for (int m = 0; m < 2; m++)
#pragma unroll
            for (int n = 0; n < 6; n++)
#pragma unroll
                for (int j = 0; j < 4; j++) acc[m][n][j] = 0.f;

#pragma unroll
        for (int kt = 0; kt < 6; kt++) {
            int kp = kt * 8 + (lane & 3);
            unsigned ah[2][4], al[2][4];
#pragma unroll
            for (int m = 0; m < 2; m++) {
                int row = wm * 32 + m * 16 + (lane >> 2);
                ah[m][0] = Ahi[row * 52 + kp];
                ah[m][1] = Ahi[(row + 8) * 52 + kp];
                ah[m][2] = Ahi[row * 52 + kp + 4];
                ah[m][3] = Ahi[(row + 8) * 52 + kp + 4];
                al[m][0] = Alo[row * 52 + kp];
                al[m][1] = Alo[(row + 8) * 52 + kp];
                al[m][2] = Alo[row * 52 + kp + 4];
                al[m][3] = Alo[(row + 8) * 52 + kp + 4];
            }
#pragma unroll
            for (int n = 0; n < 6; n++) {
                int col = wn * 48 + n * 8 + (lane >> 2);
                unsigned bh0 = Whi[col * 52 + kp], bh1 = Whi[col * 52 + kp + 4];
                unsigned bl0 = Wlo[col * 52 + kp], bl1 = Wlo[col * 52 + kp + 4];
#pragma unroll
                for (int m = 0; m < 2; m++) {
                    mma_bf16(acc[m][n], ah[m], bh0, bh1);
                    mma_bf16(acc[m][n], ah[m], bl0, bl1);
                    mma_bf16(acc[m][n], al[m], bh0, bh1);
                }
            }
        }

        const float* bias = biases[t];
#pragma unroll
        for (int m = 0; m < 2; m++) {
#pragma unroll
            for (int n = 0; n < 6; n++) {
                int row = m0 + wm * 32 + m * 16 + (lane >> 2);
                int col = wn * 48 + n * 8 + ((lane & 3) << 1);
                float b0 = bias[col], b1 = bias[col + 1];
                float v00 = acc[m][n][0] + b0, v01 = acc[m][n][1] + b1;
                float v10 = acc[m][n][2] + b0, v11 = acc[m][n][3] + b1;
                if (t == 0) {
                    if (row < NN)
                        *(float2*)&g_A[(long long)row * 96 + col] = make_float2(v00, v01);
                    if (row + 8 < NN)
                        *(float2*)&g_A[(long long)(row + 8) * 96 + col] = make_float2(v10, v11);
                } else {
                    __half* o = outsH[t];
                    if (row < NN)
                        *(__half2*)&o[(long long)row * 96 + col] = __floats2half2_rn(v00, v01);
                    if (row + 8 < NN)
                        *(__half2*)&o[(long long)(row + 8) * 96 + col] = __floats2half2_rn(v10, v11);
                }
            }
        }
    }
}

// smem layout edge (u32): Whi[96*52] Wlo[96*52] Wemb[384] | R: Ah[128*52] / Sst(h)[12800h] Sbv(h)[12800h]
#define EW_HI 0
#define EW_LO (96 * 52)
#define EW_EMB (2 * 96 * 52)
#define ER_OFF (2 * 96 * 52 + 384)
#define ESBV_OFF (ER_OFF + 6400)
#define EDGE_U32 (ER_OFF + 12800)   // 23168 u32 = 92672 B

// ---------------- persistent fused edge layer ----------------
__global__ __launch_bounds__(256) void k_edge(const __half* __restrict__ Whi_g,
                                              const __half* __restrict__ Wlo_g,
                                              const float* __restrict__ bC,
                                              const float* __restrict__ efeat,
                                              const float* __restrict__ We,
                                              const float* __restrict__ be,
                                              int fuse, int last) {
    extern __shared__ unsigned sm[];
    unsigned* Whi = sm + EW_HI;
    unsigned* Wlo = sm + EW_LO;
    float* Wemb = (float*)(sm + EW_EMB);
    unsigned* Ah = sm + ER_OFF;
    __half* Sst = (__half*)(sm + ER_OFF);
    __half* Sbv = (__half*)(sm + ESBV_OFF);
    __shared__ int s_src[128], s_dst[128];
    int tid = threadIdx.x;

    {
        const unsigned* gwh = (const unsigned*)Whi_g;
        const unsigned* gwl = (const unsigned*)Wlo_g;
        for (int i = tid; i < 96 * 48; i += 256) {
            int n = i / 48, kp = i % 48;
            Whi[n * 52 + kp] = gwh[i];
            Wlo[n * 52 + kp] = gwl[i];
        }
        if (fuse == 0)
            for (int i = tid; i < 384; i += 256) Wemb[i] = We[i];
    }

    int w = tid >> 5, lane = tid & 31;
    int wm = w & 3, wn = w >> 2;
    int colP2 = tid % 96, gP2 = tid / 96;
    float bs_tot = 0.f, bq_tot = 0.f;

    for (int tile = blockIdx.x; tile < NTILE; tile += gridDim.x) {
        int e0 = tile * 128;
        __syncthreads();  // prior tile fully consumed; W/Wemb visible on first iter
        if (tid < 128) {
            s_src[tid] = g_src_s[e0 + tid];
            s_dst[tid] = g_dst_s[e0 + tid];
        }

        if (fuse == 0) {
            // layer 0: compute e = efeat[perm] @ We + be in-flight
            for (int i = tid; i < 128 * 12; i += 256) {
                int r = i / 12, c8 = i % 12;
                int er = e0 + r;
                const float4 ef = ((const float4*)efeat)[g_perm[er]];
                uint4 v;
                __half2* vh = (__half2*)&v;
#pragma unroll
                for (int j = 0; j < 4; j++) {
                    int c = c8 * 8 + 2 * j;
                    float o0 = be[c] + ef.x * Wemb[c] + ef.y * Wemb[96 + c] +
                               ef.z * Wemb[192 + c] + ef.w * Wemb[288 + c];
                    float o1 = be[c + 1] + ef.x * Wemb[c + 1] + ef.y * Wemb[96 + c + 1] +
                               ef.z * Wemb[192 + c + 1] + ef.w * Wemb[288 + c + 1];
                    vh[j] = __floats2half2_rn(o0, o1);
                }
                ((uint4*)g_e)[(long long)er * 12 + c8] = v;
                unsigned* vu = (unsigned*)&v;
#pragma unroll
                for (int j = 0; j < 4; j++) Ah[r * 52 + c8 * 4 + j] = vu[j];
            }
        } else {
            for (int i = tid; i < 128 * 12; i += 256) {
                int r = i / 12, c8 = i % 12;
                long long gi = (long long)(e0 + r) * 12 + c8;
                uint4 v = ((const uint4*)g_e)[gi];
                uint4 en = ((const uint4*)g_enew)[gi];
                __half2* vh = (__half2*)&v;
                __half2* eh = (__half2*)&en;
                int c = c8 * 8;
#pragma unroll
                for (int j = 0; j < 4; j++) {
                    float2 f = __half22float2(vh[j]);
                    float2 ev = __half22float2(eh[j]);
                    f.x += fmaxf(0.f, ev.x * g_scale_e[c + 2 * j] + g_shift_e[c + 2 * j]);
                    f.y += fmaxf(0.f, ev.y * g_scale_e[c + 2 * j + 1] + g_shift_e[c + 2 * j + 1]);
                    vh[j] = __floats2half2_rn(f.x, f.y);
                }
                if (!last) ((uint4*)g_e)[gi] = v;
                unsigned* vu = (unsigned*)&v;
#pragma unroll
                for (int j = 0; j < 4; j++) Ah[r * 52 + c8 * 4 + j] = vu[j];
            }
        }
        __syncthreads();

        // fp16 GEMM: Ce = e @ (Whi + Wlo)
        float acc[2][6][4];
#pragma unroll
        for (int m = 0; m < 2; m++)
#pragma unroll
            for (int n = 0; n < 6; n++)
#pragma unroll
                for (int j = 0; j < 4; j++) acc[m][n][j] = 0.f;

#pragma unroll
        for (int kt = 0; kt < 6; kt++) {
            int kp = kt * 8 + (lane & 3);
            unsigned ah[2][4];
#pragma unroll
            for (int m = 0; m < 2; m++) {
                int row = wm * 32 + m * 16 + (lane >> 2);
                ah[m][0] = Ah[row * 52 + kp];
                ah[m][1] = Ah[(row + 8) * 52 + kp];
                ah[m][2] = Ah[row * 52 + kp + 4];
                ah[m][3] = Ah[(row + 8) * 52 + kp + 4];
            }
#pragma unroll
            for (int n = 0; n < 6; n++) {
                int col = wn * 48 + n * 8 + (lane >> 2);
                unsigned bh0 = Whi[col * 52 + kp], bh1 = Whi[col * 52 + kp + 4];
                unsigned bl0 = Wlo[col * 52 + kp], bl1 = Wlo[col * 52 + kp + 4];
#pragma unroll
                for (int m = 0; m < 2; m++) {
                    mma_f16(acc[m][n], ah[m], bh0, bh1);
                    mma_f16(acc[m][n], ah[m], bl0, bl1);
                }
            }
        }
        __syncthreads();  // Ah dead; stage over it

#pragma unroll
        for (int m = 0; m < 2; m++) {
#pragma unroll
            for (int n = 0; n < 6; n++) {
                int lr = wm * 32 + m * 16 + (lane >> 2);
                int col = wn * 48 + n * 8 + ((lane & 3) << 1);
                *(__half2*)&Sst[lr * 100 + col] = __floats2half2_rn(acc[m][n][0], acc[m][n][1]);
                *(__half2*)&Sst[(lr + 8) * 100 + col] = __floats2half2_rn(acc[m][n][2], acc[m][n][3]);
            }
        }
        __syncthreads();

        // pass 1: vv = Ce + bC + Dh[src] + Eh[dst]; restage vv + Bv; write e_new
        {
            int r = tid >> 1, half = tid & 1;
            int s = s_src[r], d = s_dst[r];
            const uint4* Dr = (const uint4*)(g_Dh + (long long)s * 96) + half * 6;
            const uint4* Er = (const uint4*)(g_Eh + (long long)d * 96) + half * 6;
            const uint4* Br = (const uint4*)(g_Bh + (long long)s * 96) + half * 6;
            __half2* sp = (__half2*)(Sst + r * 100 + half * 48);
            unsigned* pb = (unsigned*)Sbv + r * 50 + half * 24;
            uint4* ep = (uint4*)g_enew + (long long)(e0 + r) * 12 + half * 6;
            const float* bc = bC + half * 48;
#pragma unroll
            for (int i = 0; i < 6; i++) {
                uint4 du = Dr[i], eu = Er[i], bu = Br[i];
                __half2* dh = (__half2*)&du;
                __half2* ehh = (__half2*)&eu;
                uint4 outv;
                __half2* oh = (__half2*)&outv;
#pragma unroll
                for (int j = 0; j < 4; j++) {
                    float2 ce = __half22float2(sp[i * 4 + j]);
                    float2 dv = __half22float2(dh[j]);
                    float2 ev = __half22float2(ehh[j]);
                    float v0 = ce.x + bc[i * 8 + 2 * j] + dv.x + ev.x;
                    float v1 = ce.y + bc[i * 8 + 2 * j + 1] + dv.y + ev.y;
                    oh[j] = __floats2half2_rn(v0, v1);
                }
                if (!last) ep[i] = outv;
#pragma unroll
                for (int j = 0; j < 4; j++) sp[i * 4 + j] = oh[j];
                unsigned* bup = (unsigned*)&bu;
#pragma unroll
                for (int j = 0; j < 4; j++) pb[i * 4 + j] = bup[j];
            }
        }
        __syncthreads();

        // pass 2: per-column segment scan (pure smem)
        if (tid < 192) {
            int rbeg = gP2 * 64, rend = rbeg + 64;
            float num_acc = 0.f, den_acc = 0.f;
            int d = s_dst[rbeg];
            for (int r = rbeg; r < rend; r++) {
                float vv = __half2float(Sst[r * 100 + colP2]);
                float bv = __half2float(Sbv[r * 100 + colP2]);
                float sg = sigmoid_fast(vv);
                num_acc = fmaf(sg, bv, num_acc);
                den_acc += sg;
                bs_tot += vv;
                bq_tot = fmaf(vv, vv, bq_tot);
                int dn = (r + 1 < rend) ? s_dst[r + 1] : -1;
                if (dn != d) {
                    atomicAdd((float2*)&g_agg[((long long)d * 96 + colP2) * 2],
                              make_float2(num_acc, den_acc));
                    num_acc = 0.f;
                    den_acc = 0.f;
                    d = dn;
                }
            }
        }
    }
    if (!last && tid < 192) {
        atomicAdd(&g_sums[colP2], bs_tot);
        atomicAdd(&g_sums[DD + colP2], bq_tot);
    }
}

// ---------------- h_new = Ah + num/(den+eps), BN-h moments, re-zero agg ----------------
__global__ __launch_bounds__(384) void k_hnew() {
    __shared__ float ssum[96], ssq[96];
    int tid = threadIdx.x;
    int col = tid % 96, yr = tid / 96;
    if (tid < 96) { ssum[tid] = 0.f; ssq[tid] = 0.f; }
    __syncthreads();
    float sm = 0.f, sq = 0.f;
    for (int row = blockIdx.x * 4 + yr; row < NN; row += gridDim.x * 4) {
        int i = row * 96 + col;
        float2 nd = ((float2*)g_agg)[i];
        float v = g_A[i] + nd.x / (nd.y + AGG_EPS);
        g_hnew[i] = v;
        ((float2*)g_agg)[i] = make_float2(0.f, 0.f);
        sm += v;
        sq = fmaf(v, v, sq);
    }
    atomicAdd(&ssum[col], sm);
    atomicAdd(&ssq[col], sq);
    __syncthreads();
    if (tid < 96) {
        atomicAdd(&g_sums[2 * DD + tid], ssum[tid]);
        atomicAdd(&g_sums[3 * DD + tid], ssq[tid]);
    }
}

// ---------------- finalize BN stats ----------------
__global__ void k_finalize(int which, const float* __restrict__ g,
                           const float* __restrict__ b, float invM) {
    int c = threadIdx.x;
    if (c >= 96) return;
    int base = which * 2 * DD;
    float mu = g_sums[base + c] * invM;
    float var = g_sums[base + DD + c] * invM - mu * mu;
    float rstd = rsqrtf(var + BN_EPS);
    float sc = g[c] * rstd;
    float sh = b[c] - mu * sc;
    if (which == 0) { g_scale_e[c] = sc; g_shift_e[c] = sh; }
    else            { g_scale_h[c] = sc; g_shift_h[c] = sh; }
    g_sums[base + c] = 0.f;
    g_sums[base + DD + c] = 0.f;
}

// ---------------- MLP head ----------------
__global__ __launch_bounds__(128) void k_head(const float* __restrict__ W1,
                                              const float* __restrict__ b1,
                                              const float* __restrict__ W2,
                                              const float* __restrict__ b2,
                                              const float* __restrict__ maxa,
                                              float* __restrict__ out) {
    __shared__ float hs[8][96];
    __shared__ float hid[8][HIDN];
    int r0 = blockIdx.x * 8;
    int tid = threadIdx.x;
    for (int i = tid; i < 8 * 96; i += 128) {
        int r = i / 96, c = i % 96;
        int row = r0 + r;
        float v = 0.f;
        if (row < NN) {
            long long gi = (long long)row * 96 + c;
            v = g_h[gi] + fmaxf(0.f, g_hnew[gi] * g_scale_h[c] + g_shift_h[c]);
        }
        hs[r][c] = v;
    }
    __syncthreads();
    float acc[8];
#pragma unroll
    for (int r = 0; r < 8; r++) acc[r] = b1[tid];
#pragma unroll 4
    for (int k = 0; k < 96; k++) {
        float w = W1[k * HIDN + tid];
#pragma unroll
        for (int r = 0; r < 8; r++) acc[r] += hs[r][k] * w;
    }
#pragma unroll
    for (int r = 0; r < 8; r++) hid[r][tid] = fmaxf(acc[r], 0.f);
    __syncthreads();
    if (tid < 64) {
        int r = tid >> 3, c = tid & 7;
        int row = r0 + r;
        if (row < NN) {
            float a = b2[c];
#pragma unroll 8
            for (int k = 0; k < HIDN; k++) a += hid[r][k] * W2[k * OUTD + c];
            out[(long long)row * OUTD + c] = maxa[row] * tanhf(a);
        }
    }
}

// ---------------- launch ----------------
extern "C" void kernel_launch(void* const* d_in, const int* in_sizes, int n_in,
                              void* d_out, int out_size) {
    const float* h1 = (const float*)d_in[0];
    const float* h2 = (const float*)d_in[1];
    const float* z = (const float*)d_in[2];
    const float* efeat = (const float*)d_in[3];
    const float* max_action = (const float*)d_in[4];
    const float* Wh_emb = (const float*)d_in[5];
    const float* bh_emb = (const float*)d_in[6];
    const float* We_emb = (const float*)d_in[7];
    const float* be_emb = (const float*)d_in[8];
    const float* WA = (const float*)d_in[9];
    const float* bA = (const float*)d_in[10];
    const float* WB = (const float*)d_in[11];
    const float* bB = (const float*)d_in[12];
    const float* WC = (const float*)d_in[13];
    const float* bC = (const float*)d_in[14];
    const float* WD = (const float*)d_in[15];
    const float* bD = (const float*)d_in[16];
    const float* WE = (const float*)d_in[17];
    const float* bE = (const float*)d_in[18];
    const float* bn_h_g = (const float*)d_in[19];
    const float* bn_h_b = (const float*)d_in[20];
    const float* bn_e_g = (const float*)d_in[21];
    const float* bn_e_b = (const float*)d_in[22];
    const float* W1 = (const float*)d_in[23];
    const float* b1 = (const float*)d_in[24];
    const float* W2 = (const float*)d_in[25];
    const float* b2 = (const float*)d_in[26];
    const int* src = (const int*)d_in[27];
    const int* dst = (const int*)d_in[28];
    float* out = (float*)d_out;

    __half *p_wchi, *p_wclo;
    cudaGetSymbolAddress((void**)&p_wchi, g_Wc_hi);
    cudaGetSymbolAddress((void**)&p_wclo, g_Wc_lo);

    const int smem_node = NODE_U32 * 4;  // 93184
    const int smem_edge = EDGE_U32 * 4;  // 92672
    cudaFuncSetAttribute(k_node, cudaFuncAttributeMaxDynamicSharedMemorySize, smem_node);
    cudaFuncSetAttribute(k_edge, cudaFuncAttributeMaxDynamicSharedMemorySize, smem_edge);

    // sort (g_off/g_cursor are zero by invariant: zeroed in k_node layer0 after use)
    k_hist<<<(EE + 255) / 256, 256>>>(dst);
    k_scan<<<1, 1024>>>();
    k_scatter<<<(EE + 255) / 256, 256>>>(src, dst);

    WPtrs wp{WA, WB, WC, WD, WE};
    k_prep<<<(20 * DD * DD + 255) / 256, 256>>>(wp);

    const int nblk = (NN + 127) / 128;  // 391
    const int eblk = 296;               // persistent: 2 blocks/SM

    for (int l = 0; l < 4; l++) {
        k_node<<<nblk, 256, smem_node>>>(bA + l * DD, bB + l * DD, bD + l * DD, bE + l * DD,
                                         l, l == 0 ? 2 : 1, h1, h2, z, Wh_emb, bh_emb);
        k_edge<<<eblk, 256, smem_edge>>>(p_wchi + l * DD * DD, p_wclo + l * DD * DD,
                                         bC + l * DD, efeat, We_emb, be_emb,
                                         l == 0 ? 0 : 1, l == 3 ? 1 : 0);
        if (l < 3)
            k_finalize<<<1, 96>>>(0, bn_e_g + l * DD, bn_e_b + l * DD, 1.f / EE);
        k_hnew<<<256, 384>>>();
        k_finalize<<<1, 96>>>(1, bn_h_g + l * DD, bn_h_b + l * DD, 1.f / NN);
    }

    k_head<<<NN / 8, 128>>>(W1, b1, W2, b2, max_action, out);
}

// round 8
// speedup vs baseline: 2.3233x; 1.0712x over previous
#include <cuda_runtime.h>
#include <cuda_bf16.h>
#include <cuda_fp16.h>
#include <math.h>

#define NN 50000
#define EE 800000
#define DD 96
#define HIDN 128
#define OUTD 8
#define BN_EPS 1e-5f
#define AGG_EPS 1e-6f
#define NTILE 6250

// ---------------- device scratch ----------------
__device__ __align__(16) float g_h[NN * DD];
__device__ __align__(16) float g_A[NN * DD];
__device__ __align__(16) __half g_Bh[NN * DD];
__device__ __align__(16) __half g_Dh[NN * DD];
__device__ __align__(16) __half g_Eh[NN * DD];
__device__ __align__(16) float g_agg[NN * DD * 2];  // interleaved num/den
__device__ __align__(16) float g_hnew[NN * DD];
__device__ __align__(16) __half g_e[EE * DD];       // sorted order
__device__ __align__(16) __half g_enew[EE * DD];    // sorted order
__device__ __align__(16) float g_sums[4 * DD];
__device__ __align__(16) float g_scale_e[DD], g_shift_e[DD];
__device__ __align__(16) float g_scale_h[DD], g_shift_h[DD];
// transposed fp16 hi/lo weights: [type(A,B,C,D,E)*4+layer][n*96+k]
__device__ __align__(16) __half g_Wf_hi[20 * DD * DD];
__device__ __align__(16) __half g_Wf_lo[20 * DD * DD];
// dst-sorted edge structure
__device__ int g_perm[EE];
__device__ int g_src_s[EE];
__device__ int g_dst_s[EE];
__device__ int g_off[NN];
__device__ int g_cursor[NN];

// ---------------- helpers ----------------
__device__ __forceinline__ unsigned pack_h2(float x, float y) {
    __half2 t = __floats2half2_rn(x, y);
    return *reinterpret_cast<unsigned*>(&t);
}

__device__ __forceinline__ float sigmoid_fast(float x) {
    float t;
    asm("tanh.approx.f32 %0, %1;" : "=f"(t) : "f"(0.5f * x));
    return fmaf(0.5f, t, 0.5f);
}

__device__ __forceinline__ void mma_f16(float* c, const unsigned* a, unsigned b0, unsigned b1) {
    asm volatile(
        "mma.sync.aligned.m16n8k16.row.col.f32.f16.f16.f32 "
        "{%0,%1,%2,%3},{%4,%5,%6,%7},{%8,%9},{%0,%1,%2,%3};"
        : "+f"(c[0]), "+f"(c[1]), "+f"(c[2]), "+f"(c[3])
        : "r"(a[0]), "r"(a[1]), "r"(a[2]), "r"(a[3]), "r"(b0), "r"(b1));
}

// ---------------- counting sort by dst ----------------
__global__ void k_hist(const int* __restrict__ dst) {
    int e = blockIdx.x * blockDim.x + threadIdx.x;
    if (e < EE) atomicAdd(&g_off[dst[e]], 1);
}

__global__ void k_scan() {
    __shared__ int ssum[1024];
    const int STRIP = (NN + 1023) / 1024;
    int t = threadIdx.x;
    int beg = t * STRIP, end = beg + STRIP;
    if (end > NN) end = NN;
    int s = 0;
    for (int i = beg; i < end; i++) s += g_off[i];
    ssum[t] = s;
    __syncthreads();
    for (int ofs = 1; ofs < 1024; ofs <<= 1) {
        int v = (t >= ofs) ? ssum[t - ofs] : 0;
        __syncthreads();
        ssum[t] += v;
        __syncthreads();
    }
    int carry = (t > 0) ? ssum[t - 1] : 0;
    for (int i = beg; i < end; i++) {
        int v = g_off[i];
        g_off[i] = carry;
        carry += v;
    }
}

__global__ void k_scatter(const int* __restrict__ src, const int* __restrict__ dst) {
    int e = blockIdx.x * blockDim.x + threadIdx.x;
    if (e >= EE) return;
    int d = dst[e];
    int p = g_off[d] + atomicAdd(&g_cursor[d], 1);
    g_perm[p] = e;
    g_src_s[p] = src[e];
    g_dst_s[p] = d;
}

// ---------------- weight prep: 20 matrices, transpose + fp16 hi/lo ----------------
struct WPtrs { const float *a, *b, *c, *d, *e; };

__global__ void k_prep(WPtrs p) {
    int idx = blockIdx.x * blockDim.x + threadIdx.x;
    if (idx >= 20 * DD * DD) return;
    int m = idx / (DD * DD), r = idx % (DD * DD);
    int k = r / DD, n = r % DD;
    int type = m >> 2, layer = m & 3;
    const float* src = type == 0 ? p.a : type == 1 ? p.b : type == 2 ? p.c
                       : type == 3 ? p.d : p.e;
    float w = src[layer * DD * DD + k * DD + n];
    __half hi = __float2half(w);
    g_Wf_hi[m * DD * DD + n * DD + k] = hi;
    g_Wf_lo[m * DD * DD + n * DD + k] = __float2half(w - __half2float(hi));
}

// smem layout node (u32): Ah[128*50] Whi[96*52] Wlo[96*52]
#define N_A 0
#define N_WHI (128 * 50)
#define N_WLO (128 * 50 + 96 * 52)
#define NODE_U32 (128 * 50 + 2 * 96 * 52)   // 16384 u32 = 65536 B

// ---------------- fused node GEMM: A(fp32), B/D/E(fp16); layer0 fuses input embed ----------------
__global__ __launch_bounds__(256, 3) void k_node(const float* __restrict__ bA, const float* __restrict__ bB,
                                                 const float* __restrict__ bD, const float* __restrict__ bE,
                                                 int layer, int fuse,
                                                 const float* __restrict__ h1, const float* __restrict__ h2,
                                                 const float* __restrict__ z,
                                                 const float* __restrict__ Wh_emb,
                                                 const float* __restrict__ bh_emb) {
    extern __shared__ unsigned sm[];
    unsigned* Ah = sm + N_A;
    unsigned* Whi = sm + N_WHI;
    unsigned* Wlo = sm + N_WLO;
    int tid = threadIdx.x;
    int m0 = blockIdx.x * 128;
    int rows_valid = NN - m0;
    if (rows_valid > 128) rows_valid = 128;

    if (fuse == 2) {
        // layer 0: compute input embedding in-flight; also reset sort scratch
        float* Whf = (float*)(sm + N_WHI);  // 26*96 floats fits in W region
        for (int i = tid; i < 26 * 96; i += 256) Whf[i] = Wh_emb[i];
        int gid = blockIdx.x * 256 + tid;
        if (gid < NN) { g_off[gid] = 0; g_cursor[gid] = 0; }
        __syncthreads();
        for (int i = tid; i < 128 * 24; i += 256) {
            int r = i / 24, c4 = i % 24;
            int row = m0 + r;
            float4 v = make_float4(0.f, 0.f, 0.f, 0.f);
            if (r < rows_valid) {
                float x[26];
                const float* p1 = h1 + row * 6;
#pragma unroll
                for (int k = 0; k < 6; k++) x[k] = p1[k];
                const float* p2 = h2 + row * 4;
#pragma unroll
                for (int k = 0; k < 4; k++) x[6 + k] = p2[k];
                const float* p3 = z + row * 16;
#pragma unroll
                for (int k = 0; k < 16; k++) x[10 + k] = p3[k];
                float a[4];
#pragma unroll
                for (int c = 0; c < 4; c++) a[c] = bh_emb[c4 * 4 + c];
#pragma unroll
                for (int k = 0; k < 26; k++) {
#pragma unroll
                    for (int c = 0; c < 4; c++)
                        a[c] = fmaf(x[k], Whf[k * 96 + c4 * 4 + c], a[c]);
                }
                v = make_float4(a[0], a[1], a[2], a[3]);
                ((float4*)g_h)[(long long)row * 24 + c4] = v;
            }
            Ah[r * 50 + c4 * 2] = pack_h2(v.x, v.y);
            Ah[r * 50 + c4 * 2 + 1] = pack_h2(v.z, v.w);
        }
    } else {
        for (int i = tid; i < 128 * 24; i += 256) {
            int r = i / 24, c4 = i % 24;
            float4 v = make_float4(0.f, 0.f, 0.f, 0.f);
            if (r < rows_valid) {
                long long gi = (long long)(m0 + r) * 24 + c4;
                v = ((const float4*)g_h)[gi];
                float4 en = ((const float4*)g_hnew)[gi];
                int c = c4 * 4;
                v.x += fmaxf(0.f, en.x * g_scale_h[c] + g_shift_h[c]);
                v.y += fmaxf(0.f, en.y * g_scale_h[c + 1] + g_shift_h[c + 1]);
                v.z += fmaxf(0.f, en.z * g_scale_h[c + 2] + g_shift_h[c + 2]);
                v.w += fmaxf(0.f, en.w * g_scale_h[c + 3] + g_shift_h[c + 3]);
                ((float4*)g_h)[gi] = v;
            }
            Ah[r * 50 + c4 * 2] = pack_h2(v.x, v.y);
            Ah[r * 50 + c4 * 2 + 1] = pack_h2(v.z, v.w);
        }
    }

    int w = tid >> 5, lane = tid & 31;
    int wm = w & 3, wn = w >> 2;
    const int types[4] = {0, 1, 3, 4};
    const float* biases[4] = {bA, bB, bD, bE};
    __half* outsH[4] = {0, g_Bh, g_Dh, g_Eh};

    for (int t = 0; t < 4; t++) {
        __syncthreads();
        const unsigned* gwh = (const unsigned*)(g_Wf_hi + (types[t] * 4 + layer) * DD * DD);
        const unsigned* gwl = (const unsigned*)(g_Wf_lo + (types[t] * 4 + layer) * DD * DD);
        for (int i = tid; i < 96 * 48; i += 256) {
            int n = i / 48, kp = i % 48;
            Whi[n * 52 + kp] = gwh[i];
            Wlo[n * 52 + kp] = gwl[i];
        }
        __syncthreads();

        float acc[2][6][4];
#pragma unroll
        for (int m = 0; m < 2; m++)
#pragma unroll
            for (int n = 0; n < 6; n++)
#pragma unroll
                for (int j = 0; j < 4; j++) acc[m][n][j] = 0.f;

#pragma unroll
        for (int kt = 0; kt < 6; kt++) {
            int kp = kt * 8 + (lane & 3);
            unsigned ah[2][4];
#pragma unroll
            for (int m = 0; m < 2; m++) {
                int row = wm * 32 + m * 16 + (lane >> 2);
                ah[m][0] = Ah[row * 50 + kp];
                ah[m][1] = Ah[(row + 8) * 50 + kp];
                ah[m][2] = Ah[row * 50 + kp + 4];
                ah[m][3] = Ah[(row + 8) * 50 + kp + 4];
            }
#pragma unroll
            for (int n = 0; n < 6; n++) {
                int col = wn * 48 + n * 8 + (lane >> 2);
                unsigned bh0 = Whi[col * 52 + kp], bh1 = Whi[col * 52 + kp + 4];
                unsigned bl0 = Wlo[col * 52 + kp], bl1 = Wlo[col * 52 + kp + 4];
#pragma unroll
                for (int m = 0; m < 2; m++) {
                    mma_f16(acc[m][n], ah[m], bh0, bh1);
                    mma_f16(acc[m][n], ah[m], bl0, bl1);
                }
            }
        }

        const float* bias = biases[t];
#pragma unroll
        for (int m = 0; m < 2; m++) {
#pragma unroll
            for (int n = 0; n < 6; n++) {
                int row = m0 + wm * 32 + m * 16 + (lane >> 2);
                int col = wn * 48 + n * 8 + ((lane & 3) << 1);
                float b0 = bias[col], b1 = bias[col + 1];
                float v00 = acc[m][n][0] + b0, v01 = acc[m][n][1] + b1;
                float v10 = acc[m][n][2] + b0, v11 = acc[m][n][3] + b1;
                if (t == 0) {
                    if (row < NN)
                        *(float2*)&g_A[(long long)row * 96 + col] = make_float2(v00, v01);
                    if (row + 8 < NN)
                        *(float2*)&g_A[(long long)(row + 8) * 96 + col] = make_float2(v10, v11);
                } else {
                    __half* o = outsH[t];
                    if (row < NN)
                        *(__half2*)&o[(long long)row * 96 + col] = __floats2half2_rn(v00, v01);
                    if (row + 8 < NN)
                        *(__half2*)&o[(long long)(row + 8) * 96 + col] = __floats2half2_rn(v10, v11);
                }
            }
        }
    }
}

// smem layout edge (u32): Whi[96*52] Wlo[96*52] Wemb[384] | R: Ah[128*50]=Sst region, Sbv after
#define EW_HI 0
#define EW_LO (96 * 52)
#define EW_EMB (2 * 96 * 52)
#define ER_OFF (2 * 96 * 52 + 384)
#define ESBV_OFF (ER_OFF + 6400)
#define EDGE_U32 (ER_OFF + 12800)   // 23168 u32 = 92672 B

// ---------------- persistent fused edge layer ----------------
__global__ __launch_bounds__(256, 2) void k_edge(const __half* __restrict__ Whi_g,
                                                 const __half* __restrict__ Wlo_g,
                                                 const float* __restrict__ bC,
                                                 const float* __restrict__ efeat,
                                                 const float* __restrict__ We,
                                                 const float* __restrict__ be,
                                                 int fuse, int last) {
    extern __shared__ unsigned sm[];
    unsigned* Whi = sm + EW_HI;
    unsigned* Wlo = sm + EW_LO;
    float* Wemb = (float*)(sm + EW_EMB);
    unsigned* Ah = sm + ER_OFF;              // 128x50 u32, == Sst region
    __half* Sst = (__half*)(sm + ER_OFF);    // 128x100 halves
    __half* Sbv = (__half*)(sm + ESBV_OFF);  // 128x100 halves
    __shared__ int s_src[128], s_dst[128];
    int tid = threadIdx.x;

    {
        const unsigned* gwh = (const unsigned*)Whi_g;
        const unsigned* gwl = (const unsigned*)Wlo_g;
        for (int i = tid; i < 96 * 48; i += 256) {
            int n = i / 48, kp = i % 48;
            Whi[n * 52 + kp] = gwh[i];
            Wlo[n * 52 + kp] = gwl[i];
        }
        if (fuse == 0)
            for (int i = tid; i < 384; i += 256) Wemb[i] = We[i];
    }

    int w = tid >> 5, lane = tid & 31;
    int wm = w & 3, wn = w >> 2;
    int colP2 = tid % 96, gP2 = tid / 96;
    float bs_tot = 0.f, bq_tot = 0.f;

    for (int tile = blockIdx.x; tile < NTILE; tile += gridDim.x) {
        int e0 = tile * 128;
        __syncthreads();  // prior tile consumed; W visible on first iter
        if (tid < 128) {
            s_src[tid] = g_src_s[e0 + tid];
            s_dst[tid] = g_dst_s[e0 + tid];
        }

        // B-row gather staged NOW so its latency hides behind the GEMM
        {
            int r = tid >> 1, half = tid & 1;
            int s = g_src_s[e0 + r];
            const uint4* Br = (const uint4*)(g_Bh + (long long)s * 96) + half * 6;
            unsigned* pb = (unsigned*)Sbv + r * 50 + half * 24;
#pragma unroll
            for (int i = 0; i < 6; i++) {
                uint4 bu = Br[i];
                pb[i * 4] = bu.x; pb[i * 4 + 1] = bu.y;
                pb[i * 4 + 2] = bu.z; pb[i * 4 + 3] = bu.w;
            }
        }

        if (fuse == 0) {
            // layer 0: compute e = efeat[perm] @ We + be in-flight
            for (int i = tid; i < 128 * 12; i += 256) {
                int r = i / 12, c8 = i % 12;
                int er = e0 + r;
                const float4 ef = ((const float4*)efeat)[g_perm[er]];
                uint4 v;
                __half2* vh = (__half2*)&v;
#pragma unroll
                for (int j = 0; j < 4; j++) {
                    int c = c8 * 8 + 2 * j;
                    float o0 = be[c] + ef.x * Wemb[c] + ef.y * Wemb[96 + c] +
                               ef.z * Wemb[192 + c] + ef.w * Wemb[288 + c];
                    float o1 = be[c + 1] + ef.x * Wemb[c + 1] + ef.y * Wemb[96 + c + 1] +
                               ef.z * Wemb[192 + c + 1] + ef.w * Wemb[288 + c + 1];
                    vh[j] = __floats2half2_rn(o0, o1);
                }
                ((uint4*)g_e)[(long long)er * 12 + c8] = v;
                unsigned* vu = (unsigned*)&v;
#pragma unroll
                for (int j = 0; j < 4; j++) Ah[r * 50 + c8 * 4 + j] = vu[j];
            }
        } else {
            for (int i = tid; i < 128 * 12; i += 256) {
                int r = i / 12, c8 = i % 12;
                long long gi = (long long)(e0 + r) * 12 + c8;
                uint4 v = ((const uint4*)g_e)[gi];
                uint4 en = ((const uint4*)g_enew)[gi];
                __half2* vh = (__half2*)&v;
                __half2* eh = (__half2*)&en;
                int c = c8 * 8;
#pragma unroll
                for (int j = 0; j < 4; j++) {
                    float2 f = __half22float2(vh[j]);
                    float2 ev = __half22float2(eh[j]);
                    f.x += fmaxf(0.f, ev.x * g_scale_e[c + 2 * j] + g_shift_e[c + 2 * j]);
                    f.y += fmaxf(0.f, ev.y * g_scale_e[c + 2 * j + 1] + g_shift_e[c + 2 * j + 1]);
                    vh[j] = __floats2half2_rn(f.x, f.y);
                }
                if (!last) ((uint4*)g_e)[gi] = v;
                unsigned* vu = (unsigned*)&v;
#pragma unroll
                for (int j = 0; j < 4; j++) Ah[r * 50 + c8 * 4 + j] = vu[j];
            }
        }
        __syncthreads();

        // fp16 GEMM: Ce = e @ (Whi + Wlo)
        float acc[2][6][4];
#pragma unroll
        for (int m = 0; m < 2; m++)
#pragma unroll
            for (int n = 0; n < 6; n++)
#pragma unroll
                for (int j = 0; j < 4; j++) acc[m][n][j] = 0.f;

#pragma unroll
        for (int kt = 0; kt < 6; kt++) {
            int kp = kt * 8 + (lane & 3);
            unsigned ah[2][4];
#pragma unroll
            for (int m = 0; m < 2; m++) {
                int row = wm * 32 + m * 16 + (lane >> 2);
                ah[m][0] = Ah[row * 50 + kp];
                ah[m][1] = Ah[(row + 8) * 50 + kp];
                ah[m][2] = Ah[row * 50 + kp + 4];
                ah[m][3] = Ah[(row + 8) * 50 + kp + 4];
            }
#pragma unroll
            for (int n = 0; n < 6; n++) {
                int col = wn * 48 + n * 8 + (lane >> 2);
                unsigned bh0 = Whi[col * 52 + kp], bh1 = Whi[col * 52 + kp + 4];
                unsigned bl0 = Wlo[col * 52 + kp], bl1 = Wlo[col * 52 + kp + 4];
#pragma unroll
                for (int m = 0; m < 2; m++) {
                    mma_f16(acc[m][n], ah[m], bh0, bh1);
                    mma_f16(acc[m][n], ah[m], bl0, bl1);
                }
            }
        }
        __syncthreads();  // Ah dead; stage Ce over it

#pragma unroll
        for (int m = 0; m < 2; m++) {
#pragma unroll
            for (int n = 0; n < 6; n++) {
                int lr = wm * 32 + m * 16 + (lane >> 2);
                int col = wn * 48 + n * 8 + ((lane & 3) << 1);
                *(__half2*)&Sst[lr * 100 + col] = __floats2half2_rn(acc[m][n][0], acc[m][n][1]);
                *(__half2*)&Sst[(lr + 8) * 100 + col] = __floats2half2_rn(acc[m][n][2], acc[m][n][3]);
            }
        }
        __syncthreads();

        // pass 1: vv = Ce + bC + Dh[src] + Eh[dst]; restage vv; write e_new
        {
            int r = tid >> 1, half = tid & 1;
            int s = s_src[r], d = s_dst[r];
            const uint4* Dr = (const uint4*)(g_Dh + (long long)s * 96) + half * 6;
            const uint4* Er = (const uint4*)(g_Eh + (long long)d * 96) + half * 6;
            uint4 du[6], eu[6];
#pragma unroll
            for (int i = 0; i < 6; i++) { du[i] = Dr[i]; eu[i] = Er[i]; }
            __half2* sp = (__half2*)(Sst + r * 100 + half * 48);
            uint4* ep = (uint4*)g_enew + (long long)(e0 + r) * 12 + half * 6;
            const float* bc = bC + half * 48;
#pragma unroll
            for (int i = 0; i < 6; i++) {
                __half2* dh = (__half2*)&du[i];
                __half2* ehh = (__half2*)&eu[i];
                uint4 outv;
                __half2* oh = (__half2*)&outv;
#pragma unroll
                for (int j = 0; j < 4; j++) {
                    float2 ce = __half22float2(sp[i * 4 + j]);
                    float2 dv = __half22float2(dh[j]);
                    float2 ev = __half22float2(ehh[j]);
                    float v0 = ce.x + bc[i * 8 + 2 * j] + dv.x + ev.x;
                    float v1 = ce.y + bc[i * 8 + 2 * j + 1] + dv.y + ev.y;
                    oh[j] = __floats2half2_rn(v0, v1);
                }
                if (!last) ep[i] = outv;
#pragma unroll
                for (int j = 0; j < 4; j++) sp[i * 4 + j] = oh[j];
            }
        }
        __syncthreads();

        // pass 2: per-column segment scan (pure smem)
        if (tid < 192) {
            int rbeg = gP2 * 64, rend = rbeg + 64;
            float num_acc = 0.f, den_acc = 0.f;
            int d = s_dst[rbeg];
            for (int r = rbeg; r < rend; r++) {
                float vv = __half2float(Sst[r * 100 + colP2]);
                float bv = __half2float(Sbv[r * 100 + colP2]);
                float sg = sigmoid_fast(vv);
                num_acc = fmaf(sg, bv, num_acc);
                den_acc += sg;
                bs_tot += vv;
                bq_tot = fmaf(vv, vv, bq_tot);
                int dn = (r + 1 < rend) ? s_dst[r + 1] : -1;
                if (dn != d) {
                    atomicAdd((float2*)&g_agg[((long long)d * 96 + colP2) * 2],
                              make_float2(num_acc, den_acc));
                    num_acc = 0.f;
                    den_acc = 0.f;
                    d = dn;
                }
            }
        }
    }
    if (!last && tid < 192) {
        atomicAdd(&g_sums[colP2], bs_tot);
        atomicAdd(&g_sums[DD + colP2], bq_tot);
    }
}

// ---------------- h_new = Ah + num/(den+eps), BN-h moments, re-zero agg ----------------
__global__ __launch_bounds__(384) void k_hnew() {
    __shared__ float ssum[96], ssq[96];
    int tid = threadIdx.x;
    int col = tid % 96, yr = tid / 96;
    if (tid < 96) { ssum[tid] = 0.f; ssq[tid] = 0.f; }
    __syncthreads();
    float sm = 0.f, sq = 0.f;
    for (int row = blockIdx.x * 4 + yr; row < NN; row += gridDim.x * 4) {
        int i = row * 96 + col;
        float2 nd = ((float2*)g_agg)[i];
        float v = g_A[i] + nd.x / (nd.y + AGG_EPS);
        g_hnew[i] = v;
        ((float2*)g_agg)[i] = make_float2(0.f, 0.f);
        sm += v;
        sq = fmaf(v, v, sq);
    }
    atomicAdd(&ssum[col], sm);
    atomicAdd(&ssq[col], sq);
    __syncthreads();
    if (tid < 96) {
        atomicAdd(&g_sums[2 * DD + tid], ssum[tid]);
        atomicAdd(&g_sums[3 * DD + tid], ssq[tid]);
    }
}

// ---------------- finalize BN stats ----------------
__global__ void k_finalize(int which, const float* __restrict__ g,
                           const float* __restrict__ b, float invM) {
    int c = threadIdx.x;
    if (c >= 96) return;
    int base = which * 2 * DD;
    float mu = g_sums[base + c] * invM;
    float var = g_sums[base + DD + c] * invM - mu * mu;
    float rstd = rsqrtf(var + BN_EPS);
    float sc = g[c] * rstd;
    float sh = b[c] - mu * sc;
    if (which == 0) { g_scale_e[c] = sc; g_shift_e[c] = sh; }
    else            { g_scale_h[c] = sc; g_shift_h[c] = sh; }
    g_sums[base + c] = 0.f;
    g_sums[base + DD + c] = 0.f;
}

// ---------------- MLP head ----------------
__global__ __launch_bounds__(128) void k_head(const float* __restrict__ W1,
                                              const float* __restrict__ b1,
                                              const float* __restrict__ W2,
                                              const float* __restrict__ b2,
                                              const float* __restrict__ maxa,
                                              float* __restrict__ out) {
    __shared__ float hs[8][96];
    __shared__ float hid[8][HIDN];
    int r0 = blockIdx.x * 8;
    int tid = threadIdx.x;
    for (int i = tid; i < 8 * 96; i += 128) {
        int r = i / 96, c = i % 96;
        int row = r0 + r;
        float v = 0.f;
        if (row < NN) {
            long long gi = (long long)row * 96 + c;
            v = g_h[gi] + fmaxf(0.f, g_hnew[gi] * g_scale_h[c] + g_shift_h[c]);
        }
        hs[r][c] = v;
    }
    __syncthreads();
    float acc[8];
#pragma unroll
    for (int r = 0; r < 8; r++) acc[r] = b1[tid];
#pragma unroll 4
    for (int k = 0; k < 96; k++) {
        float w = W1[k * HIDN + tid];
#pragma unroll
        for (int r = 0; r < 8; r++) acc[r] += hs[r][k] * w;
    }
#pragma unroll
    for (int r = 0; r < 8; r++) hid[r][tid] = fmaxf(acc[r], 0.f);
    __syncthreads();
    if (tid < 64) {
        int r = tid >> 3, c = tid & 7;
        int row = r0 + r;
        if (row < NN) {
            float a = b2[c];
#pragma unroll 8
            for (int k = 0; k < HIDN; k++) a += hid[r][k] * W2[k * OUTD + c];
            out[(long long)row * OUTD + c] = maxa[row] * tanhf(a);
        }
    }
}

// ---------------- launch ----------------
extern "C" void kernel_launch(void* const* d_in, const int* in_sizes, int n_in,
                              void* d_out, int out_size) {
    const float* h1 = (const float*)d_in[0];
    const float* h2 = (const float*)d_in[1];
    const float* z = (const float*)d_in[2];
    const float* efeat = (const float*)d_in[3];
    const float* max_action = (const float*)d_in[4];
    const float* Wh_emb = (const float*)d_in[5];
    const float* bh_emb = (const float*)d_in[6];
    const float* We_emb = (const float*)d_in[7];
    const float* be_emb = (const float*)d_in[8];
    const float* WA = (const float*)d_in[9];
    const float* bA = (const float*)d_in[10];
    const float* WB = (const float*)d_in[11];
    const float* bB = (const float*)d_in[12];
    const float* WC = (const float*)d_in[13];
    const float* bC = (const float*)d_in[14];
    const float* WD = (const float*)d_in[15];
    const float* bD = (const float*)d_in[16];
    const float* WE = (const float*)d_in[17];
    const float* bE = (const float*)d_in[18];
    const float* bn_h_g = (const float*)d_in[19];
    const float* bn_h_b = (const float*)d_in[20];
    const float* bn_e_g = (const float*)d_in[21];
    const float* bn_e_b = (const float*)d_in[22];
    const float* W1 = (const float*)d_in[23];
    const float* b1 = (const float*)d_in[24];
    const float* W2 = (const float*)d_in[25];
    const float* b2 = (const float*)d_in[26];
    const int* src = (const int*)d_in[27];
    const int* dst = (const int*)d_in[28];
    float* out = (float*)d_out;

    __half *p_wfhi, *p_wflo;
    cudaGetSymbolAddress((void**)&p_wfhi, g_Wf_hi);
    cudaGetSymbolAddress((void**)&p_wflo, g_Wf_lo);

    const int smem_node = NODE_U32 * 4;  // 65536
    const int smem_edge = EDGE_U32 * 4;  // 92672
    cudaFuncSetAttribute(k_node, cudaFuncAttributeMaxDynamicSharedMemorySize, smem_node);
    cudaFuncSetAttribute(k_edge, cudaFuncAttributeMaxDynamicSharedMemorySize, smem_edge);

    // sort (g_off/g_cursor zeroed by k_node layer0 each replay)
    k_hist<<<(EE + 255) / 256, 256>>>(dst);
    k_scan<<<1, 1024>>>();
    k_scatter<<<(EE + 255) / 256, 256>>>(src, dst);

    WPtrs wp{WA, WB, WC, WD, WE};
    k_prep<<<(20 * DD * DD + 255) / 256, 256>>>(wp);

    const int nblk = (NN + 127) / 128;  // 391
    const int eblk = 296;               // persistent: 2 blocks/SM

    for (int l = 0; l < 4; l++) {
        k_node<<<nblk, 256, smem_node>>>(bA + l * DD, bB + l * DD, bD + l * DD, bE + l * DD,
                                         l, l == 0 ? 2 : 1, h1, h2, z, Wh_emb, bh_emb);
        k_edge<<<eblk, 256, smem_edge>>>(p_wfhi + (2 * 4 + l) * DD * DD,
                                         p_wflo + (2 * 4 + l) * DD * DD,
                                         bC + l * DD, efeat, We_emb, be_emb,
                                         l == 0 ? 0 : 1, l == 3 ? 1 : 0);
        if (l < 3)
            k_finalize<<<1, 96>>>(0, bn_e_g + l * DD, bn_e_b + l * DD, 1.f / EE);
        k_hnew<<<256, 384>>>();
        k_finalize<<<1, 96>>>(1, bn_h_g + l * DD, bn_h_b + l * DD, 1.f / NN);
    }

    k_head<<<NN / 8, 128>>>(W1, b1, W2, b2, max_action, out);
}

// round 9
// speedup vs baseline: 2.3908x; 1.0290x over previous
#include <cuda_runtime.h>
#include <cuda_bf16.h>
#include <cuda_fp16.h>
#include <math.h>

#define NN 50000
#define EE 800000
#define DD 96
#define HIDN 128
#define OUTD 8
#define BN_EPS 1e-5f
#define AGG_EPS 1e-6f
#define NTILE 6250

// ---------------- device scratch ----------------
__device__ __align__(16) float g_h[NN * DD];
__device__ __align__(16) float g_A[NN * DD];
__device__ __align__(16) __half g_BDh[NN * DD * 2];  // B at [0,96), D at [96,192) per node
__device__ __align__(16) __half g_Eh[NN * DD];
__device__ __align__(16) float g_agg[NN * DD * 2];   // interleaved num/den
__device__ __align__(16) float g_hnew[NN * DD];
__device__ __align__(16) __half g_e[EE * DD];        // sorted order
__device__ __align__(16) __half g_enew[EE * DD];     // sorted order
__device__ __align__(16) float g_sums[4 * DD];
__device__ __align__(16) float g_scale_e[DD], g_shift_e[DD];
__device__ __align__(16) float g_scale_h[DD], g_shift_h[DD];
// transposed fp16 hi/lo weights: [type(A,B,C,D,E)*4+layer][n*96+k]
__device__ __align__(16) __half g_Wf_hi[20 * DD * DD];
__device__ __align__(16) __half g_Wf_lo[20 * DD * DD];
// dst-sorted edge structure
__device__ int g_perm[EE];
__device__ int g_src_s[EE];
__device__ int g_dst_s[EE];
__device__ int g_off[NN];
__device__ int g_cursor[NN];

// ---------------- helpers ----------------
__device__ __forceinline__ unsigned pack_h2(float x, float y) {
    __half2 t = __floats2half2_rn(x, y);
    return *reinterpret_cast<unsigned*>(&t);
}

__device__ __forceinline__ float sigmoid_fast(float x) {
    float t;
    asm("tanh.approx.f32 %0, %1;" : "=f"(t) : "f"(0.5f * x));
    return fmaf(0.5f, t, 0.5f);
}

__device__ __forceinline__ void mma_f16(float* c, const unsigned* a, unsigned b0, unsigned b1) {
    asm volatile(
        "mma.sync.aligned.m16n8k16.row.col.f32.f16.f16.f32 "
        "{%0,%1,%2,%3},{%4,%5,%6,%7},{%8,%9},{%0,%1,%2,%3};"
        : "+f"(c[0]), "+f"(c[1]), "+f"(c[2]), "+f"(c[3])
        : "r"(a[0]), "r"(a[1]), "r"(a[2]), "r"(a[3]), "r"(b0), "r"(b1));
}

// ---------------- fused: dst histogram + weight prep (one launch) ----------------
struct WPtrs { const float *a, *b, *c, *d, *e; };

__global__ void k_histprep(const int* __restrict__ dst, WPtrs p) {
    int idx = blockIdx.x * blockDim.x + threadIdx.x;
    if (idx < EE) atomicAdd(&g_off[dst[idx]], 1);
    if (idx < 20 * DD * DD) {
        int m = idx / (DD * DD), r = idx % (DD * DD);
        int k = r / DD, n = r % DD;
        int type = m >> 2, layer = m & 3;
        const float* src = type == 0 ? p.a : type == 1 ? p.b : type == 2 ? p.c
                           : type == 3 ? p.d : p.e;
        float w = src[layer * DD * DD + k * DD + n];
        __half hi = __float2half(w);
        g_Wf_hi[m * DD * DD + n * DD + k] = hi;
        g_Wf_lo[m * DD * DD + n * DD + k] = __float2half(w - __half2float(hi));
    }
}

__global__ void k_scan() {
    __shared__ int ssum[1024];
    const int STRIP = (NN + 1023) / 1024;
    int t = threadIdx.x;
    int beg = t * STRIP, end = beg + STRIP;
    if (end > NN) end = NN;
    int s = 0;
    for (int i = beg; i < end; i++) s += g_off[i];
    ssum[t] = s;
    __syncthreads();
    for (int ofs = 1; ofs < 1024; ofs <<= 1) {
        int v = (t >= ofs) ? ssum[t - ofs] : 0;
        __syncthreads();
        ssum[t] += v;
        __syncthreads();
    }
    int carry = (t > 0) ? ssum[t - 1] : 0;
    for (int i = beg; i < end; i++) {
        int v = g_off[i];
        g_off[i] = carry;
        carry += v;
    }
}

__global__ void k_scatter(const int* __restrict__ src, const int* __restrict__ dst) {
    int e = blockIdx.x * blockDim.x + threadIdx.x;
    if (e >= EE) return;
    int d = dst[e];
    int p = g_off[d] + atomicAdd(&g_cursor[d], 1);
    g_perm[p] = e;
    g_src_s[p] = src[e];
    g_dst_s[p] = d;
}

// smem layout node (u32): Ah[128*50] Whi[96*52] Wlo[96*52]
#define N_A 0
#define N_WHI (128 * 50)
#define N_WLO (128 * 50 + 96 * 52)
#define NODE_U32 (128 * 50 + 2 * 96 * 52)   // 16384 u32 = 65536 B

// ---------------- fused node GEMM: A(fp32), B/D->g_BDh, E(fp16); layer0 embeds ----------------
__global__ __launch_bounds__(256, 3) void k_node(const float* __restrict__ bA, const float* __restrict__ bB,
                                                 const float* __restrict__ bD, const float* __restrict__ bE,
                                                 int layer, int fuse,
                                                 const float* __restrict__ h1, const float* __restrict__ h2,
                                                 const float* __restrict__ z,
                                                 const float* __restrict__ Wh_emb,
                                                 const float* __restrict__ bh_emb) {
    extern __shared__ unsigned sm[];
    unsigned* Ah = sm + N_A;
    unsigned* Whi = sm + N_WHI;
    unsigned* Wlo = sm + N_WLO;
    int tid = threadIdx.x;
    int m0 = blockIdx.x * 128;
    int rows_valid = NN - m0;
    if (rows_valid > 128) rows_valid = 128;

    if (fuse == 2) {
        float* Whf = (float*)(sm + N_WHI);
        for (int i = tid; i < 26 * 96; i += 256) Whf[i] = Wh_emb[i];
        int gid = blockIdx.x * 256 + tid;
        if (gid < NN) { g_off[gid] = 0; g_cursor[gid] = 0; }
        __syncthreads();
        for (int i = tid; i < 128 * 24; i += 256) {
            int r = i / 24, c4 = i % 24;
            int row = m0 + r;
            float4 v = make_float4(0.f, 0.f, 0.f, 0.f);
            if (r < rows_valid) {
                float x[26];
                const float* p1 = h1 + row * 6;
#pragma unroll
                for (int k = 0; k < 6; k++) x[k] = p1[k];
                const float* p2 = h2 + row * 4;
#pragma unroll
                for (int k = 0; k < 4; k++) x[6 + k] = p2[k];
                const float* p3 = z + row * 16;
#pragma unroll
                for (int k = 0; k < 16; k++) x[10 + k] = p3[k];
                float a[4];
#pragma unroll
                for (int c = 0; c < 4; c++) a[c] = bh_emb[c4 * 4 + c];
#pragma unroll
                for (int k = 0; k < 26; k++) {
#pragma unroll
                    for (int c = 0; c < 4; c++)
                        a[c] = fmaf(x[k], Whf[k * 96 + c4 * 4 + c], a[c]);
                }
                v = make_float4(a[0], a[1], a[2], a[3]);
                ((float4*)g_h)[(long long)row * 24 + c4] = v;
            }
            Ah[r * 50 + c4 * 2] = pack_h2(v.x, v.y);
            Ah[r * 50 + c4 * 2 + 1] = pack_h2(v.z, v.w);
        }
    } else {
        for (int i = tid; i < 128 * 24; i += 256) {
            int r = i / 24, c4 = i % 24;
            float4 v = make_float4(0.f, 0.f, 0.f, 0.f);
            if (r < rows_valid) {
                long long gi = (long long)(m0 + r) * 24 + c4;
                v = ((const float4*)g_h)[gi];
                float4 en = ((const float4*)g_hnew)[gi];
                int c = c4 * 4;
                v.x += fmaxf(0.f, en.x * g_scale_h[c] + g_shift_h[c]);
                v.y += fmaxf(0.f, en.y * g_scale_h[c + 1] + g_shift_h[c + 1]);
                v.z += fmaxf(0.f, en.z * g_scale_h[c + 2] + g_shift_h[c + 2]);
                v.w += fmaxf(0.f, en.w * g_scale_h[c + 3] + g_shift_h[c + 3]);
                ((float4*)g_h)[gi] = v;
            }
            Ah[r * 50 + c4 * 2] = pack_h2(v.x, v.y);
            Ah[r * 50 + c4 * 2 + 1] = pack_h2(v.z, v.w);
        }
    }

    int w = tid >> 5, lane = tid & 31;
    int wm = w & 3, wn = w >> 2;
    const int types[4] = {0, 1, 3, 4};
    const float* biases[4] = {bA, bB, bD, bE};

    for (int t = 0; t < 4; t++) {
        __syncthreads();
        const unsigned* gwh = (const unsigned*)(g_Wf_hi + (types[t] * 4 + layer) * DD * DD);
        const unsigned* gwl = (const unsigned*)(g_Wf_lo + (types[t] * 4 + layer) * DD * DD);
        for (int i = tid; i < 96 * 48; i += 256) {
            int n = i / 48, kp = i % 48;
            Whi[n * 52 + kp] = gwh[i];
            Wlo[n * 52 + kp] = gwl[i];
        }
        __syncthreads();

        float acc[2][6][4];
#pragma unroll
        for (int m = 0; m < 2; m++)
#pragma unroll
            for (int n = 0; n < 6; n++)
#pragma unroll
                for (int j = 0; j < 4; j++) acc[m][n][j] = 0.f;

#pragma unroll
        for (int kt = 0; kt < 6; kt++) {
            int kp = kt * 8 + (lane & 3);
            unsigned ah[2][4];
#pragma unroll
            for (int m = 0; m < 2; m++) {
                int row = wm * 32 + m * 16 + (lane >> 2);
                ah[m][0] = Ah[row * 50 + kp];
                ah[m][1] = Ah[(row + 8) * 50 + kp];
                ah[m][2] = Ah[row * 50 + kp + 4];
                ah[m][3] = Ah[(row + 8) * 50 + kp + 4];
            }
#pragma unroll
            for (int n = 0; n < 6; n++) {
                int col = wn * 48 + n * 8 + (lane >> 2);
                unsigned bh0 = Whi[col * 52 + kp], bh1 = Whi[col * 52 + kp + 4];
                unsigned bl0 = Wlo[col * 52 + kp], bl1 = Wlo[col * 52 + kp + 4];
#pragma unroll
                for (int m = 0; m < 2; m++) {
                    mma_f16(acc[m][n], ah[m], bh0, bh1);
                    mma_f16(acc[m][n], ah[m], bl0, bl1);
                }
            }
        }

        const float* bias = biases[t];
#pragma unroll
        for (int m = 0; m < 2; m++) {
#pragma unroll
            for (int n = 0; n < 6; n++) {
                int row = m0 + wm * 32 + m * 16 + (lane >> 2);
                int col = wn * 48 + n * 8 + ((lane & 3) << 1);
                float b0 = bias[col], b1 = bias[col + 1];
                float v00 = acc[m][n][0] + b0, v01 = acc[m][n][1] + b1;
                float v10 = acc[m][n][2] + b0, v11 = acc[m][n][3] + b1;
                if (t == 0) {
                    if (row < NN)
                        *(float2*)&g_A[(long long)row * 96 + col] = make_float2(v00, v01);
                    if (row + 8 < NN)
                        *(float2*)&g_A[(long long)(row + 8) * 96 + col] = make_float2(v10, v11);
                } else {
                    // t=1 -> B (BDh+0), t=2 -> D (BDh+96), t=3 -> E
                    if (t < 3) {
                        int ofs = (t == 1) ? 0 : 96;
                        if (row < NN)
                            *(__half2*)&g_BDh[(long long)row * 192 + ofs + col] = __floats2half2_rn(v00, v01);
                        if (row + 8 < NN)
                            *(__half2*)&g_BDh[(long long)(row + 8) * 192 + ofs + col] = __floats2half2_rn(v10, v11);
                    } else {
                        if (row < NN)
                            *(__half2*)&g_Eh[(long long)row * 96 + col] = __floats2half2_rn(v00, v01);
                        if (row + 8 < NN)
                            *(__half2*)&g_Eh[(long long)(row + 8) * 96 + col] = __floats2half2_rn(v10, v11);
                    }
                }
            }
        }
    }
}

// smem layout edge (u32): Whi[96*52] Wlo[96*52] Wemb[384] | Sst[128*50] Sbv[128*50]
#define EW_HI 0
#define EW_LO (96 * 52)
#define EW_EMB (2 * 96 * 52)
#define ER_OFF (2 * 96 * 52 + 384)
#define ESBV_OFF (ER_OFF + 6400)
#define EDGE_U32 (ER_OFF + 12800)   // 23168 u32 = 92672 B

// ---------------- persistent fused edge layer (384 threads, 12 warps) ----------------
__global__ __launch_bounds__(384, 2) void k_edge(const __half* __restrict__ Whi_g,
                                                 const __half* __restrict__ Wlo_g,
                                                 const float* __restrict__ bC,
                                                 const float* __restrict__ efeat,
                                                 const float* __restrict__ We,
                                                 const float* __restrict__ be,
                                                 int fuse, int last) {
    extern __shared__ unsigned sm[];
    unsigned* Whi = sm + EW_HI;
    unsigned* Wlo = sm + EW_LO;
    float* Wemb = (float*)(sm + EW_EMB);
    unsigned* Ah = sm + ER_OFF;              // 128x50 u32, aliases Sst
    __half* Sst = (__half*)(sm + ER_OFF);    // 128x100 halves
    __half* Sbv = (__half*)(sm + ESBV_OFF);  // 128x100 halves
    unsigned* SbvU = sm + ESBV_OFF;
    __shared__ int s_src[128], s_dst[128];
    int tid = threadIdx.x;

    {
        const unsigned* gwh = (const unsigned*)Whi_g;
        const unsigned* gwl = (const unsigned*)Wlo_g;
        for (int i = tid; i < 96 * 48; i += 384) {
            int n = i / 48, kp = i % 48;
            Whi[n * 52 + kp] = gwh[i];
            Wlo[n * 52 + kp] = gwl[i];
        }
        if (fuse == 0 && tid < 384) Wemb[tid] = We[tid];
    }

    int w = tid >> 5, lane = tid & 31;
    int wm = w & 3, wn = w >> 2;              // 4 x 3 warp grid
    int rP = tid / 3, thirdP = tid % 3;       // pass-1 split: 3 threads/row
    int colP2 = tid % 96, gP2 = tid / 96;     // pass-2 split: 4 groups x 32 rows
    float bs_tot = 0.f, bq_tot = 0.f;

    for (int tile = blockIdx.x; tile < NTILE; tile += gridDim.x) {
        int e0 = tile * 128;
        __syncthreads();
        if (tid < 128) {
            s_src[tid] = g_src_s[e0 + tid];
            s_dst[tid] = g_dst_s[e0 + tid];
        }

        // stage B rows now: latency hides behind GEMM
        {
            int s = g_src_s[e0 + rP];
            const uint4* Br = (const uint4*)(g_BDh + (long long)s * 192) + thirdP * 4;
            unsigned* pb = SbvU + rP * 50 + thirdP * 16;
#pragma unroll
            for (int i = 0; i < 4; i++) {
                uint4 bu = Br[i];
                pb[i * 4] = bu.x; pb[i * 4 + 1] = bu.y;
                pb[i * 4 + 2] = bu.z; pb[i * 4 + 3] = bu.w;
            }
        }

        if (fuse == 0) {
            for (int i = tid; i < 128 * 12; i += 384) {
                int r = i / 12, c8 = i % 12;
                int er = e0 + r;
                const float4 ef = ((const float4*)efeat)[g_perm[er]];
                uint4 v;
                __half2* vh = (__half2*)&v;
#pragma unroll
                for (int j = 0; j < 4; j++) {
                    int c = c8 * 8 + 2 * j;
                    float o0 = be[c] + ef.x * Wemb[c] + ef.y * Wemb[96 + c] +
                               ef.z * Wemb[192 + c] + ef.w * Wemb[288 + c];
                    float o1 = be[c + 1] + ef.x * Wemb[c + 1] + ef.y * Wemb[96 + c + 1] +
                               ef.z * Wemb[192 + c + 1] + ef.w * Wemb[288 + c + 1];
                    vh[j] = __floats2half2_rn(o0, o1);
                }
                __stcs((uint4*)g_e + (long long)er * 12 + c8, v);
                unsigned* vu = (unsigned*)&v;
#pragma unroll
                for (int j = 0; j < 4; j++) Ah[r * 50 + c8 * 4 + j] = vu[j];
            }
        } else {
            for (int i = tid; i < 128 * 12; i += 384) {
                int r = i / 12, c8 = i % 12;
                long long gi = (long long)(e0 + r) * 12 + c8;
                uint4 v = __ldcs((const uint4*)g_e + gi);
                uint4 en = __ldcs((const uint4*)g_enew + gi);
                __half2* vh = (__half2*)&v;
                __half2* eh = (__half2*)&en;
                int c = c8 * 8;
#pragma unroll
                for (int j = 0; j < 4; j++) {
                    float2 f = __half22float2(vh[j]);
                    float2 ev = __half22float2(eh[j]);
                    f.x += fmaxf(0.f, ev.x * g_scale_e[c + 2 * j] + g_shift_e[c + 2 * j]);
                    f.y += fmaxf(0.f, ev.y * g_scale_e[c + 2 * j + 1] + g_shift_e[c + 2 * j + 1]);
                    vh[j] = __floats2half2_rn(f.x, f.y);
                }
                if (!last) __stcs((uint4*)g_e + gi, v);
                unsigned* vu = (unsigned*)&v;
#pragma unroll
                for (int j = 0; j < 4; j++) Ah[r * 50 + c8 * 4 + j] = vu[j];
            }
        }
        __syncthreads();

        // fp16 GEMM: Ce = e @ (Whi + Wlo); 12 warps, each 32 rows x 32 cols
        float acc[2][4][4];
#pragma unroll
        for (int m = 0; m < 2; m++)
#pragma unroll
            for (int n = 0; n < 4; n++)
#pragma unroll
                for (int j = 0; j < 4; j++) acc[m][n][j] = 0.f;

#pragma unroll
        for (int kt = 0; kt < 6; kt++) {
            int kp = kt * 8 + (lane & 3);
            unsigned ah[2][4];
#pragma unroll
            for (int m = 0; m < 2; m++) {
                int row = wm * 32 + m * 16 + (lane >> 2);
                ah[m][0] = Ah[row * 50 + kp];
                ah[m][1] = Ah[(row + 8) * 50 + kp];
                ah[m][2] = Ah[row * 50 + kp + 4];
                ah[m][3] = Ah[(row + 8) * 50 + kp + 4];
            }
#pragma unroll
            for (int n = 0; n < 4; n++) {
                int col = wn * 32 + n * 8 + (lane >> 2);
                unsigned bh0 = Whi[col * 52 + kp], bh1 = Whi[col * 52 + kp + 4];
                unsigned bl0 = Wlo[col * 52 + kp], bl1 = Wlo[col * 52 + kp + 4];
#pragma unroll
                for (int m = 0; m < 2; m++) {
                    mma_f16(acc[m][n], ah[m], bh0, bh1);
                    mma_f16(acc[m][n], ah[m], bl0, bl1);
                }
            }
        }
        __syncthreads();  // Ah dead; stage Ce over it

#pragma unroll
        for (int m = 0; m < 2; m++) {
#pragma unroll
            for (int n = 0; n < 4; n++) {
                int lr = wm * 32 + m * 16 + (lane >> 2);
                int col = wn * 32 + n * 8 + ((lane & 3) << 1);
                *(__half2*)&Sst[lr * 100 + col] = __floats2half2_rn(acc[m][n][0], acc[m][n][1]);
                *(__half2*)&Sst[(lr + 8) * 100 + col] = __floats2half2_rn(acc[m][n][2], acc[m][n][3]);
            }
        }
        __syncthreads();

        // pass 1: vv = Ce + bC + D[src] + E[dst]; restage vv; write e_new (3 thr/row)
        {
            int s = s_src[rP], d = s_dst[rP];
            const uint4* Dr = (const uint4*)(g_BDh + (long long)s * 192) + 12 + thirdP * 4;
            const uint4* Er = (const uint4*)(g_Eh + (long long)d * 96) + thirdP * 4;
            uint4 du[4], eu[4];
#pragma unroll
            for (int i = 0; i < 4; i++) { du[i] = Dr[i]; eu[i] = Er[i]; }
            __half2* sp = (__half2*)(Sst + rP * 100 + thirdP * 32);
            uint4* ep = (uint4*)g_enew + (long long)(e0 + rP) * 12 + thirdP * 4;
            const float* bc = bC + thirdP * 32;
#pragma unroll
            for (int i = 0; i < 4; i++) {
                __half2* dh = (__half2*)&du[i];
                __half2* ehh = (__half2*)&eu[i];
                uint4 outv;
                __half2* oh = (__half2*)&outv;
#pragma unroll
                for (int j = 0; j < 4; j++) {
                    float2 ce = __half22float2(sp[i * 4 + j]);
                    float2 dv = __half22float2(dh[j]);
                    float2 ev = __half22float2(ehh[j]);
                    float v0 = ce.x + bc[i * 8 + 2 * j] + dv.x + ev.x;
                    float v1 = ce.y + bc[i * 8 + 2 * j + 1] + dv.y + ev.y;
                    oh[j] = __floats2half2_rn(v0, v1);
                }
                if (!last) __stcs(ep + i, outv);
#pragma unroll
                for (int j = 0; j < 4; j++) sp[i * 4 + j] = oh[j];
            }
        }
        __syncthreads();

        // pass 2: per-column segment scan, 4 groups x 32 rows (all 384 threads)
        {
            int rbeg = gP2 * 32, rend = rbeg + 32;
            float num_acc = 0.f, den_acc = 0.f;
            int d = s_dst[rbeg];
            for (int r = rbeg; r < rend; r++) {
                float vv = __half2float(Sst[r * 100 + colP2]);
                float bv = __half2float(Sbv[r * 100 + colP2]);
                float sg = sigmoid_fast(vv);
                num_acc = fmaf(sg, bv, num_acc);
                den_acc += sg;
                bs_tot += vv;
                bq_tot = fmaf(vv, vv, bq_tot);
                int dn = (r + 1 < rend) ? s_dst[r + 1] : -1;
                if (dn != d) {
                    atomicAdd((float2*)&g_agg[((long long)d * 96 + colP2) * 2],
                              make_float2(num_acc, den_acc));
                    num_acc = 0.f;
                    den_acc = 0.f;
                    d = dn;
                }
            }
        }
    }
    if (!last) {
        atomicAdd(&g_sums[colP2], bs_tot);
        atomicAdd(&g_sums[DD + colP2], bq_tot);
    }
}

// ---------------- h_new = Ah + num/(den+eps), BN-h moments, re-zero agg ----------------
__global__ __launch_bounds__(384) void k_hnew() {
    __shared__ float ssum[96], ssq[96];
    int tid = threadIdx.x;
    int col = tid % 96, yr = tid / 96;
    if (tid < 96) { ssum[tid] = 0.f; ssq[tid] = 0.f; }
    __syncthreads();
    float sm = 0.f, sq = 0.f;
    for (int row = blockIdx.x * 4 + yr; row < NN; row += gridDim.x * 4) {
        int i = row * 96 + col;
        float2 nd = ((float2*)g_agg)[i];
        float v = g_A[i] + nd.x / (nd.y + AGG_EPS);
        g_hnew[i] = v;
        ((float2*)g_agg)[i] = make_float2(0.f, 0.f);
        sm += v;
        sq = fmaf(v, v, sq);
    }
    atomicAdd(&ssum[col], sm);
    atomicAdd(&ssq[col], sq);
    __syncthreads();
    if (tid < 96) {
        atomicAdd(&g_sums[2 * DD + tid], ssum[tid]);
        atomicAdd(&g_sums[3 * DD + tid], ssq[tid]);
    }
}

// ---------------- finalize BN stats ----------------
__global__ void k_finalize(int which, const float* __restrict__ g,
                           const float* __restrict__ b, float invM) {
    int c = threadIdx.x;
    if (c >= 96) return;
    int base = which * 2 * DD;
    float mu = g_sums[base + c] * invM;
    float var = g_sums[base + DD + c] * invM - mu * mu;
    float rstd = rsqrtf(var + BN_EPS);
    float sc = g[c] * rstd;
    float sh = b[c] - mu * sc;
    if (which == 0) { g_scale_e[c] = sc; g_shift_e[c] = sh; }
    else            { g_scale_h[c] = sc; g_shift_h[c] = sh; }
    g_sums[base + c] = 0.f;
    g_sums[base + DD + c] = 0.f;
}

// ---------------- MLP head ----------------
__global__ __launch_bounds__(128) void k_head(const float* __restrict__ W1,
                                              const float* __restrict__ b1,
                                              const float* __restrict__ W2,
                                              const float* __restrict__ b2,
                                              const float* __restrict__ maxa,
                                              float* __restrict__ out) {
    __shared__ float hs[8][96];
    __shared__ float hid[8][HIDN];
    int r0 = blockIdx.x * 8;
    int tid = threadIdx.x;
    for (int i = tid; i < 8 * 96; i += 128) {
        int r = i / 96, c = i % 96;
        int row = r0 + r;
        float v = 0.f;
        if (row < NN) {
            long long gi = (long long)row * 96 + c;
            v = g_h[gi] + fmaxf(0.f, g_hnew[gi] * g_scale_h[c] + g_shift_h[c]);
        }
        hs[r][c] = v;
    }
    __syncthreads();
    float acc[8];
#pragma unroll
    for (int r = 0; r < 8; r++) acc[r] = b1[tid];
#pragma unroll 4
    for (int k = 0; k < 96; k++) {
        float w = W1[k * HIDN + tid];
#pragma unroll
        for (int r = 0; r < 8; r++) acc[r] += hs[r][k] * w;
    }
#pragma unroll
    for (int r = 0; r < 8; r++) hid[r][tid] = fmaxf(acc[r], 0.f);
    __syncthreads();
    if (tid < 64) {
        int r = tid >> 3, c = tid & 7;
        int row = r0 + r;
        if (row < NN) {
            float a = b2[c];
#pragma unroll 8
            for (int k = 0; k < HIDN; k++) a += hid[r][k] * W2[k * OUTD + c];
            out[(long long)row * OUTD + c] = maxa[row] * tanhf(a);
        }
    }
}

// ---------------- launch ----------------
extern "C" void kernel_launch(void* const* d_in, const int* in_sizes, int n_in,
                              void* d_out, int out_size) {
    const float* h1 = (const float*)d_in[0];
    const float* h2 = (const float*)d_in[1];
    const float* z = (const float*)d_in[2];
    const float* efeat = (const float*)d_in[3];
    const float* max_action = (const float*)d_in[4];
    const float* Wh_emb = (const float*)d_in[5];
    const float* bh_emb = (const float*)d_in[6];
    const float* We_emb = (const float*)d_in[7];
    const float* be_emb = (const float*)d_in[8];
    const float* WA = (const float*)d_in[9];
    const float* bA = (const float*)d_in[10];
    const float* WB = (const float*)d_in[11];
    const float* bB = (const float*)d_in[12];
    const float* WC = (const float*)d_in[13];
    const float* bC = (const float*)d_in[14];
    const float* WD = (const float*)d_in[15];
    const float* bD = (const float*)d_in[16];
    const float* WE = (const float*)d_in[17];
    const float* bE = (const float*)d_in[18];
    const float* bn_h_g = (const float*)d_in[19];
    const float* bn_h_b = (const float*)d_in[20];
    const float* bn_e_g = (const float*)d_in[21];
    const float* bn_e_b = (const float*)d_in[22];
    const float* W1 = (const float*)d_in[23];
    const float* b1 = (const float*)d_in[24];
    const float* W2 = (const float*)d_in[25];
    const float* b2 = (const float*)d_in[26];
    const int* src = (const int*)d_in[27];
    const int* dst = (const int*)d_in[28];
    float* out = (float*)d_out;

    __half *p_wfhi, *p_wflo;
    cudaGetSymbolAddress((void**)&p_wfhi, g_Wf_hi);
    cudaGetSymbolAddress((void**)&p_wflo, g_Wf_lo);

    const int smem_node = NODE_U32 * 4;  // 65536
    const int smem_edge = EDGE_U32 * 4;  // 92672
    cudaFuncSetAttribute(k_node, cudaFuncAttributeMaxDynamicSharedMemorySize, smem_node);
    cudaFuncSetAttribute(k_edge, cudaFuncAttributeMaxDynamicSharedMemorySize, smem_edge);

    // sort + weight prep (g_off/g_cursor zeroed by k_node layer0 each replay)
    WPtrs wp{WA, WB, WC, WD, WE};
    k_histprep<<<(EE + 255) / 256, 256>>>(dst, wp);
    k_scan<<<1, 1024>>>();
    k_scatter<<<(EE + 255) / 256, 256>>>(src, dst);

    const int nblk = (NN + 127) / 128;  // 391
    const int eblk = 296;               // persistent: 2 blocks/SM

    for (int l = 0; l < 4; l++) {
        k_node<<<nblk, 256, smem_node>>>(bA + l * DD, bB + l * DD, bD + l * DD, bE + l * DD,
                                         l, l == 0 ? 2 : 1, h1, h2, z, Wh_emb, bh_emb);
        k_edge<<<eblk, 384, smem_edge>>>(p_wfhi + (2 * 4 + l) * DD * DD,
                                         p_wflo + (2 * 4 + l) * DD * DD,
                                         bC + l * DD, efeat, We_emb, be_emb,
                                         l == 0 ? 0 : 1, l == 3 ? 1 : 0);
        if (l < 3)
            k_finalize<<<1, 96>>>(0, bn_e_g + l * DD, bn_e_b + l * DD, 1.f / EE);
        k_hnew<<<256, 384>>>();
        k_finalize<<<1, 96>>>(1, bn_h_g + l * DD, bn_h_b + l * DD, 1.f / NN);
    }

    k_head<<<NN / 8, 128>>>(W1, b1, W2, b2, max_action, out);
}

// round 10
// speedup vs baseline: 2.5574x; 1.0697x over previous
#include <cuda_runtime.h>
#include <cuda_bf16.h>
#include <cuda_fp16.h>
#include <math.h>

#define NN 50000
#define EE 800000
#define DD 96
#define HIDN 128
#define OUTD 8
#define BN_EPS 1e-5f
#define AGG_EPS 1e-6f
#define NTILE 6250

// ---------------- device scratch ----------------
__device__ __align__(16) float g_h[NN * DD];
__device__ __align__(16) float g_A[NN * DD];
__device__ __align__(16) __half g_BDh[NN * DD * 2];  // B at [0,96), D at [96,192) per node
__device__ __align__(16) __half g_Eh[NN * DD];
__device__ __align__(16) float g_agg[NN * DD * 2];   // interleaved num/den
__device__ __align__(16) float g_hnew[NN * DD];
__device__ __align__(16) __half g_e[EE * DD];        // sorted order
__device__ __align__(16) __half g_enew[EE * DD];     // sorted order
__device__ __align__(16) float g_sums[4 * DD];
__device__ __align__(16) float g_scale_e[DD], g_shift_e[DD];
__device__ __align__(16) float g_scale_h[DD], g_shift_h[DD];
__device__ __align__(16) __half g_Wf_hi[20 * DD * DD];
__device__ __align__(16) __half g_Wf_lo[20 * DD * DD];
// dst-sorted edge structure
__device__ int g_perm[EE];
__device__ int g_src_s[EE];
__device__ int g_dst_s[EE];
__device__ int g_off[NN];
__device__ int g_cursor[NN];

// ---------------- helpers ----------------
__device__ __forceinline__ unsigned pack_h2(float x, float y) {
    __half2 t = __floats2half2_rn(x, y);
    return *reinterpret_cast<unsigned*>(&t);
}

__device__ __forceinline__ float sigmoid_fast(float x) {
    float t;
    asm("tanh.approx.f32 %0, %1;" : "=f"(t) : "f"(0.5f * x));
    return fmaf(0.5f, t, 0.5f);
}

__device__ __forceinline__ void prefetchL2(const void* p) {
    asm volatile("prefetch.global.L2 [%0];" :: "l"(p));
}

__device__ __forceinline__ void mma_f16(float* c, const unsigned* a, unsigned b0, unsigned b1) {
    asm volatile(
        "mma.sync.aligned.m16n8k16.row.col.f32.f16.f16.f32 "
        "{%0,%1,%2,%3},{%4,%5,%6,%7},{%8,%9},{%0,%1,%2,%3};"
        : "+f"(c[0]), "+f"(c[1]), "+f"(c[2]), "+f"(c[3])
        : "r"(a[0]), "r"(a[1]), "r"(a[2]), "r"(a[3]), "r"(b0), "r"(b1));
}

// ---------------- fused: dst histogram + weight prep ----------------
struct WPtrs { const float *a, *b, *c, *d, *e; };

__global__ void k_histprep(const int* __restrict__ dst, WPtrs p) {
    int idx = blockIdx.x * blockDim.x + threadIdx.x;
    if (idx < EE) atomicAdd(&g_off[dst[idx]], 1);
    if (idx < 20 * DD * DD) {
        int m = idx / (DD * DD), r = idx % (DD * DD);
        int k = r / DD, n = r % DD;
        int type = m >> 2, layer = m & 3;
        const float* src = type == 0 ? p.a : type == 1 ? p.b : type == 2 ? p.c
                           : type == 3 ? p.d : p.e;
        float w = src[layer * DD * DD + k * DD + n];
        __half hi = __float2half(w);
        g_Wf_hi[m * DD * DD + n * DD + k] = hi;
        g_Wf_lo[m * DD * DD + n * DD + k] = __float2half(w - __half2float(hi));
    }
}

__global__ void k_scan() {
    __shared__ int ssum[1024];
    const int STRIP = (NN + 1023) / 1024;
    int t = threadIdx.x;
    int beg = t * STRIP, end = beg + STRIP;
    if (end > NN) end = NN;
    int s = 0;
    for (int i = beg; i < end; i++) s += g_off[i];
    ssum[t] = s;
    __syncthreads();
    for (int ofs = 1; ofs < 1024; ofs <<= 1) {
        int v = (t >= ofs) ? ssum[t - ofs] : 0;
        __syncthreads();
        ssum[t] += v;
        __syncthreads();
    }
    int carry = (t > 0) ? ssum[t - 1] : 0;
    for (int i = beg; i < end; i++) {
        int v = g_off[i];
        g_off[i] = carry;
        carry += v;
    }
}

// smem layout node (u32): Ah[128*50] Whi[96*52] Wlo[96*52]
#define N_A 0
#define N_WHI (128 * 50)
#define N_WLO (128 * 50 + 96 * 52)
#define NODE_U32 (128 * 50 + 2 * 96 * 52)   // 16384 u32 = 65536 B

// ---------------- fused node GEMM (+ scatter when fuse==2) ----------------
__global__ __launch_bounds__(256, 3) void k_node(const float* __restrict__ bA, const float* __restrict__ bB,
                                                 const float* __restrict__ bD, const float* __restrict__ bE,
                                                 int layer, int fuse,
                                                 const float* __restrict__ h1, const float* __restrict__ h2,
                                                 const float* __restrict__ z,
                                                 const float* __restrict__ Wh_emb,
                                                 const float* __restrict__ bh_emb,
                                                 const int* __restrict__ src_in,
                                                 const int* __restrict__ dst_in) {
    extern __shared__ unsigned sm[];
    unsigned* Ah = sm + N_A;
    unsigned* Whi = sm + N_WHI;
    unsigned* Wlo = sm + N_WLO;
    int tid = threadIdx.x;

    if (fuse == 2) {
        // scatter phase (all 3125 blocks)
        int e = blockIdx.x * 256 + tid;
        if (e < EE) {
            int d = dst_in[e];
            int p = g_off[d] + atomicAdd(&g_cursor[d], 1);
            g_perm[p] = e;
            g_src_s[p] = src_in[e];
            g_dst_s[p] = d;
        }
        if (blockIdx.x >= (NN + 127) / 128) return;  // only 391 blocks do node work
    }

    int m0 = blockIdx.x * 128;
    int rows_valid = NN - m0;
    if (rows_valid > 128) rows_valid = 128;

    if (fuse == 2) {
        float* Whf = (float*)(sm + N_WHI);
        for (int i = tid; i < 26 * 96; i += 256) Whf[i] = Wh_emb[i];
        __syncthreads();
        for (int i = tid; i < 128 * 24; i += 256) {
            int r = i / 24, c4 = i % 24;
            int row = m0 + r;
            float4 v = make_float4(0.f, 0.f, 0.f, 0.f);
            if (r < rows_valid) {
                float x[26];
                const float* p1 = h1 + row * 6;
#pragma unroll
                for (int k = 0; k < 6; k++) x[k] = p1[k];
                const float* p2 = h2 + row * 4;
#pragma unroll
                for (int k = 0; k < 4; k++) x[6 + k] = p2[k];
                const float* p3 = z + row * 16;
#pragma unroll
                for (int k = 0; k < 16; k++) x[10 + k] = p3[k];
                float a[4];
#pragma unroll
                for (int c = 0; c < 4; c++) a[c] = bh_emb[c4 * 4 + c];
#pragma unroll
                for (int k = 0; k < 26; k++) {
#pragma unroll
                    for (int c = 0; c < 4; c++)
                        a[c] = fmaf(x[k], Whf[k * 96 + c4 * 4 + c], a[c]);
                }
                v = make_float4(a[0], a[1], a[2], a[3]);
                ((float4*)g_h)[(long long)row * 24 + c4] = v;
            }
            Ah[r * 50 + c4 * 2] = pack_h2(v.x, v.y);
            Ah[r * 50 + c4 * 2 + 1] = pack_h2(v.z, v.w);
        }
    } else {
        for (int i = tid; i < 128 * 24; i += 256) {
            int r = i / 24, c4 = i % 24;
            float4 v = make_float4(0.f, 0.f, 0.f, 0.f);
            if (r < rows_valid) {
                long long gi = (long long)(m0 + r) * 24 + c4;
                v = ((const float4*)g_h)[gi];
                float4 en = ((const float4*)g_hnew)[gi];
                int c = c4 * 4;
                v.x += fmaxf(0.f, en.x * g_scale_h[c] + g_shift_h[c]);
                v.y += fmaxf(0.f, en.y * g_scale_h[c + 1] + g_shift_h[c + 1]);
                v.z += fmaxf(0.f, en.z * g_scale_h[c + 2] + g_shift_h[c + 2]);
                v.w += fmaxf(0.f, en.w * g_scale_h[c + 3] + g_shift_h[c + 3]);
                ((float4*)g_h)[gi] = v;
            }
            Ah[r * 50 + c4 * 2] = pack_h2(v.x, v.y);
            Ah[r * 50 + c4 * 2 + 1] = pack_h2(v.z, v.w);
        }
    }

    int w = tid >> 5, lane = tid & 31;
    int wm = w & 3, wn = w >> 2;
    const int types[4] = {0, 1, 3, 4};
    const float* biases[4] = {bA, bB, bD, bE};

    for (int t = 0; t < 4; t++) {
        __syncthreads();
        const unsigned* gwh = (const unsigned*)(g_Wf_hi + (types[t] * 4 + layer) * DD * DD);
        const unsigned* gwl = (const unsigned*)(g_Wf_lo + (types[t] * 4 + layer) * DD * DD);
        for (int i = tid; i < 96 * 48; i += 256) {
            int n = i / 48, kp = i % 48;
            Whi[n * 52 + kp] = gwh[i];
            Wlo[n * 52 + kp] = gwl[i];
        }
        __syncthreads();

        float acc[2][6][4];
#pragma unroll
        for (int m = 0; m < 2; m++)
#pragma unroll
            for (int n = 0; n < 6; n++)
#pragma unroll
                for (int j = 0; j < 4; j++) acc[m][n][j] = 0.f;

#pragma unroll
        for (int kt = 0; kt < 6; kt++) {
            int kp = kt * 8 + (lane & 3);
            unsigned ah[2][4];
#pragma unroll
            for (int m = 0; m < 2; m++) {
                int row = wm * 32 + m * 16 + (lane >> 2);
                ah[m][0] = Ah[row * 50 + kp];
                ah[m][1] = Ah[(row + 8) * 50 + kp];
                ah[m][2] = Ah[row * 50 + kp + 4];
                ah[m][3] = Ah[(row + 8) * 50 + kp + 4];
            }
#pragma unroll
            for (int n = 0; n < 6; n++) {
                int col = wn * 48 + n * 8 + (lane >> 2);
                unsigned bh0 = Whi[col * 52 + kp], bh1 = Whi[col * 52 + kp + 4];
                unsigned bl0 = Wlo[col * 52 + kp], bl1 = Wlo[col * 52 + kp + 4];
#pragma unroll
                for (int m = 0; m < 2; m++) {
                    mma_f16(acc[m][n], ah[m], bh0, bh1);
                    mma_f16(acc[m][n], ah[m], bl0, bl1);
                }
            }
        }

        const float* bias = biases[t];
#pragma unroll
        for (int m = 0; m < 2; m++) {
#pragma unroll
            for (int n = 0; n < 6; n++) {
                int row = m0 + wm * 32 + m * 16 + (lane >> 2);
                int col = wn * 48 + n * 8 + ((lane & 3) << 1);
                float b0 = bias[col], b1 = bias[col + 1];
                float v00 = acc[m][n][0] + b0, v01 = acc[m][n][1] + b1;
                float v10 = acc[m][n][2] + b0, v11 = acc[m][n][3] + b1;
                if (t == 0) {
                    if (row < NN)
                        *(float2*)&g_A[(long long)row * 96 + col] = make_float2(v00, v01);
                    if (row + 8 < NN)
                        *(float2*)&g_A[(long long)(row + 8) * 96 + col] = make_float2(v10, v11);
                } else if (t < 3) {
                    int ofs = (t == 1) ? 0 : 96;
                    if (row < NN)
                        *(__half2*)&g_BDh[(long long)row * 192 + ofs + col] = __floats2half2_rn(v00, v01);
                    if (row + 8 < NN)
                        *(__half2*)&g_BDh[(long long)(row + 8) * 192 + ofs + col] = __floats2half2_rn(v10, v11);
                } else {
                    if (row < NN)
                        *(__half2*)&g_Eh[(long long)row * 96 + col] = __floats2half2_rn(v00, v01);
                    if (row + 8 < NN)
                        *(__half2*)&g_Eh[(long long)(row + 8) * 96 + col] = __floats2half2_rn(v10, v11);
                }
            }
        }
    }
}

// smem layout edge (u32): Whi[96*52] Wlo[96*52] Wemb[384] | Ah/Sst[128*50] Sbv[128*50]
#define EW_HI 0
#define EW_LO (96 * 52)
#define EW_EMB (2 * 96 * 52)
#define ER_OFF (2 * 96 * 52 + 384)
#define ESBV_OFF (ER_OFF + 6400)
#define EDGE_U32 (ER_OFF + 12800)   // 23168 u32 = 92672 B

// ---------------- persistent fused edge layer (384 threads) ----------------
__global__ __launch_bounds__(384, 2) void k_edge(const __half* __restrict__ Whi_g,
                                                 const __half* __restrict__ Wlo_g,
                                                 const float* __restrict__ bC,
                                                 const float* __restrict__ efeat,
                                                 const float* __restrict__ We,
                                                 const float* __restrict__ be,
                                                 int fuse, int last) {
    extern __shared__ unsigned sm[];
    unsigned* Whi = sm + EW_HI;
    unsigned* Wlo = sm + EW_LO;
    float* Wemb = (float*)(sm + EW_EMB);
    unsigned* Ah = sm + ER_OFF;              // aliases Sst
    __half* Sst = (__half*)(sm + ER_OFF);    // 128x100 halves (vv)
    __half* Sbv = (__half*)(sm + ESBV_OFF);  // 128x100 halves (B rows)
    unsigned* SbvU = sm + ESBV_OFF;
    __shared__ int s_src[128], s_dst[128];
    int tid = threadIdx.x;

    {
        const unsigned* gwh = (const unsigned*)Whi_g;
        const unsigned* gwl = (const unsigned*)Wlo_g;
        for (int i = tid; i < 96 * 48; i += 384) {
            int n = i / 48, kp = i % 48;
            Whi[n * 52 + kp] = gwh[i];
            Wlo[n * 52 + kp] = gwl[i];
        }
        if (fuse == 0 && tid < 384) Wemb[tid] = We[tid];
    }

    int w = tid >> 5, lane = tid & 31;
    int wm = w & 3, wn = w >> 2;              // 4 x 3 warp grid
    int rP = tid / 3, thirdP = tid % 3;       // B-stage split
    int colP2 = tid % 96, gP2 = tid / 96;     // pass-2 split
    float bs_tot = 0.f, bq_tot = 0.f;

    // per-thread bias registers for epilogue cols
    float bcr[8];
#pragma unroll
    for (int n = 0; n < 4; n++) {
        int col = wn * 32 + n * 8 + ((lane & 3) << 1);
        bcr[2 * n] = bC[col];
        bcr[2 * n + 1] = bC[col + 1];
    }

    for (int tile = blockIdx.x; tile < NTILE; tile += gridDim.x) {
        int e0 = tile * 128;
        __syncthreads();
        if (tid < 128) {
            s_src[tid] = g_src_s[e0 + tid];
            s_dst[tid] = g_dst_s[e0 + tid];
        }

        // stage B rows: latency hidden by GEMM
        {
            int s = g_src_s[e0 + rP];
            const uint4* Br = (const uint4*)(g_BDh + (long long)s * 192) + thirdP * 4;
            unsigned* pb = SbvU + rP * 50 + thirdP * 16;
#pragma unroll
            for (int i = 0; i < 4; i++) {
                uint4 bu = Br[i];
                pb[i * 4] = bu.x; pb[i * 4 + 1] = bu.y;
                pb[i * 4 + 2] = bu.z; pb[i * 4 + 3] = bu.w;
            }
        }

        if (fuse == 0) {
            for (int i = tid; i < 128 * 12; i += 384) {
                int r = i / 12, c8 = i % 12;
                int er = e0 + r;
                const float4 ef = ((const float4*)efeat)[g_perm[er]];
                uint4 v;
                __half2* vh = (__half2*)&v;
#pragma unroll
                for (int j = 0; j < 4; j++) {
                    int c = c8 * 8 + 2 * j;
                    float o0 = be[c] + ef.x * Wemb[c] + ef.y * Wemb[96 + c] +
                               ef.z * Wemb[192 + c] + ef.w * Wemb[288 + c];
                    float o1 = be[c + 1] + ef.x * Wemb[c + 1] + ef.y * Wemb[96 + c + 1] +
                               ef.z * Wemb[192 + c + 1] + ef.w * Wemb[288 + c + 1];
                    vh[j] = __floats2half2_rn(o0, o1);
                }
                __stcs((uint4*)g_e + (long long)er * 12 + c8, v);
                unsigned* vu = (unsigned*)&v;
#pragma unroll
                for (int j = 0; j < 4; j++) Ah[r * 50 + c8 * 4 + j] = vu[j];
            }
        } else {
            for (int i = tid; i < 128 * 12; i += 384) {
                int r = i / 12, c8 = i % 12;
                long long gi = (long long)(e0 + r) * 12 + c8;
                uint4 v = __ldcs((const uint4*)g_e + gi);
                uint4 en = __ldcs((const uint4*)g_enew + gi);
                __half2* vh = (__half2*)&v;
                __half2* eh = (__half2*)&en;
                int c = c8 * 8;
#pragma unroll
                for (int j = 0; j < 4; j++) {
                    float2 f = __half22float2(vh[j]);
                    float2 ev = __half22float2(eh[j]);
                    f.x += fmaxf(0.f, ev.x * g_scale_e[c + 2 * j] + g_shift_e[c + 2 * j]);
                    f.y += fmaxf(0.f, ev.y * g_scale_e[c + 2 * j + 1] + g_shift_e[c + 2 * j + 1]);
                    vh[j] = __floats2half2_rn(f.x, f.y);
                }
                if (!last) __stcs((uint4*)g_e + gi, v);
                unsigned* vu = (unsigned*)&v;
#pragma unroll
                for (int j = 0; j < 4; j++) Ah[r * 50 + c8 * 4 + j] = vu[j];
            }
        }

        // L2 prefetch for tile + gridDim
        {
            int nt = tile + gridDim.x;
            if (nt < NTILE) {
                int ne0 = nt * 128;
                if (fuse != 0) {
                    const char* eb = (const char*)(g_e + (long long)ne0 * 96);
                    const char* nb = (const char*)(g_enew + (long long)ne0 * 96);
                    const char* p = (tid < 192) ? eb + tid * 128 : nb + (tid - 192) * 128;
                    prefetchL2(p);
                }
                if (tid < 128) {
                    int s = g_src_s[ne0 + tid], d = g_dst_s[ne0 + tid];
                    const char* pb = (const char*)(g_BDh + (long long)s * 192);
                    const char* pe = (const char*)(g_Eh + (long long)d * 96);
                    prefetchL2(pb); prefetchL2(pb + 128); prefetchL2(pb + 256);
                    prefetchL2(pe); prefetchL2(pe + 184);
                }
            }
        }
        __syncthreads();

        // fp16 GEMM: Ce = e @ (Whi + Wlo)
        float acc[2][4][4];
#pragma unroll
        for (int m = 0; m < 2; m++)
#pragma unroll
            for (int n = 0; n < 4; n++)
#pragma unroll
                for (int j = 0; j < 4; j++) acc[m][n][j] = 0.f;

#pragma unroll
        for (int kt = 0; kt < 6; kt++) {
            int kp = kt * 8 + (lane & 3);
            unsigned ah[2][4];
#pragma unroll
            for (int m = 0; m < 2; m++) {
                int row = wm * 32 + m * 16 + (lane >> 2);
                ah[m][0] = Ah[row * 50 + kp];
                ah[m][1] = Ah[(row + 8) * 50 + kp];
                ah[m][2] = Ah[row * 50 + kp + 4];
                ah[m][3] = Ah[(row + 8) * 50 + kp + 4];
            }
#pragma unroll
            for (int n = 0; n < 4; n++) {
                int col = wn * 32 + n * 8 + (lane >> 2);
                unsigned bh0 = Whi[col * 52 + kp], bh1 = Whi[col * 52 + kp + 4];
                unsigned bl0 = Wlo[col * 52 + kp], bl1 = Wlo[col * 52 + kp + 4];
#pragma unroll
                for (int m = 0; m < 2; m++) {
                    mma_f16(acc[m][n], ah[m], bh0, bh1);
                    mma_f16(acc[m][n], ah[m], bl0, bl1);
                }
            }
        }
        __syncthreads();  // all warps done reading Ah

        // fused epilogue: vv = acc + bC + D[src] + E[dst]; write Sst + e_new
#pragma unroll
        for (int m = 0; m < 2; m++) {
            int lr0 = wm * 32 + m * 16 + (lane >> 2);
            int lr1 = lr0 + 8;
            int s0 = s_src[lr0], d0 = s_dst[lr0];
            int s1 = s_src[lr1], d1 = s_dst[lr1];
            const __half* D0 = g_BDh + (long long)s0 * 192 + 96;
            const __half* E0 = g_Eh + (long long)d0 * 96;
            const __half* D1 = g_BDh + (long long)s1 * 192 + 96;
            const __half* E1 = g_Eh + (long long)d1 * 96;
#pragma unroll
            for (int n = 0; n < 4; n++) {
                int col = wn * 32 + n * 8 + ((lane & 3) << 1);
                float2 dv0 = __half22float2(*(const __half2*)&D0[col]);
                float2 ev0 = __half22float2(*(const __half2*)&E0[col]);
                float2 dv1 = __half22float2(*(const __half2*)&D1[col]);
                float2 ev1 = __half22float2(*(const __half2*)&E1[col]);
                float v00 = acc[m][n][0] + bcr[2 * n] + dv0.x + ev0.x;
                float v01 = acc[m][n][1] + bcr[2 * n + 1] + dv0.y + ev0.y;
                float v10 = acc[m][n][2] + bcr[2 * n] + dv1.x + ev1.x;
                float v11 = acc[m][n][3] + bcr[2 * n + 1] + dv1.y + ev1.y;
                __half2 o0 = __floats2half2_rn(v00, v01);
                __half2 o1 = __floats2half2_rn(v10, v11);
                *(__half2*)&Sst[lr0 * 100 + col] = o0;
                *(__half2*)&Sst[lr1 * 100 + col] = o1;
                if (!last) {
                    __stcs((__half2*)&g_enew[(long long)(e0 + lr0) * 96 + col], o0);
                    __stcs((__half2*)&g_enew[(long long)(e0 + lr1) * 96 + col], o1);
                }
            }
        }
        __syncthreads();

        // pass 2: per-column segment scan, 4 groups x 32 rows
        {
            int rbeg = gP2 * 32, rend = rbeg + 32;
            float num_acc = 0.f, den_acc = 0.f;
            int d = s_dst[rbeg];
            for (int r = rbeg; r < rend; r++) {
                float vv = __half2float(Sst[r * 100 + colP2]);
                float bv = __half2float(Sbv[r * 100 + colP2]);
                float sg = sigmoid_fast(vv);
                num_acc = fmaf(sg, bv, num_acc);
                den_acc += sg;
                bs_tot += vv;
                bq_tot = fmaf(vv, vv, bq_tot);
                int dn = (r + 1 < rend) ? s_dst[r + 1] : -1;
                if (dn != d) {
                    atomicAdd((float2*)&g_agg[((long long)d * 96 + colP2) * 2],
                              make_float2(num_acc, den_acc));
                    num_acc = 0.f;
                    den_acc = 0.f;
                    d = dn;
                }
            }
        }
    }
    if (!last) {
        atomicAdd(&g_sums[colP2], bs_tot);
        atomicAdd(&g_sums[DD + colP2], bq_tot);
    }
}

// ---------------- h_new = Ah + num/(den+eps), BN-h moments, re-zero agg ----------------
__global__ __launch_bounds__(384) void k_hnew() {
    __shared__ float ssum[96], ssq[96];
    int tid = threadIdx.x;
    int col = tid % 96, yr = tid / 96;
    if (tid < 96) { ssum[tid] = 0.f; ssq[tid] = 0.f; }
    __syncthreads();
    float sm = 0.f, sq = 0.f;
    for (int row = blockIdx.x * 4 + yr; row < NN; row += gridDim.x * 4) {
        int i = row * 96 + col;
        float2 nd = ((float2*)g_agg)[i];
        float v = g_A[i] + nd.x / (nd.y + AGG_EPS);
        g_hnew[i] = v;
        ((float2*)g_agg)[i] = make_float2(0.f, 0.f);
        sm += v;
        sq = fmaf(v, v, sq);
    }
    atomicAdd(&ssum[col], sm);
    atomicAdd(&ssq[col], sq);
    __syncthreads();
    if (tid < 96) {
        atomicAdd(&g_sums[2 * DD + tid], ssum[tid]);
        atomicAdd(&g_sums[3 * DD + tid], ssq[tid]);
    }
}

// ---------------- finalize BN stats ----------------
__global__ void k_finalize(int which, const float* __restrict__ g,
                           const float* __restrict__ b, float invM) {
    int c = threadIdx.x;
    if (c >= 96) return;
    int base = which * 2 * DD;
    float mu = g_sums[base + c] * invM;
    float var = g_sums[base + DD + c] * invM - mu * mu;
    float rstd = rsqrtf(var + BN_EPS);
    float sc = g[c] * rstd;
    float sh = b[c] - mu * sc;
    if (which == 0) { g_scale_e[c] = sc; g_shift_e[c] = sh; }
    else            { g_scale_h[c] = sc; g_shift_h[c] = sh; }
    g_sums[base + c] = 0.f;
    g_sums[base + DD + c] = 0.f;
}

// ---------------- MLP head (also re-zeroes sort scratch for next replay) ----------------
__global__ __launch_bounds__(128) void k_head(const float* __restrict__ W1,
                                              const float* __restrict__ b1,
                                              const float* __restrict__ W2,
                                              const float* __restrict__ b2,
                                              const float* __restrict__ maxa,
                                              float* __restrict__ out) {
    __shared__ float hs[8][96];
    __shared__ float hid[8][HIDN];
    int r0 = blockIdx.x * 8;
    int tid = threadIdx.x;
    int gid = blockIdx.x * 128 + tid;
    if (gid < NN) { g_off[gid] = 0; g_cursor[gid] = 0; }
    for (int i = tid; i < 8 * 96; i += 128) {
        int r = i / 96, c = i % 96;
        int row = r0 + r;
        float v = 0.f;
        if (row < NN) {
            long long gi = (long long)row * 96 + c;
            v = g_h[gi] + fmaxf(0.f, g_hnew[gi] * g_scale_h[c] + g_shift_h[c]);
        }
        hs[r][c] = v;
    }
    __syncthreads();
    float acc[8];
#pragma unroll
    for (int r = 0; r < 8; r++) acc[r] = b1[tid];
#pragma unroll 4
    for (int k = 0; k < 96; k++) {
        float w = W1[k * HIDN + tid];
#pragma unroll
        for (int r = 0; r < 8; r++) acc[r] += hs[r][k] * w;
    }
#pragma unroll
    for (int r = 0; r < 8; r++) hid[r][tid] = fmaxf(acc[r], 0.f);
    __syncthreads();
    if (tid < 64) {
        int r = tid >> 3, c = tid & 7;
        int row = r0 + r;
        if (row < NN) {
            float a = b2[c];
#pragma unroll 8
            for (int k = 0; k < HIDN; k++) a += hid[r][k] * W2[k * OUTD + c];
            out[(long long)row * OUTD + c] = maxa[row] * tanhf(a);
        }
    }
}

// ---------------- launch ----------------
extern "C" void kernel_launch(void* const* d_in, const int* in_sizes, int n_in,
                              void* d_out, int out_size) {
    const float* h1 = (const float*)d_in[0];
    const float* h2 = (const float*)d_in[1];
    const float* z = (const float*)d_in[2];
    const float* efeat = (const float*)d_in[3];
    const float* max_action = (const float*)d_in[4];
    const float* Wh_emb = (const float*)d_in[5];
    const float* bh_emb = (const float*)d_in[6];
    const float* We_emb = (const float*)d_in[7];
    const float* be_emb = (const float*)d_in[8];
    const float* WA = (const float*)d_in[9];
    const float* bA = (const float*)d_in[10];
    const float* WB = (const float*)d_in[11];
    const float* bB = (const float*)d_in[12];
    const float* WC = (const float*)d_in[13];
    const float* bC = (const float*)d_in[14];
    const float* WD = (const float*)d_in[15];
    const float* bD = (const float*)d_in[16];
    const float* WE = (const float*)d_in[17];
    const float* bE = (const float*)d_in[18];
    const float* bn_h_g = (const float*)d_in[19];
    const float* bn_h_b = (const float*)d_in[20];
    const float* bn_e_g = (const float*)d_in[21];
    const float* bn_e_b = (const float*)d_in[22];
    const float* W1 = (const float*)d_in[23];
    const float* b1 = (const float*)d_in[24];
    const float* W2 = (const float*)d_in[25];
    const float* b2 = (const float*)d_in[26];
    const int* src = (const int*)d_in[27];
    const int* dst = (const int*)d_in[28];
    float* out = (float*)d_out;

    __half *p_wfhi, *p_wflo;
    cudaGetSymbolAddress((void**)&p_wfhi, g_Wf_hi);
    cudaGetSymbolAddress((void**)&p_wflo, g_Wf_lo);

    const int smem_node = NODE_U32 * 4;  // 65536
    const int smem_edge = EDGE_U32 * 4;  // 92672
    cudaFuncSetAttribute(k_node, cudaFuncAttributeMaxDynamicSharedMemorySize, smem_node);
    cudaFuncSetAttribute(k_edge, cudaFuncAttributeMaxDynamicSharedMemorySize, smem_edge);

    WPtrs wp{WA, WB, WC, WD, WE};
    k_histprep<<<(EE + 255) / 256, 256>>>(dst, wp);     // launch 1
    k_scan<<<1, 1024>>>();                               // launch 2

    const int nblk = (NN + 127) / 128;  // 391
    const int sblk = (EE + 255) / 256;  // 3125 (scatter coverage, layer 0)
    const int eblk = 296;               // persistent edge

    for (int l = 0; l < 4; l++) {
        // layer 0: fused scatter+node (launch 3) so k_edge is launch 4 (ncu slot)
        k_node<<<(l == 0 ? sblk : nblk), 256, smem_node>>>(
            bA + l * DD, bB + l * DD, bD + l * DD, bE + l * DD,
            l, l == 0 ? 2 : 1, h1, h2, z, Wh_emb, bh_emb, src, dst);
        k_edge<<<eblk, 384, smem_edge>>>(p_wfhi + (2 * 4 + l) * DD * DD,
                                         p_wflo + (2 * 4 + l) * DD * DD,
                                         bC + l * DD, efeat, We_emb, be_emb,
                                         l == 0 ? 0 : 1, l == 3 ? 1 : 0);
        if (l < 3)
            k_finalize<<<1, 96>>>(0, bn_e_g + l * DD, bn_e_b + l * DD, 1.f / EE);
        k_hnew<<<256, 384>>>();
        k_finalize<<<1, 96>>>(1, bn_h_g + l * DD, bn_h_b + l * DD, 1.f / NN);
    }

    k_head<<<NN / 8, 128>>>(W1, b1, W2, b2, max_action, out);
}

// round 12
// speedup vs baseline: 2.6599x; 1.0401x over previous
#include <cuda_runtime.h>
#include <cuda_bf16.h>
#include <cuda_fp16.h>
#include <math.h>

#define NN 50000
#define EE 800000
#define DD 96
#define HIDN 128
#define OUTD 8
#define BN_EPS 1e-5f
#define AGG_EPS 1e-6f
#define NTILE 6250

// ---------------- device scratch ----------------
__device__ __align__(16) float g_h[NN * DD];
__device__ __align__(16) float g_A[NN * DD];
__device__ __align__(16) __half g_BDh[NN * DD * 2];  // B at [0,96), D at [96,192) per node
__device__ __align__(16) __half g_Eh[NN * DD];
__device__ __align__(16) float g_agg[NN * DD * 2];   // interleaved num/den
__device__ __align__(16) float g_hnew[NN * DD];
__device__ __align__(16) __half g_e[EE * DD];        // sorted order
__device__ __align__(16) __half g_enew[EE * DD];     // sorted order
__device__ __align__(16) float g_sums[4 * DD];
__device__ __align__(16) float g_scale_e[DD], g_shift_e[DD];
__device__ __align__(16) float g_scale_h[DD], g_shift_h[DD];
__device__ __align__(16) __half g_Wf_hi[20 * DD * DD];
__device__ __align__(16) __half g_Wf_lo[20 * DD * DD];
// dst-sorted edge structure
__device__ int g_perm[EE];
__device__ int g_src_s[EE];
__device__ int g_dst_s[EE];
__device__ int g_off[NN];
__device__ int g_cursor[NN];

// ---------------- helpers ----------------
__device__ __forceinline__ unsigned pack_h2(float x, float y) {
    __half2 t = __floats2half2_rn(x, y);
    return *reinterpret_cast<unsigned*>(&t);
}

__device__ __forceinline__ float sigmoid_fast(float x) {
    float t;
    asm("tanh.approx.f32 %0, %1;" : "=f"(t) : "f"(0.5f * x));
    return fmaf(0.5f, t, 0.5f);
}

__device__ __forceinline__ void prefetchL2(const void* p) {
    asm volatile("prefetch.global.L2 [%0];" :: "l"(p));
}

__device__ __forceinline__ void mma_f16(float* c, const unsigned* a, unsigned b0, unsigned b1) {
    asm volatile(
        "mma.sync.aligned.m16n8k16.row.col.f32.f16.f16.f32 "
        "{%0,%1,%2,%3},{%4,%5,%6,%7},{%8,%9},{%0,%1,%2,%3};"
        : "+f"(c[0]), "+f"(c[1]), "+f"(c[2]), "+f"(c[3])
        : "r"(a[0]), "r"(a[1]), "r"(a[2]), "r"(a[3]), "r"(b0), "r"(b1));
}

// ---------------- fused: dst histogram + weight prep ----------------
struct WPtrs { const float *a, *b, *c, *d, *e; };

__global__ void k_histprep(const int* __restrict__ dst, WPtrs p) {
    int idx = blockIdx.x * blockDim.x + threadIdx.x;
    if (idx < EE) atomicAdd(&g_off[dst[idx]], 1);
    if (idx < 20 * DD * DD) {
        int m = idx / (DD * DD), r = idx % (DD * DD);
        int k = r / DD, n = r % DD;
        int type = m >> 2, layer = m & 3;
        const float* src = type == 0 ? p.a : type == 1 ? p.b : type == 2 ? p.c
                           : type == 3 ? p.d : p.e;
        float w = src[layer * DD * DD + k * DD + n];
        __half hi = __float2half(w);
        g_Wf_hi[m * DD * DD + n * DD + k] = hi;
        g_Wf_lo[m * DD * DD + n * DD + k] = __float2half(w - __half2float(hi));
    }
}

__global__ void k_scan() {
    __shared__ int ssum[1024];
    const int STRIP = (NN + 1023) / 1024;
    int t = threadIdx.x;
    int beg = t * STRIP, end = beg + STRIP;
    if (end > NN) end = NN;
    int s = 0;
    for (int i = beg; i < end; i++) s += g_off[i];
    ssum[t] = s;
    __syncthreads();
    for (int ofs = 1; ofs < 1024; ofs <<= 1) {
        int v = (t >= ofs) ? ssum[t - ofs] : 0;
        __syncthreads();
        ssum[t] += v;
        __syncthreads();
    }
    int carry = (t > 0) ? ssum[t - 1] : 0;
    for (int i = beg; i < end; i++) {
        int v = g_off[i];
        g_off[i] = carry;
        carry += v;
    }
}

// smem layout node (u32): Ah[128*50] Whi[96*52] Wlo[96*52]
#define N_A 0
#define N_WHI (128 * 50)
#define N_WLO (128 * 50 + 96 * 52)
#define NODE_U32 (128 * 50 + 2 * 96 * 52)   // 16384 u32 = 65536 B

// ---------------- fused node GEMM (+ scatter when fuse==2) ----------------
__global__ __launch_bounds__(256, 3) void k_node(const float* __restrict__ bA, const float* __restrict__ bB,
                                                 const float* __restrict__ bD, const float* __restrict__ bE,
                                                 int layer, int fuse,
                                                 const float* __restrict__ h1, const float* __restrict__ h2,
                                                 const float* __restrict__ z,
                                                 const float* __restrict__ Wh_emb,
                                                 const float* __restrict__ bh_emb,
                                                 const int* __restrict__ src_in,
                                                 const int* __restrict__ dst_in) {
    extern __shared__ unsigned sm[];
    unsigned* Ah = sm + N_A;
    unsigned* Whi = sm + N_WHI;
    unsigned* Wlo = sm + N_WLO;
    int tid = threadIdx.x;

    if (fuse == 2) {
        int e = blockIdx.x * 256 + tid;
        if (e < EE) {
            int d = dst_in[e];
            int p = g_off[d] + atomicAdd(&g_cursor[d], 1);
            g_perm[p] = e;
            g_src_s[p] = src_in[e];
            g_dst_s[p] = d;
        }
        if (blockIdx.x >= (NN + 127) / 128) return;
    }

    int m0 = blockIdx.x * 128;
    int rows_valid = NN - m0;
    if (rows_valid > 128) rows_valid = 128;

    if (fuse == 2) {
        float* Whf = (float*)(sm + N_WHI);
        for (int i = tid; i < 26 * 96; i += 256) Whf[i] = Wh_emb[i];
        __syncthreads();
        for (int i = tid; i < 128 * 24; i += 256) {
            int r = i / 24, c4 = i % 24;
            int row = m0 + r;
            float4 v = make_float4(0.f, 0.f, 0.f, 0.f);
            if (r < rows_valid) {
                float x[26];
                const float* p1 = h1 + row * 6;
#pragma unroll
                for (int k = 0; k < 6; k++) x[k] = p1[k];
                const float* p2 = h2 + row * 4;
#pragma unroll
                for (int k = 0; k < 4; k++) x[6 + k] = p2[k];
                const float* p3 = z + row * 16;
#pragma unroll
                for (int k = 0; k < 16; k++) x[10 + k] = p3[k];
                float a[4];
#pragma unroll
                for (int c = 0; c < 4; c++) a[c] = bh_emb[c4 * 4 + c];
#pragma unroll
                for (int k = 0; k < 26; k++) {
#pragma unroll
                    for (int c = 0; c < 4; c++)
                        a[c] = fmaf(x[k], Whf[k * 96 + c4 * 4 + c], a[c]);
                }
                v = make_float4(a[0], a[1], a[2], a[3]);
                ((float4*)g_h)[(long long)row * 24 + c4] = v;
            }
            Ah[r * 50 + c4 * 2] = pack_h2(v.x, v.y);
            Ah[r * 50 + c4 * 2 + 1] = pack_h2(v.z, v.w);
        }
    } else {
        for (int i = tid; i < 128 * 24; i += 256) {
            int r = i / 24, c4 = i % 24;
            float4 v = make_float4(0.f, 0.f, 0.f, 0.f);
            if (r < rows_valid) {
                long long gi = (long long)(m0 + r) * 24 + c4;
                v = ((const float4*)g_h)[gi];
                float4 en = ((const float4*)g_hnew)[gi];
                int c = c4 * 4;
                v.x += fmaxf(0.f, en.x * g_scale_h[c] + g_shift_h[c]);
                v.y += fmaxf(0.f, en.y * g_scale_h[c + 1] + g_shift_h[c + 1]);
                v.z += fmaxf(0.f, en.z * g_scale_h[c + 2] + g_shift_h[c + 2]);
                v.w += fmaxf(0.f, en.w * g_scale_h[c + 3] + g_shift_h[c + 3]);
                ((float4*)g_h)[gi] = v;
            }
            Ah[r * 50 + c4 * 2] = pack_h2(v.x, v.y);
            Ah[r * 50 + c4 * 2 + 1] = pack_h2(v.z, v.w);
        }
    }

    int w = tid >> 5, lane = tid & 31;
    int wm = w & 3, wn = w >> 2;
    const int types[4] = {0, 1, 3, 4};
    const float* biases[4] = {bA, bB, bD, bE};

    for (int t = 0; t < 4; t++) {
        __syncthreads();
        const unsigned* gwh = (const unsigned*)(g_Wf_hi + (types[t] * 4 + layer) * DD * DD);
        const unsigned* gwl = (const unsigned*)(g_Wf_lo + (types[t] * 4 + layer) * DD * DD);
        for (int i = tid; i < 96 * 48; i += 256) {
            int n = i / 48, kp = i % 48;
            Whi[n * 52 + kp] = gwh[i];
            Wlo[n * 52 + kp] = gwl[i];
        }
        __syncthreads();

        float acc[2][6][4];
#pragma unroll
        for (int m = 0; m < 2; m++)
#pragma unroll
            for (int n = 0; n < 6; n++)
#pragma unroll
                for (int j = 0; j < 4; j++) acc[m][n][j] = 0.f;

#pragma unroll
        for (int kt = 0; kt < 6; kt++) {
            int kp = kt * 8 + (lane & 3);
            unsigned ah[2][4];
#pragma unroll
            for (int m = 0; m < 2; m++) {
                int row = wm * 32 + m * 16 + (lane >> 2);
                ah[m][0] = Ah[row * 50 + kp];
                ah[m][1] = Ah[(row + 8) * 50 + kp];
                ah[m][2] = Ah[row * 50 + kp + 4];
                ah[m][3] = Ah[(row + 8) * 50 + kp + 4];
            }
#pragma unroll
            for (int n = 0; n < 6; n++) {
                int col = wn * 48 + n * 8 + (lane >> 2);
                unsigned bh0 = Whi[col * 52 + kp], bh1 = Whi[col * 52 + kp + 4];
                unsigned bl0 = Wlo[col * 52 + kp], bl1 = Wlo[col * 52 + kp + 4];
#pragma unroll
                for (int m = 0; m < 2; m++) {
                    mma_f16(acc[m][n], ah[m], bh0, bh1);
                    mma_f16(acc[m][n], ah[m], bl0, bl1);
                }
            }
        }

        const float* bias = biases[t];
#pragma unroll
        for (int m = 0; m < 2; m++) {
#pragma unroll
            for (int n = 0; n < 6; n++) {
                int row = m0 + wm * 32 + m * 16 + (lane >> 2);
                int col = wn * 48 + n * 8 + ((lane & 3) << 1);
                float b0 = bias[col], b1 = bias[col + 1];
                float v00 = acc[m][n][0] + b0, v01 = acc[m][n][1] + b1;
                float v10 = acc[m][n][2] + b0, v11 = acc[m][n][3] + b1;
                if (t == 0) {
                    if (row < NN)
                        *(float2*)&g_A[(long long)row * 96 + col] = make_float2(v00, v01);
                    if (row + 8 < NN)
                        *(float2*)&g_A[(long long)(row + 8) * 96 + col] = make_float2(v10, v11);
                } else if (t < 3) {
                    int ofs = (t == 1) ? 0 : 96;
                    if (row < NN)
                        *(__half2*)&g_BDh[(long long)row * 192 + ofs + col] = __floats2half2_rn(v00, v01);
                    if (row + 8 < NN)
                        *(__half2*)&g_BDh[(long long)(row + 8) * 192 + ofs + col] = __floats2half2_rn(v10, v11);
                } else {
                    if (row < NN)
                        *(__half2*)&g_Eh[(long long)row * 96 + col] = __floats2half2_rn(v00, v01);
                    if (row + 8 < NN)
                        *(__half2*)&g_Eh[(long long)(row + 8) * 96 + col] = __floats2half2_rn(v10, v11);
                }
            }
        }
    }
}

// smem layout edge (u32): Whi[96*52] Wemb[384] | Ah/Sst[128*50] Sbv[128*50]
#define EW_HI 0
#define EW_EMB (96 * 52)
#define ER_OFF (96 * 52 + 384)
#define ESBV_OFF (ER_OFF + 6400)
#define EDGE_U32 (ER_OFF + 12800)   // 18176 u32 = 72704 B

// ---------------- persistent fused edge layer (384 threads, W-hi only) ----------------
__global__ __launch_bounds__(384, 2) void k_edge(const __half* __restrict__ Whi_g,
                                                 const float* __restrict__ bC,
                                                 const float* __restrict__ efeat,
                                                 const float* __restrict__ We,
                                                 const float* __restrict__ be,
                                                 int fuse, int last) {
    extern __shared__ unsigned sm[];
    unsigned* Whi = sm + EW_HI;
    float* Wemb = (float*)(sm + EW_EMB);
    unsigned* Ah = sm + ER_OFF;              // aliases Sst
    __half* Sst = (__half*)(sm + ER_OFF);    // 128x100 halves (vv)
    __half* Sbv = (__half*)(sm + ESBV_OFF);  // 128x100 halves (B rows)
    unsigned* SbvU = sm + ESBV_OFF;
    __shared__ int s_src[128], s_dst[128];
    int tid = threadIdx.x;

    {
        const unsigned* gwh = (const unsigned*)Whi_g;
        for (int i = tid; i < 96 * 48; i += 384) {
            int n = i / 48, kp = i % 48;
            Whi[n * 52 + kp] = gwh[i];
        }
        if (fuse == 0 && tid < 384) Wemb[tid] = We[tid];
    }

    int w = tid >> 5, lane = tid & 31;
    int wm = w & 3, wn = w >> 2;              // 4 x 3 warp grid
    int rP = tid / 3, thirdP = tid % 3;       // B-stage split
    int colPair = (tid % 48) * 2, gP2 = tid / 48;  // pass-2: 8 groups x 16 rows, 2 cols/thread
    float bs0 = 0.f, bs1 = 0.f, bq0 = 0.f, bq1 = 0.f;

    float bcr[8];
#pragma unroll
    for (int n = 0; n < 4; n++) {
        int col = wn * 32 + n * 8 + ((lane & 3) << 1);
        bcr[2 * n] = bC[col];
        bcr[2 * n + 1] = bC[col + 1];
    }

    for (int tile = blockIdx.x; tile < NTILE; tile += gridDim.x) {
        int e0 = tile * 128;
        __syncthreads();
        if (tid < 128) {
            s_src[tid] = g_src_s[e0 + tid];
            s_dst[tid] = g_dst_s[e0 + tid];
        }

        // stage B rows: latency hidden by GEMM
        {
            int s = g_src_s[e0 + rP];
            const uint4* Br = (const uint4*)(g_BDh + (long long)s * 192) + thirdP * 4;
            unsigned* pb = SbvU + rP * 50 + thirdP * 16;
#pragma unroll
            for (int i = 0; i < 4; i++) {
                uint4 bu = Br[i];
                pb[i * 4] = bu.x; pb[i * 4 + 1] = bu.y;
                pb[i * 4 + 2] = bu.z; pb[i * 4 + 3] = bu.w;
            }
        }

        if (fuse == 0) {
            for (int i = tid; i < 128 * 12; i += 384) {
                int r = i / 12, c8 = i % 12;
                int er = e0 + r;
                const float4 ef = ((const float4*)efeat)[g_perm[er]];
                uint4 v;
                __half2* vh = (__half2*)&v;
#pragma unroll
                for (int j = 0; j < 4; j++) {
                    int c = c8 * 8 + 2 * j;
                    float o0 = be[c] + ef.x * Wemb[c] + ef.y * Wemb[96 + c] +
                               ef.z * Wemb[192 + c] + ef.w * Wemb[288 + c];
                    float o1 = be[c + 1] + ef.x * Wemb[c + 1] + ef.y * Wemb[96 + c + 1] +
                               ef.z * Wemb[192 + c + 1] + ef.w * Wemb[288 + c + 1];
                    vh[j] = __floats2half2_rn(o0, o1);
                }
                __stcs((uint4*)g_e + (long long)er * 12 + c8, v);
                unsigned* vu = (unsigned*)&v;
#pragma unroll
                for (int j = 0; j < 4; j++) Ah[r * 50 + c8 * 4 + j] = vu[j];
            }
        } else {
            for (int i = tid; i < 128 * 12; i += 384) {
                int r = i / 12, c8 = i % 12;
                long long gi = (long long)(e0 + r) * 12 + c8;
                uint4 v = __ldcs((const uint4*)g_e + gi);
                uint4 en = __ldcs((const uint4*)g_enew + gi);
                __half2* vh = (__half2*)&v;
                __half2* eh = (__half2*)&en;
                int c = c8 * 8;
#pragma unroll
                for (int j = 0; j < 4; j++) {
                    float2 f = __half22float2(vh[j]);
                    float2 ev = __half22float2(eh[j]);
                    f.x += fmaxf(0.f, ev.x * g_scale_e[c + 2 * j] + g_shift_e[c + 2 * j]);
                    f.y += fmaxf(0.f, ev.y * g_scale_e[c + 2 * j + 1] + g_shift_e[c + 2 * j + 1]);
                    vh[j] = __floats2half2_rn(f.x, f.y);
                }
                if (!last) __stcs((uint4*)g_e + gi, v);
                unsigned* vu = (unsigned*)&v;
#pragma unroll
                for (int j = 0; j < 4; j++) Ah[r * 50 + c8 * 4 + j] = vu[j];
            }
        }

        // L2 prefetch for tile + gridDim
        {
            int nt = tile + gridDim.x;
            if (nt < NTILE) {
                int ne0 = nt * 128;
                if (fuse != 0) {
                    const char* eb = (const char*)(g_e + (long long)ne0 * 96);
                    const char* nb = (const char*)(g_enew + (long long)ne0 * 96);
                    const char* p = (tid < 192) ? eb + tid * 128 : nb + (tid - 192) * 128;
                    prefetchL2(p);
                }
                if (tid < 128) {
                    int s = g_src_s[ne0 + tid], d = g_dst_s[ne0 + tid];
                    const char* pb = (const char*)(g_BDh + (long long)s * 192);
                    const char* pe = (const char*)(g_Eh + (long long)d * 96);
                    prefetchL2(pb); prefetchL2(pb + 128); prefetchL2(pb + 256);
                    prefetchL2(pe); prefetchL2(pe + 184);
                }
            }
        }
        __syncthreads();

        // fp16 GEMM: Ce = e @ Whi (single term)
        float acc[2][4][4];
#pragma unroll
        for (int m = 0; m < 2; m++)
#pragma unroll
            for (int n = 0; n < 4; n++)
#pragma unroll
                for (int j = 0; j < 4; j++) acc[m][n][j] = 0.f;

#pragma unroll
        for (int kt = 0; kt < 6; kt++) {
            int kp = kt * 8 + (lane & 3);
            unsigned ah[2][4];
#pragma unroll
            for (int m = 0; m < 2; m++) {
                int row = wm * 32 + m * 16 + (lane >> 2);
                ah[m][0] = Ah[row * 50 + kp];
                ah[m][1] = Ah[(row + 8) * 50 + kp];
                ah[m][2] = Ah[row * 50 + kp + 4];
                ah[m][3] = Ah[(row + 8) * 50 + kp + 4];
            }
#pragma unroll
            for (int n = 0; n < 4; n++) {
                int col = wn * 32 + n * 8 + (lane >> 2);
                unsigned bh0 = Whi[col * 52 + kp], bh1 = Whi[col * 52 + kp + 4];
#pragma unroll
                for (int m = 0; m < 2; m++)
                    mma_f16(acc[m][n], ah[m], bh0, bh1);
            }
        }
        __syncthreads();  // all warps done reading Ah

        // fused epilogue: vv = acc + bC + D[src] + E[dst]; write Sst + e_new
#pragma unroll
        for (int m = 0; m < 2; m++) {
            int lr0 = wm * 32 + m * 16 + (lane >> 2);
            int lr1 = lr0 + 8;
            int s0 = s_src[lr0], d0 = s_dst[lr0];
            int s1 = s_src[lr1], d1 = s_dst[lr1];
            const __half* D0 = g_BDh + (long long)s0 * 192 + 96;
            const __half* E0 = g_Eh + (long long)d0 * 96;
            const __half* D1 = g_BDh + (long long)s1 * 192 + 96;
            const __half* E1 = g_Eh + (long long)d1 * 96;
#pragma unroll
            for (int n = 0; n < 4; n++) {
                int col = wn * 32 + n * 8 + ((lane & 3) << 1);
                float2 dv0 = __half22float2(*(const __half2*)&D0[col]);
                float2 ev0 = __half22float2(*(const __half2*)&E0[col]);
                float2 dv1 = __half22float2(*(const __half2*)&D1[col]);
                float2 ev1 = __half22float2(*(const __half2*)&E1[col]);
                float v00 = acc[m][n][0] + bcr[2 * n] + dv0.x + ev0.x;
                float v01 = acc[m][n][1] + bcr[2 * n + 1] + dv0.y + ev0.y;
                float v10 = acc[m][n][2] + bcr[2 * n] + dv1.x + ev1.x;
                float v11 = acc[m][n][3] + bcr[2 * n + 1] + dv1.y + ev1.y;
                __half2 o0 = __floats2half2_rn(v00, v01);
                __half2 o1 = __floats2half2_rn(v10, v11);
                *(__half2*)&Sst[lr0 * 100 + col] = o0;
                *(__half2*)&Sst[lr1 * 100 + col] = o1;
                if (!last) {
                    __stcs((__half2*)&g_enew[(long long)(e0 + lr0) * 96 + col], o0);
                    __stcs((__half2*)&g_enew[(long long)(e0 + lr1) * 96 + col], o1);
                }
            }
        }
        __syncthreads();

        // pass 2: per-column-pair segment scan, 8 groups x 16 rows
        {
            int rbeg = gP2 * 16, rend = rbeg + 16;
            float n0 = 0.f, n1 = 0.f, de0 = 0.f, de1 = 0.f;
            int d = s_dst[rbeg];
            for (int r = rbeg; r < rend; r++) {
                float2 vv = __half22float2(*(const __half2*)&Sst[r * 100 + colPair]);
                float2 bv = __half22float2(*(const __half2*)&Sbv[r * 100 + colPair]);
                float sg0 = sigmoid_fast(vv.x);
                float sg1 = sigmoid_fast(vv.y);
                n0 = fmaf(sg0, bv.x, n0);
                n1 = fmaf(sg1, bv.y, n1);
                de0 += sg0;
                de1 += sg1;
                bs0 += vv.x; bs1 += vv.y;
                bq0 = fmaf(vv.x, vv.x, bq0);
                bq1 = fmaf(vv.y, vv.y, bq1);
                int dn = (r + 1 < rend) ? s_dst[r + 1] : -1;
                if (dn != d) {
                    atomicAdd((float4*)&g_agg[((long long)d * 96 + colPair) * 2],
                              make_float4(n0, de0, n1, de1));
                    n0 = 0.f; n1 = 0.f; de0 = 0.f; de1 = 0.f;
                    d = dn;
                }
            }
        }
    }
    if (!last) {
        atomicAdd(&g_sums[colPair], bs0);
        atomicAdd(&g_sums[colPair + 1], bs1);
        atomicAdd(&g_sums[DD + colPair], bq0);
        atomicAdd(&g_sums[DD + colPair + 1], bq1);
    }
}

// ---------------- h_new = Ah + num/(den+eps), BN-h moments, re-zero agg ----------------
__global__ __launch_bounds__(384) void k_hnew() {
    __shared__ float ssum[96], ssq[96];
    int tid = threadIdx.x;
    int col = tid % 96, yr = tid / 96;
    if (tid < 96) { ssum[tid] = 0.f; ssq[tid] = 0.f; }
    __syncthreads();
    float sm = 0.f, sq = 0.f;
    for (int row = blockIdx.x * 4 + yr; row < NN; row += gridDim.x * 4) {
        int i = row * 96 + col;
        float2 nd = ((float2*)g_agg)[i];
        float v = g_A[i] + nd.x / (nd.y + AGG_EPS);
        g_hnew[i] = v;
        ((float2*)g_agg)[i] = make_float2(0.f, 0.f);
        sm += v;
        sq = fmaf(v, v, sq);
    }
    atomicAdd(&ssum[col], sm);
    atomicAdd(&ssq[col], sq);
    __syncthreads();
    if (tid < 96) {
        atomicAdd(&g_sums[2 * DD + tid], ssum[tid]);
        atomicAdd(&g_sums[3 * DD + tid], ssq[tid]);
    }
}

// ---------------- finalize BN stats ----------------
__global__ void k_finalize(int which, const float* __restrict__ g,
                           const float* __restrict__ b, float invM) {
    int c = threadIdx.x;
    if (c >= 96) return;
    int base = which * 2 * DD;
    float mu = g_sums[base + c] * invM;
    float var = g_sums[base + DD + c] * invM - mu * mu;
    float rstd = rsqrtf(var + BN_EPS);
    float sc = g[c] * rstd;
    float sh = b[c] - mu * sc;
    if (which == 0) { g_scale_e[c] = sc; g_shift_e[c] = sh; }
    else            { g_scale_h[c] = sc; g_shift_h[c] = sh; }
    g_sums[base + c] = 0.f;
    g_sums[base + DD + c] = 0.f;
}

// ---------------- MLP head (re-zeroes sort scratch for next replay) ----------------
__global__ __launch_bounds__(128) void k_head(const float* __restrict__ W1,
                                              const float* __restrict__ b1,
                                              const float* __restrict__ W2,
                                              const float* __restrict__ b2,
                                              const float* __restrict__ maxa,
                                              float* __restrict__ out) {
    __shared__ float hs[8][96];
    __shared__ float hid[8][HIDN];
    int r0 = blockIdx.x * 8;
    int tid = threadIdx.x;
    int gid = blockIdx.x * 128 + tid;
    if (gid < NN) { g_off[gid] = 0; g_cursor[gid] = 0; }
    for (int i = tid; i < 8 * 96; i += 128) {
        int r = i / 96, c = i % 96;
        int row = r0 + r;
        float v = 0.f;
        if (row < NN) {
            long long gi = (long long)row * 96 + c;
            v = g_h[gi] + fmaxf(0.f, g_hnew[gi] * g_scale_h[c] + g_shift_h[c]);
        }
        hs[r][c] = v;
    }
    __syncthreads();
    float acc[8];
#pragma unroll
    for (int r = 0; r < 8; r++) acc[r] = b1[tid];
#pragma unroll 4
    for (int k = 0; k < 96; k++) {
        float w = W1[k * HIDN + tid];
#pragma unroll
        for (int r = 0; r < 8; r++) acc[r] += hs[r][k] * w;
    }
#pragma unroll
    for (int r = 0; r < 8; r++) hid[r][tid] = fmaxf(acc[r], 0.f);
    __syncthreads();
    if (tid < 64) {
        int r = tid >> 3, c = tid & 7;
        int row = r0 + r;
        if (row < NN) {
            float a = b2[c];
#pragma unroll 8
            for (int k = 0; k < HIDN; k++) a += hid[r][k] * W2[k * OUTD + c];
            out[(long long)row * OUTD + c] = maxa[row] * tanhf(a);
        }
    }
}

// ---------------- launch ----------------
extern "C" void kernel_launch(void* const* d_in, const int* in_sizes, int n_in,
                              void* d_out, int out_size) {
    const float* h1 = (const float*)d_in[0];
    const float* h2 = (const float*)d_in[1];
    const float* z = (const float*)d_in[2];
    const float* efeat = (const float*)d_in[3];
    const float* max_action = (const float*)d_in[4];
    const float* Wh_emb = (const float*)d_in[5];
    const float* bh_emb = (const float*)d_in[6];
    const float* We_emb = (const float*)d_in[7];
    const float* be_emb = (const float*)d_in[8];
    const float* WA = (const float*)d_in[9];
    const float* bA = (const float*)d_in[10];
    const float* WB = (const float*)d_in[11];
    const float* bB = (const float*)d_in[12];
    const float* WC = (const float*)d_in[13];
    const float* bC = (const float*)d_in[14];
    const float* WD = (const float*)d_in[15];
    const float* bD = (const float*)d_in[16];
    const float* WE = (const float*)d_in[17];
    const float* bE = (const float*)d_in[18];
    const float* bn_h_g = (const float*)d_in[19];
    const float* bn_h_b = (const float*)d_in[20];
    const float* bn_e_g = (const float*)d_in[21];
    const float* bn_e_b = (const float*)d_in[22];
    const float* W1 = (const float*)d_in[23];
    const float* b1 = (const float*)d_in[24];
    const float* W2 = (const float*)d_in[25];
    const float* b2 = (const float*)d_in[26];
    const int* src = (const int*)d_in[27];
    const int* dst = (const int*)d_in[28];
    float* out = (float*)d_out;

    __half* p_wfhi;
    cudaGetSymbolAddress((void**)&p_wfhi, g_Wf_hi);

    const int smem_node = NODE_U32 * 4;  // 65536
    const int smem_edge = EDGE_U32 * 4;  // 72704
    cudaFuncSetAttribute(k_node, cudaFuncAttributeMaxDynamicSharedMemorySize, smem_node);
    cudaFuncSetAttribute(k_edge, cudaFuncAttributeMaxDynamicSharedMemorySize, smem_edge);

    WPtrs wp{WA, WB, WC, WD, WE};
    k_histprep<<<(EE + 255) / 256, 256>>>(dst, wp);
    k_scan<<<1, 1024>>>();

    const int nblk = (NN + 127) / 128;  // 391
    const int sblk = (EE + 255) / 256;  // 3125
    const int eblk = 296;

    for (int l = 0; l < 4; l++) {
        k_node<<<(l == 0 ? sblk : nblk), 256, smem_node>>>(
            bA + l * DD, bB + l * DD, bD + l * DD, bE + l * DD,
            l, l == 0 ? 2 : 1, h1, h2, z, Wh_emb, bh_emb, src, dst);
        k_edge<<<eblk, 384, smem_edge>>>(p_wfhi + (2 * 4 + l) * DD * DD,
                                         bC + l * DD, efeat, We_emb, be_emb,
                                         l == 0 ? 0 : 1, l == 3 ? 1 : 0);
        if (l < 3)
            k_finalize<<<1, 96>>>(0, bn_e_g + l * DD, bn_e_b + l * DD, 1.f / EE);
        k_hnew<<<256, 384>>>();
        k_finalize<<<1, 96>>>(1, bn_h_g + l * DD, bn_h_b + l * DD, 1.f / NN);
    }

    k_head<<<NN / 8, 128>>>(W1, b1, W2, b2, max_action, out);
}